// round 5
// baseline (speedup 1.0000x reference)
#include <cuda_runtime.h>
#include <cuda_bf16.h>
#include <math.h>
#include <stdint.h>

#define P_PTS     16384
#define M_PART    4096
#define HASHMAP_SZ 524288u
#define NUM_LVL   16
#define INV_SQRT2 0.70710678118654752f

// ---------------- scratch (device globals; no allocation allowed) -------------
// activations: [P][512] bf16  (cols 0..255 = hi, 256..511 = lo)
__device__ __align__(16) float g_xin[232 * P_PTS];
__device__ __align__(16) __nv_bfloat16 g_x[P_PTS * 512];
__device__ __align__(16) __nv_bfloat16 g_a[P_PTS * 512];
__device__ __align__(16) __nv_bfloat16 g_b[P_PTS * 512];
__device__ __align__(16) __nv_bfloat16 g_s[P_PTS * 512];   // layer-4 (skip) input
__device__ __align__(16) __nv_bfloat16 g_w[2304 * 512];

// ---------------- PTX helpers -------------------------------------------------
static __device__ __forceinline__ uint32_t smem_u32(const void* p) {
    uint32_t a;
    asm("{ .reg .u64 t; cvta.to.shared.u64 t, %1; cvt.u32.u64 %0, t; }" : "=r"(a) : "l"(p));
    return a;
}
static __device__ __forceinline__ void cp16(uint32_t s, const void* g) {
    asm volatile("cp.async.ca.shared.global [%0], [%1], 16;" :: "r"(s), "l"(g));
}
#define CP_COMMIT()  asm volatile("cp.async.commit_group;" ::: "memory")
#define CP_WAIT1()   asm volatile("cp.async.wait_group 1;" ::: "memory")

static __device__ __forceinline__ void ldsm4(uint32_t* r, uint32_t a) {
    asm volatile("ldmatrix.sync.aligned.m8n8.x4.shared.b16 {%0,%1,%2,%3}, [%4];"
                 : "=r"(r[0]), "=r"(r[1]), "=r"(r[2]), "=r"(r[3]) : "r"(a));
}
static __device__ __forceinline__ void mma16816(float* c, const uint32_t* a,
                                                uint32_t b0, uint32_t b1) {
    asm volatile(
        "mma.sync.aligned.m16n8k16.row.col.f32.bf16.bf16.f32 "
        "{%0,%1,%2,%3}, {%4,%5,%6,%7}, {%8,%9}, {%0,%1,%2,%3};"
        : "+f"(c[0]), "+f"(c[1]), "+f"(c[2]), "+f"(c[3])
        : "r"(a[0]), "r"(a[1]), "r"(a[2]), "r"(a[3]), "r"(b0), "r"(b1));
}

// ---------------- fused weight prep -------------------------------------------
struct WPtrs { const float* w[9]; };

__global__ void prep_w_all(WPtrs wp, __nv_bfloat16* __restrict__ out)
{
    int i = blockIdx.x * blockDim.x + threadIdx.x;
    if (i >= 2304 * 256) return;
    int r = i >> 8, k = i & 255;
    const int cum[10]  = {0, 256, 512, 768, 896, 1152, 1408, 1664, 1920, 2304};
    const int nout[9]  = {256, 256, 256, 26, 256, 256, 256, 256, 257};
    const int kact[9]  = {230, 256, 256, 256, 256, 256, 256, 256, 256};
    int l = 0;
#pragma unroll
    for (int t = 1; t < 9; ++t) if (r >= cum[t]) l = t;
    int n = r - cum[l];
    float v = (n < nout[l] && k < kact[l]) ? wp.w[l][n * kact[l] + k] : 0.0f;
    __nv_bfloat16 h = __float2bfloat16(v);
    out[(size_t)r * 512 + k]       = h;
    out[(size_t)r * 512 + 256 + k] = __float2bfloat16(v - __bfloat162float(h));
}

// ---------------- transpose + bf16-split --------------------------------------
__global__ void conv_tr(const float* __restrict__ src, __nv_bfloat16* __restrict__ dst,
                        int vlo, int vhi, int srcoff, float scale, int wlo)
{
    __shared__ float s[32][33];
    int tx = threadIdx.x, ty = threadIdx.y;
    int ct = blockIdx.x, pt = blockIdx.y;
#pragma unroll
    for (int r2 = 0; r2 < 4; ++r2) {
        int ci = ty + r2 * 8;
        int c = ct * 32 + ci;
        int p = pt * 32 + tx;
        float v = 0.0f;
        if (c >= vlo && c < vhi) v = src[(size_t)(c + srcoff) * P_PTS + p] * scale;
        s[ci][tx] = v;
    }
    __syncthreads();
#pragma unroll
    for (int r2 = 0; r2 < 4; ++r2) {
        int pi = ty + r2 * 8;
        int p = pt * 32 + pi;
        int c = ct * 32 + tx;
        if (c >= wlo) {
            float v = s[tx][pi];
            __nv_bfloat16 h = __float2bfloat16(v);
            dst[(size_t)p * 512 + c]       = h;
            dst[(size_t)p * 512 + 256 + c] = __float2bfloat16(v - __bfloat162float(h));
        }
    }
}

// ---------------- feature kernel ----------------------------------------------
__device__ __forceinline__ void penc3(float* __restrict__ xin, int p, int base,
                                      float a, float b, float c)
{
    xin[(base + 0) * P_PTS + p] = a;
    xin[(base + 1) * P_PTS + p] = b;
    xin[(base + 2) * P_PTS + p] = c;
    float v[3] = {a, b, c};
#pragma unroll
    for (int f = 0; f < 10; ++f) {
        float fr = (float)(1 << f);
#pragma unroll
        for (int ch = 0; ch < 3; ++ch) {
            float s, co;
            sincosf(v[ch] * fr, &s, &co);
            xin[(base + 3 + f * 6 + ch)     * P_PTS + p] = s;
            xin[(base + 3 + f * 6 + 3 + ch) * P_PTS + p] = co;
        }
    }
}

__global__ void feature_kernel(const float* __restrict__ inp,
                               const float* __restrict__ parts,
                               const float* __restrict__ table,
                               float* __restrict__ xin)
{
    extern __shared__ float4 sp4[];
    int tid = threadIdx.x;
    for (int i = tid; i < M_PART; i += blockDim.x) {
        float px = parts[3 * i], py = parts[3 * i + 1], pz = parts[3 * i + 2];
        sp4[i] = make_float4(px, py, pz, (px * px + py * py) + pz * pz);
    }
    __syncthreads();

    int p = blockIdx.x * blockDim.x + tid;
    float x = inp[3 * p + 0], y = inp[3 * p + 1], z = inp[3 * p + 2];
    float q1 = (x * x + y * y) + z * z;

    int   cnt  = 0;
    float wsum = 0.f, swx = 0.f, swy = 0.f, swz = 0.f;
    float sdx  = 0.f, sdy = 0.f, sdz = 0.f;
    float s2x  = 0.f, s2y = 0.f, s2z = 0.f;
    const float R2 = 0.01f;
#pragma unroll 8
    for (int j = 0; j < M_PART; ++j) {
        float4 q = sp4[j];
        float dot = x * q.x + y * q.y + z * q.z;
        float d2e = (q1 + q.w) - 2.0f * dot;
        if (d2e < R2) {
            ++cnt;
            float dx = q.x - x, dy = q.y - y, dz = q.z - z;
            float d2 = dx * dx + dy * dy + dz * dz;
            float d  = sqrtf(fmaxf(d2, 1e-24f));
            float dr = d / 0.1f;
            float w  = fmaxf(1.0f - dr * dr * dr, 0.0f);
            wsum += w;
            swx = fmaf(w, q.x, swx); swy = fmaf(w, q.y, swy); swz = fmaf(w, q.z, swz);
            sdx += dx; sdy += dy; sdz += dz;
            s2x = fmaf(dx, dx, s2x); s2y = fmaf(dy, dy, s2y); s2z = fmaf(dz, dz, s2z);
            if (cnt >= 32) break;
        }
    }
    int ninv = 32 - cnt;
    if (ninv > 0) {
        float d  = sqrtf(fmaxf(q1, 1e-24f));
        float dr = d / 0.1f;
        float w  = fmaxf(1.0f - dr * dr * dr, 0.0f);
        wsum += (float)ninv * w;
    }
    float nf  = (float)cnt;
    float wdn = wsum + 1e-12f;
    float smx = swx / wdn, smy = swy / wdn, smz = swz / wdn;
    float den = nf + 1e-12f;
    float vmx = sdx / den, vmy = sdy / den, vmz = sdz / den;
    float vrx = (s2x - 2.0f * vmx * sdx + nf * vmx * vmx) / den;
    float vry = (s2y - 2.0f * vmy * sdy + nf * vmy * vmy) / den;
    float vrz = (s2z - 2.0f * vmz * sdz + nf * vmz * vmz) / den;

    penc3(xin, p, 0, x, y, z);
    xin[63 * P_PTS + p] = wsum;
#pragma unroll
    for (int f = 0; f < 4; ++f) {
        float s, co;
        sincosf(wsum * (float)(1 << f), &s, &co);
        xin[(64 + 2 * f) * P_PTS + p] = s;
        xin[(65 + 2 * f) * P_PTS + p] = co;
    }
    penc3(xin, p, 72,  smx, smy, smz);
    penc3(xin, p, 135, vrx, vry, vrz);

    float xn[3] = { (x / 1.5f + 1.0f) * 0.5f,
                    (y / 1.5f + 1.0f) * 0.5f,
                    (z / 1.5f + 1.0f) * 0.5f };
#pragma unroll 1
    for (int l = 0; l < NUM_LVL; ++l) {
        double scd   = exp2((7.0 * (double)l) / 15.0) * 16.0 - 1.0;
        float  scale = (float)scd;
        unsigned res = (unsigned)ceil(scd) + 1u;
        bool dense   = ((unsigned long long)res * res * res <= (unsigned long long)HASHMAP_SZ);
        unsigned pg[3]; float fr[3];
#pragma unroll
        for (int c = 0; c < 3; ++c) {
            float pos = fmaf(xn[c], scale, 0.5f);
            float pf  = floorf(pos);
            fr[c] = pos - pf;
            pg[c] = (unsigned)pf;
        }
        float wx[2] = {1.f - fr[0], fr[0]};
        float wy[2] = {1.f - fr[1], fr[1]};
        float wz[2] = {1.f - fr[2], fr[2]};
        const float2* tbl = (const float2*)table + (size_t)l * HASHMAP_SZ;
        float f0 = 0.f, f1 = 0.f;
#pragma unroll
        for (int c = 0; c < 8; ++c) {
            unsigned gx = pg[0] + (unsigned)(c & 1);
            unsigned gy = pg[1] + (unsigned)((c >> 1) & 1);
            unsigned gz = pg[2] + (unsigned)((c >> 2) & 1);
            unsigned idx;
            if (dense) idx = gx + gy * res + gz * res * res;
            else       idx = ((gx * 1u) ^ (gy * 2654435761u) ^ (gz * 805459861u)) & (HASHMAP_SZ - 1u);
            float w = (wx[c & 1] * wy[(c >> 1) & 1]) * wz[(c >> 2) & 1];
            float2 t = tbl[idx];
            f0 = fmaf(w, t.x, f0);
            f1 = fmaf(w, t.y, f1);
        }
        xin[(198 + 2 * l) * P_PTS + p] = f0;
        xin[(199 + 2 * l) * P_PTS + p] = f1;
    }
    xin[230 * P_PTS + p] = 0.0f;
    xin[231 * P_PTS + p] = 0.0f;
}

// ---------------- bf16x3 GEMM, BK=64, swizzled smem, 3 stages -----------------
// 12 K-tiles of 64: t 0..3 (Ahi,Whi)  t 4..7 (Alo,Whi)  t 8..11 (Ahi,Wlo)
#define NKT64   12
#define TILE_B  16384                 // one 128x64 bf16 tile (swizzled, 128B rows)
#define STAGE_B (2 * TILE_B)          // A + W
#define SMEM_GEMM (3 * STAGE_B)       // 98304

__global__ __launch_bounds__(256, 2)
void gemm_mma(const __nv_bfloat16* __restrict__ A, const __nv_bfloat16* __restrict__ W,
              const float* __restrict__ bias,
              __nv_bfloat16* __restrict__ Obf, float* __restrict__ Of32,
              int Nreal, int act, float oscale)
{
    extern __shared__ __align__(16) char smem[];

    const int tid  = threadIdx.x;
    const int warp = tid >> 5, lane = tid & 31;
    const int m0 = blockIdx.y << 7;
    const int n0 = blockIdx.x << 7;
    const int wm = warp & 3, wn = warp >> 2;

    const uint32_t s0 = smem_u32(smem);

    // loader: thread -> row tid>>1, 4 chunks of 16B (halves of a 128B row)
    const int ldrow  = tid >> 1;
    const int ldcb   = (tid & 1) * 4;
    const uint32_t ldr7 = (uint32_t)(ldrow & 7);

    auto load_tile = [&](int t, int s) {
        int pass = t >> 2, k64 = (t & 3) << 6;
        int acol = ((pass == 1) ? 256 : 0) + k64;
        int wcol = ((pass == 2) ? 256 : 0) + k64;
        uint32_t sa = s0 + s * STAGE_B;
        uint32_t sw = sa + TILE_B;
        const __nv_bfloat16* Ag = A + (size_t)(m0 + ldrow) * 512 + acol + ldcb * 8;
        const __nv_bfloat16* Wg = W + (size_t)(n0 + ldrow) * 512 + wcol + ldcb * 8;
#pragma unroll
        for (int j = 0; j < 4; ++j) {
            uint32_t off = (uint32_t)(ldrow * 128) + ((((uint32_t)(ldcb + j)) ^ ldr7) << 4);
            cp16(sa + off, Ag + j * 8);
            cp16(sw + off, Wg + j * 8);
        }
    };

    float c[2][8][4];
#pragma unroll
    for (int mi = 0; mi < 2; ++mi)
#pragma unroll
        for (int nf = 0; nf < 8; ++nf)
#pragma unroll
            for (int r = 0; r < 4; ++r) c[mi][nf][r] = 0.0f;

    load_tile(0, 0); CP_COMMIT();
    load_tile(1, 1); CP_COMMIT();

    // per-lane ldsm row terms
    const int lrow = lane & 15;
    const uint32_t lhi = (uint32_t)(lane >> 4);
    uint32_t rowA[2], r7A[2], rowB[4], r7B[4];
#pragma unroll
    for (int mi = 0; mi < 2; ++mi) {
        int R = wm * 32 + mi * 16 + lrow;
        rowA[mi] = (uint32_t)(R * 128); r7A[mi] = (uint32_t)(R & 7);
    }
#pragma unroll
    for (int nb = 0; nb < 4; ++nb) {
        int R = wn * 64 + nb * 16 + lrow;
        rowB[nb] = (uint32_t)(R * 128); r7B[nb] = (uint32_t)(R & 7);
    }

    uint32_t aF[2][2][4], bF[2][4][4];

    auto ldfr = [&](int buf, int ks, uint32_t sa, uint32_t sw) {
        uint32_t ch = (uint32_t)(2 * ks) + lhi;
#pragma unroll
        for (int mi = 0; mi < 2; ++mi)
            ldsm4(aF[buf][mi], sa + rowA[mi] + ((ch ^ r7A[mi]) << 4));
#pragma unroll
        for (int nb = 0; nb < 4; ++nb)
            ldsm4(bF[buf][nb], sw + rowB[nb] + ((ch ^ r7B[nb]) << 4));
    };

    for (int tt = 0; tt < NKT64; tt += 3) {
#pragma unroll
        for (int s = 0; s < 3; ++s) {
            const int t = tt + s;
            CP_WAIT1();
            __syncthreads();
            const uint32_t sa = s0 + s * STAGE_B;
            const uint32_t sw = sa + TILE_B;
            ldfr(0, 0, sa, sw);
            if (t + 2 < NKT64) load_tile(t + 2, (s + 2) % 3);
            CP_COMMIT();
#pragma unroll
            for (int ks = 0; ks < 4; ++ks) {
                const int cur = ks & 1;
                if (ks < 3) ldfr(cur ^ 1, ks + 1, sa, sw);
#pragma unroll
                for (int mi = 0; mi < 2; ++mi)
#pragma unroll
                    for (int nb = 0; nb < 4; ++nb) {
                        mma16816(c[mi][nb * 2],     aF[cur][mi], bF[cur][nb][0], bF[cur][nb][2]);
                        mma16816(c[mi][nb * 2 + 1], aF[cur][mi], bF[cur][nb][1], bF[cur][nb][3]);
                    }
            }
        }
    }

    // ---- epilogue: direct stores ------------------------------------------
#pragma unroll
    for (int mi = 0; mi < 2; ++mi) {
        int mbase = m0 + wm * 32 + mi * 16 + (lane >> 2);
#pragma unroll
        for (int nf = 0; nf < 8; ++nf) {
            int n = n0 + wn * 64 + nf * 8 + ((lane & 3) << 1);
            if (n >= Nreal && n + 1 >= Nreal) continue;
            float b0 = (n < Nreal)     ? __ldg(bias + n)     : 0.0f;
            float b1 = (n + 1 < Nreal) ? __ldg(bias + n + 1) : 0.0f;
#pragma unroll
            for (int r2 = 0; r2 < 2; ++r2) {
                int m = mbase + r2 * 8;
                float v0 = c[mi][nf][r2 * 2 + 0] + b0;
                float v1 = c[mi][nf][r2 * 2 + 1] + b1;
                if (act) {
                    float y0 = 100.0f * v0, y1 = 100.0f * v1;
                    v0 = (fmaxf(y0, 0.0f) + log1pf(expf(-fabsf(y0)))) * 0.01f;
                    v1 = (fmaxf(y1, 0.0f) + log1pf(expf(-fabsf(y1)))) * 0.01f;
                }
                v0 *= oscale; v1 *= oscale;
                if (Of32) {
                    if (n < Nreal)     Of32[(size_t)m * 257 + n]     = v0;
                    if (n + 1 < Nreal) Of32[(size_t)m * 257 + n + 1] = v1;
                } else if (n < Nreal) {
                    __nv_bfloat16 h0 = __float2bfloat16(v0);
                    __nv_bfloat16 h1 = __float2bfloat16(v1);
                    __nv_bfloat16 l0 = __float2bfloat16(v0 - __bfloat162float(h0));
                    __nv_bfloat16 l1 = __float2bfloat16(v1 - __bfloat162float(h1));
                    *(uint32_t*)(Obf + (size_t)m * 512 + n) =
                        (uint32_t)__bfloat16_as_ushort(h0) | ((uint32_t)__bfloat16_as_ushort(h1) << 16);
                    *(uint32_t*)(Obf + (size_t)m * 512 + 256 + n) =
                        (uint32_t)__bfloat16_as_ushort(l0) | ((uint32_t)__bfloat16_as_ushort(l1) << 16);
                }
            }
        }
    }
}

// ---------------- launch ------------------------------------------------------
extern "C" void kernel_launch(void* const* d_in, const int* in_sizes, int n_in,
                              void* d_out, int out_size)
{
    const float* inp   = (const float*)d_in[0];
    const float* parts = (const float*)d_in[1];
    const float* table = (const float*)d_in[2];
    WPtrs wp;
    const float* B[9];
    for (int l = 0; l < 9; ++l) {
        wp.w[l] = (const float*)d_in[3 + 2 * l];
        B[l]    = (const float*)d_in[4 + 2 * l];
    }

    float* xin;
    __nv_bfloat16 *xb, *ab, *bb, *sb, *wbase;
    cudaGetSymbolAddress((void**)&xin, g_xin);
    cudaGetSymbolAddress((void**)&xb, g_x);
    cudaGetSymbolAddress((void**)&ab, g_a);
    cudaGetSymbolAddress((void**)&bb, g_b);
    cudaGetSymbolAddress((void**)&sb, g_s);
    cudaGetSymbolAddress((void**)&wbase, g_w);

    static const int Nout[9]  = {256, 256, 256, 26, 256, 256, 256, 256, 257};
    static const int Nrows[9] = {256, 256, 256, 128, 256, 256, 256, 256, 384};

    __nv_bfloat16* wt[9];
    {
        size_t off = 0;
        for (int l = 0; l < 9; ++l) { wt[l] = wbase + off; off += (size_t)Nrows[l] * 512; }
    }

    cudaFuncSetAttribute(gemm_mma, cudaFuncAttributeMaxDynamicSharedMemorySize, SMEM_GEMM);
    cudaFuncSetAttribute(feature_kernel, cudaFuncAttributeMaxDynamicSharedMemorySize, M_PART * 16);

    prep_w_all<<<(2304 * 256 + 255) / 256, 256>>>(wp, wbase);
    feature_kernel<<<128, 128, M_PART * 16>>>(inp, parts, table, xin);
    conv_tr<<<dim3(8, P_PTS / 32), dim3(32, 8)>>>(xin, xb, 0, 232, 0, 1.0f, 0);
    // skip buffer: cols 26..255 = xin * inv_sqrt2 (cols 0..25 come from layer 3)
    conv_tr<<<dim3(8, P_PTS / 32), dim3(32, 8)>>>(xin, sb, 26, 256, -26, INV_SQRT2, 26);

    auto gemm = [&](const __nv_bfloat16* Ain, int l, __nv_bfloat16* Obf, float* Of,
                    int act, float os) {
        dim3 grid(Nrows[l] / 128, P_PTS / 128);
        gemm_mma<<<grid, 256, SMEM_GEMM>>>(Ain, wt[l], B[l], Obf, Of, Nout[l], act, os);
    };

    gemm(xb, 0, ab, nullptr, 1, 1.0f);
    gemm(ab, 1, bb, nullptr, 1, 1.0f);
    gemm(bb, 2, ab, nullptr, 1, 1.0f);
    gemm(ab, 3, sb, nullptr, 1, INV_SQRT2);   // writes cols 0..25 (pre-scaled)
    gemm(sb, 4, ab, nullptr, 1, 1.0f);
    gemm(ab, 5, bb, nullptr, 1, 1.0f);
    gemm(bb, 6, ab, nullptr, 1, 1.0f);
    gemm(ab, 7, bb, nullptr, 1, 1.0f);
    gemm(bb, 8, nullptr, (float*)d_out, 0, 1.0f);
}

// round 6
// speedup vs baseline: 1.0847x; 1.0847x over previous
#include <cuda_runtime.h>
#include <cuda_bf16.h>
#include <math.h>
#include <stdint.h>

#define P_PTS     16384
#define M_PART    4096
#define HASHMAP_SZ 524288u
#define NUM_LVL   16
#define INV_SQRT2 0.70710678118654752f

// ---------------- scratch (device globals; no allocation allowed) -------------
// activations: [P][512] bf16  (cols 0..255 = hi, 256..511 = lo)
__device__ __align__(16) float g_xin[232 * P_PTS];
__device__ __align__(16) __nv_bfloat16 g_x[P_PTS * 512];
__device__ __align__(16) __nv_bfloat16 g_a[P_PTS * 512];
__device__ __align__(16) __nv_bfloat16 g_b[P_PTS * 512];
__device__ __align__(16) __nv_bfloat16 g_s[P_PTS * 512];   // layer-4 (skip) input
__device__ __align__(16) __nv_bfloat16 g_w[2304 * 512];

// ---------------- PTX helpers -------------------------------------------------
static __device__ __forceinline__ uint32_t smem_u32(const void* p) {
    uint32_t a;
    asm("{ .reg .u64 t; cvta.to.shared.u64 t, %1; cvt.u32.u64 %0, t; }" : "=r"(a) : "l"(p));
    return a;
}
static __device__ __forceinline__ void cp16(uint32_t s, const void* g) {
    asm volatile("cp.async.ca.shared.global [%0], [%1], 16;" :: "r"(s), "l"(g));
}
#define CP_COMMIT()  asm volatile("cp.async.commit_group;" ::: "memory")
#define CP_WAIT1()   asm volatile("cp.async.wait_group 1;" ::: "memory")

static __device__ __forceinline__ void ldsm4(uint32_t* r, uint32_t a) {
    asm volatile("ldmatrix.sync.aligned.m8n8.x4.shared.b16 {%0,%1,%2,%3}, [%4];"
                 : "=r"(r[0]), "=r"(r[1]), "=r"(r[2]), "=r"(r[3]) : "r"(a));
}
static __device__ __forceinline__ void mma16816(float* c, const uint32_t* a,
                                                uint32_t b0, uint32_t b1) {
    asm volatile(
        "mma.sync.aligned.m16n8k16.row.col.f32.bf16.bf16.f32 "
        "{%0,%1,%2,%3}, {%4,%5,%6,%7}, {%8,%9}, {%0,%1,%2,%3};"
        : "+f"(c[0]), "+f"(c[1]), "+f"(c[2]), "+f"(c[3])
        : "r"(a[0]), "r"(a[1]), "r"(a[2]), "r"(a[3]), "r"(b0), "r"(b1));
}

// ---------------- fused weight prep -------------------------------------------
struct WPtrs { const float* w[9]; };

__global__ void prep_w_all(WPtrs wp, __nv_bfloat16* __restrict__ out)
{
    int i = blockIdx.x * blockDim.x + threadIdx.x;
    if (i >= 2304 * 256) return;
    int r = i >> 8, k = i & 255;
    const int cum[10]  = {0, 256, 512, 768, 896, 1152, 1408, 1664, 1920, 2304};
    const int nout[9]  = {256, 256, 256, 26, 256, 256, 256, 256, 257};
    const int kact[9]  = {230, 256, 256, 256, 256, 256, 256, 256, 256};
    int l = 0;
#pragma unroll
    for (int t = 1; t < 9; ++t) if (r >= cum[t]) l = t;
    int n = r - cum[l];
    float v = (n < nout[l] && k < kact[l]) ? wp.w[l][n * kact[l] + k] : 0.0f;
    __nv_bfloat16 h = __float2bfloat16(v);
    out[(size_t)r * 512 + k]       = h;
    out[(size_t)r * 512 + 256 + k] = __float2bfloat16(v - __bfloat162float(h));
}

// ---------------- transpose + bf16-split --------------------------------------
__global__ void conv_tr(const float* __restrict__ src, __nv_bfloat16* __restrict__ dst,
                        int vlo, int vhi, int srcoff, float scale, int wlo)
{
    __shared__ float s[32][33];
    int tx = threadIdx.x, ty = threadIdx.y;
    int ct = blockIdx.x, pt = blockIdx.y;
#pragma unroll
    for (int r2 = 0; r2 < 4; ++r2) {
        int ci = ty + r2 * 8;
        int c = ct * 32 + ci;
        int p = pt * 32 + tx;
        float v = 0.0f;
        if (c >= vlo && c < vhi) v = src[(size_t)(c + srcoff) * P_PTS + p] * scale;
        s[ci][tx] = v;
    }
    __syncthreads();
#pragma unroll
    for (int r2 = 0; r2 < 4; ++r2) {
        int pi = ty + r2 * 8;
        int p = pt * 32 + pi;
        int c = ct * 32 + tx;
        if (c >= wlo) {
            float v = s[tx][pi];
            __nv_bfloat16 h = __float2bfloat16(v);
            dst[(size_t)p * 512 + c]       = h;
            dst[(size_t)p * 512 + 256 + c] = __float2bfloat16(v - __bfloat162float(h));
        }
    }
}

// ---------------- feature kernel ----------------------------------------------
__device__ __forceinline__ void penc3(float* __restrict__ xin, int p, int base,
                                      float a, float b, float c)
{
    xin[(base + 0) * P_PTS + p] = a;
    xin[(base + 1) * P_PTS + p] = b;
    xin[(base + 2) * P_PTS + p] = c;
    float v[3] = {a, b, c};
#pragma unroll
    for (int f = 0; f < 10; ++f) {
        float fr = (float)(1 << f);
#pragma unroll
        for (int ch = 0; ch < 3; ++ch) {
            float s, co;
            sincosf(v[ch] * fr, &s, &co);
            xin[(base + 3 + f * 6 + ch)     * P_PTS + p] = s;
            xin[(base + 3 + f * 6 + 3 + ch) * P_PTS + p] = co;
        }
    }
}

__global__ void feature_kernel(const float* __restrict__ inp,
                               const float* __restrict__ parts,
                               const float* __restrict__ table,
                               float* __restrict__ xin)
{
    extern __shared__ float4 sp4[];
    int tid = threadIdx.x;
    for (int i = tid; i < M_PART; i += blockDim.x) {
        float px = parts[3 * i], py = parts[3 * i + 1], pz = parts[3 * i + 2];
        sp4[i] = make_float4(px, py, pz, (px * px + py * py) + pz * pz);
    }
    __syncthreads();

    int p = blockIdx.x * blockDim.x + tid;
    float x = inp[3 * p + 0], y = inp[3 * p + 1], z = inp[3 * p + 2];
    float q1 = (x * x + y * y) + z * z;

    int   cnt  = 0;
    float wsum = 0.f, swx = 0.f, swy = 0.f, swz = 0.f;
    float sdx  = 0.f, sdy = 0.f, sdz = 0.f;
    float s2x  = 0.f, s2y = 0.f, s2z = 0.f;
    const float R2 = 0.01f;
#pragma unroll 8
    for (int j = 0; j < M_PART; ++j) {
        float4 q = sp4[j];
        float dot = x * q.x + y * q.y + z * q.z;
        float d2e = (q1 + q.w) - 2.0f * dot;
        if (d2e < R2) {
            ++cnt;
            float dx = q.x - x, dy = q.y - y, dz = q.z - z;
            float d2 = dx * dx + dy * dy + dz * dz;
            float d  = sqrtf(fmaxf(d2, 1e-24f));
            float dr = d / 0.1f;
            float w  = fmaxf(1.0f - dr * dr * dr, 0.0f);
            wsum += w;
            swx = fmaf(w, q.x, swx); swy = fmaf(w, q.y, swy); swz = fmaf(w, q.z, swz);
            sdx += dx; sdy += dy; sdz += dz;
            s2x = fmaf(dx, dx, s2x); s2y = fmaf(dy, dy, s2y); s2z = fmaf(dz, dz, s2z);
            if (cnt >= 32) break;
        }
    }
    int ninv = 32 - cnt;
    if (ninv > 0) {
        float d  = sqrtf(fmaxf(q1, 1e-24f));
        float dr = d / 0.1f;
        float w  = fmaxf(1.0f - dr * dr * dr, 0.0f);
        wsum += (float)ninv * w;
    }
    float nf  = (float)cnt;
    float wdn = wsum + 1e-12f;
    float smx = swx / wdn, smy = swy / wdn, smz = swz / wdn;
    float den = nf + 1e-12f;
    float vmx = sdx / den, vmy = sdy / den, vmz = sdz / den;
    float vrx = (s2x - 2.0f * vmx * sdx + nf * vmx * vmx) / den;
    float vry = (s2y - 2.0f * vmy * sdy + nf * vmy * vmy) / den;
    float vrz = (s2z - 2.0f * vmz * sdz + nf * vmz * vmz) / den;

    penc3(xin, p, 0, x, y, z);
    xin[63 * P_PTS + p] = wsum;
#pragma unroll
    for (int f = 0; f < 4; ++f) {
        float s, co;
        sincosf(wsum * (float)(1 << f), &s, &co);
        xin[(64 + 2 * f) * P_PTS + p] = s;
        xin[(65 + 2 * f) * P_PTS + p] = co;
    }
    penc3(xin, p, 72,  smx, smy, smz);
    penc3(xin, p, 135, vrx, vry, vrz);

    float xn[3] = { (x / 1.5f + 1.0f) * 0.5f,
                    (y / 1.5f + 1.0f) * 0.5f,
                    (z / 1.5f + 1.0f) * 0.5f };
#pragma unroll 1
    for (int l = 0; l < NUM_LVL; ++l) {
        double scd   = exp2((7.0 * (double)l) / 15.0) * 16.0 - 1.0;
        float  scale = (float)scd;
        unsigned res = (unsigned)ceil(scd) + 1u;
        bool dense   = ((unsigned long long)res * res * res <= (unsigned long long)HASHMAP_SZ);
        unsigned pg[3]; float fr[3];
#pragma unroll
        for (int c = 0; c < 3; ++c) {
            float pos = fmaf(xn[c], scale, 0.5f);
            float pf  = floorf(pos);
            fr[c] = pos - pf;
            pg[c] = (unsigned)pf;
        }
        float wx[2] = {1.f - fr[0], fr[0]};
        float wy[2] = {1.f - fr[1], fr[1]};
        float wz[2] = {1.f - fr[2], fr[2]};
        const float2* tbl = (const float2*)table + (size_t)l * HASHMAP_SZ;
        float f0 = 0.f, f1 = 0.f;
#pragma unroll
        for (int c = 0; c < 8; ++c) {
            unsigned gx = pg[0] + (unsigned)(c & 1);
            unsigned gy = pg[1] + (unsigned)((c >> 1) & 1);
            unsigned gz = pg[2] + (unsigned)((c >> 2) & 1);
            unsigned idx;
            if (dense) idx = gx + gy * res + gz * res * res;
            else       idx = ((gx * 1u) ^ (gy * 2654435761u) ^ (gz * 805459861u)) & (HASHMAP_SZ - 1u);
            float w = (wx[c & 1] * wy[(c >> 1) & 1]) * wz[(c >> 2) & 1];
            float2 t = tbl[idx];
            f0 = fmaf(w, t.x, f0);
            f1 = fmaf(w, t.y, f1);
        }
        xin[(198 + 2 * l) * P_PTS + p] = f0;
        xin[(199 + 2 * l) * P_PTS + p] = f1;
    }
    xin[230 * P_PTS + p] = 0.0f;
    xin[231 * P_PTS + p] = 0.0f;
}

// ---------------- bf16x3 GEMM: hi/lo co-resident K-chunks ---------------------
// 8 K-chunks of 32. Per chunk the stage holds Ahi|Alo|Whi|Wlo (4 x 8KB).
// Passes per chunk: Ahi*Whi, Alo*Whi (reuse W frags), Ahi*Wlo.
#define NCHUNK 8
#define T_AHI 0
#define T_ALO 8192
#define T_WHI 16384
#define T_WLO 24576
#define STAGE_B 32768
#define SMEM_GEMM (3 * STAGE_B)      // 98304 -> 2 CTAs/SM

__global__ __launch_bounds__(256, 2)
void gemm_mma(const __nv_bfloat16* __restrict__ A, const __nv_bfloat16* __restrict__ W,
              const float* __restrict__ bias,
              __nv_bfloat16* __restrict__ Obf, float* __restrict__ Of32,
              int Nreal, int act, float oscale)
{
    extern __shared__ __align__(16) char smem[];

    const int tid  = threadIdx.x;
    const int warp = tid >> 5, lane = tid & 31;
    const int m0 = blockIdx.y << 7;
    const int n0 = blockIdx.x << 7;
    const int wm = warp & 3, wn = warp >> 2;

    const uint32_t s0 = smem_u32(smem);

    // loader: c = tid&3 (16B chunk in row), rows rbase and rbase+64
    const int rbase = tid >> 2;
    const int cc    = tid & 3;
    const __nv_bfloat16* pA = A + (size_t)(m0 + rbase) * 512 + cc * 8;
    const __nv_bfloat16* pW = W + (size_t)(n0 + rbase) * 512 + cc * 8;
    // smem offset for (rbase, cc); row+64 variant = +4096 (swizzle key invariant)
    const uint32_t so0 = (uint32_t)(rbase * 64) + (((uint32_t)cc ^ (((uint32_t)rbase >> 1) & 3)) << 4);

    auto load_stage = [&](int kc, int stg) {
        uint32_t sb = s0 + stg * STAGE_B;
        int k32 = kc << 5;
        cp16(sb + T_AHI + so0,        pA + k32);
        cp16(sb + T_AHI + so0 + 4096, pA + 64 * 512 + k32);
        cp16(sb + T_ALO + so0,        pA + 256 + k32);
        cp16(sb + T_ALO + so0 + 4096, pA + 64 * 512 + 256 + k32);
        cp16(sb + T_WHI + so0,        pW + k32);
        cp16(sb + T_WHI + so0 + 4096, pW + 64 * 512 + k32);
        cp16(sb + T_WLO + so0,        pW + 256 + k32);
        cp16(sb + T_WLO + so0 + 4096, pW + 64 * 512 + 256 + k32);
    };

    float c[2][8][4];
#pragma unroll
    for (int mi = 0; mi < 2; ++mi)
#pragma unroll
        for (int nf = 0; nf < 8; ++nf)
#pragma unroll
            for (int r = 0; r < 4; ++r) c[mi][nf][r] = 0.0f;

    load_stage(0, 0); CP_COMMIT();
    load_stage(1, 1); CP_COMMIT();

    // per-lane ldsm row terms (64B rows, 4-chunk swizzle key (row>>1)&3)
    const int lrow = lane & 15;
    const uint32_t lhi = (uint32_t)(lane >> 4);
    uint32_t rowA[2], rqA[2], rowB[4], rqB[4];
#pragma unroll
    for (int mi = 0; mi < 2; ++mi) {
        int R = wm * 32 + mi * 16 + lrow;
        rowA[mi] = (uint32_t)(R * 64); rqA[mi] = (uint32_t)((R >> 1) & 3);
    }
#pragma unroll
    for (int nb = 0; nb < 4; ++nb) {
        int R = wn * 64 + nb * 16 + lrow;
        rowB[nb] = (uint32_t)(R * 64); rqB[nb] = (uint32_t)((R >> 1) & 3);
    }

    for (int t = 0; t < NCHUNK; ++t) {
        CP_WAIT1();
        __syncthreads();
        if (t + 2 < NCHUNK) load_stage(t + 2, (t + 2) % 3);
        CP_COMMIT();

        const uint32_t sb = s0 + (t % 3) * STAGE_B;
        uint32_t aF[2][4], bF[4][4];

        // passes 0 (Ahi*Whi) and 1 (Alo*Whi), W frags reused
#pragma unroll
        for (int ks = 0; ks < 2; ++ks) {
            const uint32_t ch = (uint32_t)(2 * ks) + lhi;
#pragma unroll
            for (int nb = 0; nb < 4; ++nb)
                ldsm4(bF[nb], sb + T_WHI + rowB[nb] + ((ch ^ rqB[nb]) << 4));
#pragma unroll
            for (int mi = 0; mi < 2; ++mi)
                ldsm4(aF[mi], sb + T_AHI + rowA[mi] + ((ch ^ rqA[mi]) << 4));
#pragma unroll
            for (int mi = 0; mi < 2; ++mi)
#pragma unroll
                for (int nb = 0; nb < 4; ++nb) {
                    mma16816(c[mi][nb * 2],     aF[mi], bF[nb][0], bF[nb][2]);
                    mma16816(c[mi][nb * 2 + 1], aF[mi], bF[nb][1], bF[nb][3]);
                }
#pragma unroll
            for (int mi = 0; mi < 2; ++mi)
                ldsm4(aF[mi], sb + T_ALO + rowA[mi] + ((ch ^ rqA[mi]) << 4));
#pragma unroll
            for (int mi = 0; mi < 2; ++mi)
#pragma unroll
                for (int nb = 0; nb < 4; ++nb) {
                    mma16816(c[mi][nb * 2],     aF[mi], bF[nb][0], bF[nb][2]);
                    mma16816(c[mi][nb * 2 + 1], aF[mi], bF[nb][1], bF[nb][3]);
                }
        }
        // pass 2 (Ahi*Wlo)
#pragma unroll
        for (int ks = 0; ks < 2; ++ks) {
            const uint32_t ch = (uint32_t)(2 * ks) + lhi;
#pragma unroll
            for (int nb = 0; nb < 4; ++nb)
                ldsm4(bF[nb], sb + T_WLO + rowB[nb] + ((ch ^ rqB[nb]) << 4));
#pragma unroll
            for (int mi = 0; mi < 2; ++mi)
                ldsm4(aF[mi], sb + T_AHI + rowA[mi] + ((ch ^ rqA[mi]) << 4));
#pragma unroll
            for (int mi = 0; mi < 2; ++mi)
#pragma unroll
                for (int nb = 0; nb < 4; ++nb) {
                    mma16816(c[mi][nb * 2],     aF[mi], bF[nb][0], bF[nb][2]);
                    mma16816(c[mi][nb * 2 + 1], aF[mi], bF[nb][1], bF[nb][3]);
                }
        }
    }

    // ---- epilogue: direct stores ------------------------------------------
#pragma unroll
    for (int mi = 0; mi < 2; ++mi) {
        int mbase = m0 + wm * 32 + mi * 16 + (lane >> 2);
#pragma unroll
        for (int nf = 0; nf < 8; ++nf) {
            int n = n0 + wn * 64 + nf * 8 + ((lane & 3) << 1);
            if (n >= Nreal && n + 1 >= Nreal) continue;
            float b0 = (n < Nreal)     ? __ldg(bias + n)     : 0.0f;
            float b1 = (n + 1 < Nreal) ? __ldg(bias + n + 1) : 0.0f;
#pragma unroll
            for (int r2 = 0; r2 < 2; ++r2) {
                int m = mbase + r2 * 8;
                float v0 = c[mi][nf][r2 * 2 + 0] + b0;
                float v1 = c[mi][nf][r2 * 2 + 1] + b1;
                if (act) {
                    float y0 = 100.0f * v0, y1 = 100.0f * v1;
                    v0 = (fmaxf(y0, 0.0f) + log1pf(expf(-fabsf(y0)))) * 0.01f;
                    v1 = (fmaxf(y1, 0.0f) + log1pf(expf(-fabsf(y1)))) * 0.01f;
                }
                v0 *= oscale; v1 *= oscale;
                if (Of32) {
                    if (n < Nreal)     Of32[(size_t)m * 257 + n]     = v0;
                    if (n + 1 < Nreal) Of32[(size_t)m * 257 + n + 1] = v1;
                } else if (n < Nreal) {
                    __nv_bfloat16 h0 = __float2bfloat16(v0);
                    __nv_bfloat16 h1 = __float2bfloat16(v1);
                    __nv_bfloat16 l0 = __float2bfloat16(v0 - __bfloat162float(h0));
                    __nv_bfloat16 l1 = __float2bfloat16(v1 - __bfloat162float(h1));
                    *(uint32_t*)(Obf + (size_t)m * 512 + n) =
                        (uint32_t)__bfloat16_as_ushort(h0) | ((uint32_t)__bfloat16_as_ushort(h1) << 16);
                    *(uint32_t*)(Obf + (size_t)m * 512 + 256 + n) =
                        (uint32_t)__bfloat16_as_ushort(l0) | ((uint32_t)__bfloat16_as_ushort(l1) << 16);
                }
            }
        }
    }
}

// ---------------- launch ------------------------------------------------------
extern "C" void kernel_launch(void* const* d_in, const int* in_sizes, int n_in,
                              void* d_out, int out_size)
{
    const float* inp   = (const float*)d_in[0];
    const float* parts = (const float*)d_in[1];
    const float* table = (const float*)d_in[2];
    WPtrs wp;
    const float* B[9];
    for (int l = 0; l < 9; ++l) {
        wp.w[l] = (const float*)d_in[3 + 2 * l];
        B[l]    = (const float*)d_in[4 + 2 * l];
    }

    float* xin;
    __nv_bfloat16 *xb, *ab, *bb, *sb, *wbase;
    cudaGetSymbolAddress((void**)&xin, g_xin);
    cudaGetSymbolAddress((void**)&xb, g_x);
    cudaGetSymbolAddress((void**)&ab, g_a);
    cudaGetSymbolAddress((void**)&bb, g_b);
    cudaGetSymbolAddress((void**)&sb, g_s);
    cudaGetSymbolAddress((void**)&wbase, g_w);

    static const int Nout[9]  = {256, 256, 256, 26, 256, 256, 256, 256, 257};
    static const int Nrows[9] = {256, 256, 256, 128, 256, 256, 256, 256, 384};

    __nv_bfloat16* wt[9];
    {
        size_t off = 0;
        for (int l = 0; l < 9; ++l) { wt[l] = wbase + off; off += (size_t)Nrows[l] * 512; }
    }

    cudaFuncSetAttribute(gemm_mma, cudaFuncAttributeMaxDynamicSharedMemorySize, SMEM_GEMM);
    cudaFuncSetAttribute(feature_kernel, cudaFuncAttributeMaxDynamicSharedMemorySize, M_PART * 16);

    prep_w_all<<<(2304 * 256 + 255) / 256, 256>>>(wp, wbase);
    feature_kernel<<<128, 128, M_PART * 16>>>(inp, parts, table, xin);
    conv_tr<<<dim3(8, P_PTS / 32), dim3(32, 8)>>>(xin, xb, 0, 232, 0, 1.0f, 0);
    // skip buffer: cols 26..255 = xin * inv_sqrt2 (cols 0..25 come from layer 3)
    conv_tr<<<dim3(8, P_PTS / 32), dim3(32, 8)>>>(xin, sb, 26, 256, -26, INV_SQRT2, 26);

    auto gemm = [&](const __nv_bfloat16* Ain, int l, __nv_bfloat16* Obf, float* Of,
                    int act, float os) {
        dim3 grid(Nrows[l] / 128, P_PTS / 128);
        gemm_mma<<<grid, 256, SMEM_GEMM>>>(Ain, wt[l], B[l], Obf, Of, Nout[l], act, os);
    };

    gemm(xb, 0, ab, nullptr, 1, 1.0f);
    gemm(ab, 1, bb, nullptr, 1, 1.0f);
    gemm(bb, 2, ab, nullptr, 1, 1.0f);
    gemm(ab, 3, sb, nullptr, 1, INV_SQRT2);   // writes cols 0..25 (pre-scaled)
    gemm(sb, 4, ab, nullptr, 1, 1.0f);
    gemm(ab, 5, bb, nullptr, 1, 1.0f);
    gemm(bb, 6, ab, nullptr, 1, 1.0f);
    gemm(ab, 7, bb, nullptr, 1, 1.0f);
    gemm(bb, 8, nullptr, (float*)d_out, 0, 1.0f);
}

// round 7
// speedup vs baseline: 1.1437x; 1.0543x over previous
#include <cuda_runtime.h>
#include <cuda_bf16.h>
#include <math.h>
#include <stdint.h>

#define P_PTS     16384
#define M_PART    4096
#define HASHMAP_SZ 524288u
#define NUM_LVL   16
#define INV_SQRT2 0.70710678118654752f

// ---------------- scratch (device globals; no allocation allowed) -------------
// activations: [P][512] bf16  (cols 0..255 = hi, 256..511 = lo)
__device__ __align__(16) float g_xin[232 * P_PTS];
__device__ __align__(16) __nv_bfloat16 g_x[P_PTS * 512];
__device__ __align__(16) __nv_bfloat16 g_a[P_PTS * 512];
__device__ __align__(16) __nv_bfloat16 g_b[P_PTS * 512];
__device__ __align__(16) __nv_bfloat16 g_s[P_PTS * 512];   // layer-4 (skip) input
__device__ __align__(16) __nv_bfloat16 g_w[2304 * 512];

// ---------------- PTX helpers -------------------------------------------------
static __device__ __forceinline__ uint32_t smem_u32(const void* p) {
    uint32_t a;
    asm("{ .reg .u64 t; cvta.to.shared.u64 t, %1; cvt.u32.u64 %0, t; }" : "=r"(a) : "l"(p));
    return a;
}
static __device__ __forceinline__ void cp16(uint32_t s, const void* g) {
    asm volatile("cp.async.ca.shared.global [%0], [%1], 16;" :: "r"(s), "l"(g));
}
#define CP_COMMIT()  asm volatile("cp.async.commit_group;" ::: "memory")
#define CP_WAIT1()   asm volatile("cp.async.wait_group 1;" ::: "memory")

static __device__ __forceinline__ void ldsm4(uint32_t* r, uint32_t a) {
    asm volatile("ldmatrix.sync.aligned.m8n8.x4.shared.b16 {%0,%1,%2,%3}, [%4];"
                 : "=r"(r[0]), "=r"(r[1]), "=r"(r[2]), "=r"(r[3]) : "r"(a));
}
static __device__ __forceinline__ void mma16816(float* c, const uint32_t* a,
                                                uint32_t b0, uint32_t b1) {
    asm volatile(
        "mma.sync.aligned.m16n8k16.row.col.f32.bf16.bf16.f32 "
        "{%0,%1,%2,%3}, {%4,%5,%6,%7}, {%8,%9}, {%0,%1,%2,%3};"
        : "+f"(c[0]), "+f"(c[1]), "+f"(c[2]), "+f"(c[3])
        : "r"(a[0]), "r"(a[1]), "r"(a[2]), "r"(a[3]), "r"(b0), "r"(b1));
}
// softplus(100x)/100 with fast intrinsics; |err| ~1e-7 absolute
static __device__ __forceinline__ float softplus100(float v) {
    float y = 100.0f * v;
    return (fmaxf(y, 0.0f) + __logf(1.0f + __expf(-fabsf(y)))) * 0.01f;
}

// ---------------- fused weight prep -------------------------------------------
struct WPtrs { const float* w[9]; };

__global__ void prep_w_all(WPtrs wp, __nv_bfloat16* __restrict__ out)
{
    int i = blockIdx.x * blockDim.x + threadIdx.x;
    if (i >= 2304 * 256) return;
    int r = i >> 8, k = i & 255;
    const int cum[10]  = {0, 256, 512, 768, 896, 1152, 1408, 1664, 1920, 2304};
    const int nout[9]  = {256, 256, 256, 26, 256, 256, 256, 256, 257};
    const int kact[9]  = {230, 256, 256, 256, 256, 256, 256, 256, 256};
    int l = 0;
#pragma unroll
    for (int t = 1; t < 9; ++t) if (r >= cum[t]) l = t;
    int n = r - cum[l];
    float v = (n < nout[l] && k < kact[l]) ? wp.w[l][n * kact[l] + k] : 0.0f;
    __nv_bfloat16 h = __float2bfloat16(v);
    out[(size_t)r * 512 + k]       = h;
    out[(size_t)r * 512 + 256 + k] = __float2bfloat16(v - __bfloat162float(h));
}

// ---------------- fused transpose + bf16-split: xin -> g_x AND g_s ------------
__global__ void conv_tr2(const float* __restrict__ src,
                         __nv_bfloat16* __restrict__ dx,
                         __nv_bfloat16* __restrict__ ds)
{
    __shared__ float s[32][33];
    int tx = threadIdx.x, ty = threadIdx.y;
    int ct = blockIdx.x, pt = blockIdx.y;
#pragma unroll
    for (int r2 = 0; r2 < 4; ++r2) {
        int ci = ty + r2 * 8;
        int c = ct * 32 + ci;
        int p = pt * 32 + tx;
        s[ci][tx] = (c < 232) ? src[(size_t)c * P_PTS + p] : 0.0f;
    }
    __syncthreads();
#pragma unroll
    for (int r2 = 0; r2 < 4; ++r2) {
        int pi = ty + r2 * 8;
        int p = pt * 32 + pi;
        int c = ct * 32 + tx;
        float v = s[tx][pi];
        __nv_bfloat16 h = __float2bfloat16(v);
        dx[(size_t)p * 512 + c]       = h;
        dx[(size_t)p * 512 + 256 + c] = __float2bfloat16(v - __bfloat162float(h));
        if (c < 230) {
            float vs = v * INV_SQRT2;
            __nv_bfloat16 hs = __float2bfloat16(vs);
            ds[(size_t)p * 512 + c + 26]       = hs;
            ds[(size_t)p * 512 + 256 + c + 26] = __float2bfloat16(vs - __bfloat162float(hs));
        }
    }
}

// ---------------- feature kernel ----------------------------------------------
__device__ __forceinline__ void penc3(float* __restrict__ xin, int p, int base,
                                      float a, float b, float c)
{
    xin[(base + 0) * P_PTS + p] = a;
    xin[(base + 1) * P_PTS + p] = b;
    xin[(base + 2) * P_PTS + p] = c;
    float v[3] = {a, b, c};
#pragma unroll
    for (int f = 0; f < 10; ++f) {
        float fr = (float)(1 << f);
#pragma unroll
        for (int ch = 0; ch < 3; ++ch) {
            float s, co;
            sincosf(v[ch] * fr, &s, &co);
            xin[(base + 3 + f * 6 + ch)     * P_PTS + p] = s;
            xin[(base + 3 + f * 6 + 3 + ch) * P_PTS + p] = co;
        }
    }
}

__global__ void feature_kernel(const float* __restrict__ inp,
                               const float* __restrict__ parts,
                               const float* __restrict__ table,
                               float* __restrict__ xin)
{
    extern __shared__ float4 sp4[];
    int tid = threadIdx.x;
    for (int i = tid; i < M_PART; i += blockDim.x) {
        float px = parts[3 * i], py = parts[3 * i + 1], pz = parts[3 * i + 2];
        sp4[i] = make_float4(px, py, pz, (px * px + py * py) + pz * pz);
    }
    __syncthreads();

    int p = blockIdx.x * blockDim.x + tid;
    float x = inp[3 * p + 0], y = inp[3 * p + 1], z = inp[3 * p + 2];
    float q1 = (x * x + y * y) + z * z;

    int   cnt  = 0;
    float wsum = 0.f, swx = 0.f, swy = 0.f, swz = 0.f;
    float sdx  = 0.f, sdy = 0.f, sdz = 0.f;
    float s2x  = 0.f, s2y = 0.f, s2z = 0.f;
    const float R2 = 0.01f;
#pragma unroll 8
    for (int j = 0; j < M_PART; ++j) {
        float4 q = sp4[j];
        float dot = x * q.x + y * q.y + z * q.z;
        float d2e = (q1 + q.w) - 2.0f * dot;
        if (d2e < R2) {
            ++cnt;
            float dx = q.x - x, dy = q.y - y, dz = q.z - z;
            float d2 = dx * dx + dy * dy + dz * dz;
            float d  = sqrtf(fmaxf(d2, 1e-24f));
            float dr = d / 0.1f;
            float w  = fmaxf(1.0f - dr * dr * dr, 0.0f);
            wsum += w;
            swx = fmaf(w, q.x, swx); swy = fmaf(w, q.y, swy); swz = fmaf(w, q.z, swz);
            sdx += dx; sdy += dy; sdz += dz;
            s2x = fmaf(dx, dx, s2x); s2y = fmaf(dy, dy, s2y); s2z = fmaf(dz, dz, s2z);
            if (cnt >= 32) break;
        }
    }
    int ninv = 32 - cnt;
    if (ninv > 0) {
        float d  = sqrtf(fmaxf(q1, 1e-24f));
        float dr = d / 0.1f;
        float w  = fmaxf(1.0f - dr * dr * dr, 0.0f);
        wsum += (float)ninv * w;
    }
    float nf  = (float)cnt;
    float wdn = wsum + 1e-12f;
    float smx = swx / wdn, smy = swy / wdn, smz = swz / wdn;
    float den = nf + 1e-12f;
    float vmx = sdx / den, vmy = sdy / den, vmz = sdz / den;
    float vrx = (s2x - 2.0f * vmx * sdx + nf * vmx * vmx) / den;
    float vry = (s2y - 2.0f * vmy * sdy + nf * vmy * vmy) / den;
    float vrz = (s2z - 2.0f * vmz * sdz + nf * vmz * vmz) / den;

    penc3(xin, p, 0, x, y, z);
    xin[63 * P_PTS + p] = wsum;
#pragma unroll
    for (int f = 0; f < 4; ++f) {
        float s, co;
        sincosf(wsum * (float)(1 << f), &s, &co);
        xin[(64 + 2 * f) * P_PTS + p] = s;
        xin[(65 + 2 * f) * P_PTS + p] = co;
    }
    penc3(xin, p, 72,  smx, smy, smz);
    penc3(xin, p, 135, vrx, vry, vrz);

    float xn[3] = { (x / 1.5f + 1.0f) * 0.5f,
                    (y / 1.5f + 1.0f) * 0.5f,
                    (z / 1.5f + 1.0f) * 0.5f };
#pragma unroll 1
    for (int l = 0; l < NUM_LVL; ++l) {
        double scd   = exp2((7.0 * (double)l) / 15.0) * 16.0 - 1.0;
        float  scale = (float)scd;
        unsigned res = (unsigned)ceil(scd) + 1u;
        bool dense   = ((unsigned long long)res * res * res <= (unsigned long long)HASHMAP_SZ);
        unsigned pg[3]; float fr[3];
#pragma unroll
        for (int c = 0; c < 3; ++c) {
            float pos = fmaf(xn[c], scale, 0.5f);
            float pf  = floorf(pos);
            fr[c] = pos - pf;
            pg[c] = (unsigned)pf;
        }
        float wx[2] = {1.f - fr[0], fr[0]};
        float wy[2] = {1.f - fr[1], fr[1]};
        float wz[2] = {1.f - fr[2], fr[2]};
        const float2* tbl = (const float2*)table + (size_t)l * HASHMAP_SZ;
        float f0 = 0.f, f1 = 0.f;
#pragma unroll
        for (int c = 0; c < 8; ++c) {
            unsigned gx = pg[0] + (unsigned)(c & 1);
            unsigned gy = pg[1] + (unsigned)((c >> 1) & 1);
            unsigned gz = pg[2] + (unsigned)((c >> 2) & 1);
            unsigned idx;
            if (dense) idx = gx + gy * res + gz * res * res;
            else       idx = ((gx * 1u) ^ (gy * 2654435761u) ^ (gz * 805459861u)) & (HASHMAP_SZ - 1u);
            float w = (wx[c & 1] * wy[(c >> 1) & 1]) * wz[(c >> 2) & 1];
            float2 t = tbl[idx];
            f0 = fmaf(w, t.x, f0);
            f1 = fmaf(w, t.y, f1);
        }
        xin[(198 + 2 * l) * P_PTS + p] = f0;
        xin[(199 + 2 * l) * P_PTS + p] = f1;
    }
    xin[230 * P_PTS + p] = 0.0f;
    xin[231 * P_PTS + p] = 0.0f;
}

// ---------------- bf16x3 GEMM: hi/lo co-resident K-chunks ---------------------
// 8 K-chunks of 32. Per chunk the stage holds Ahi|Alo|Whi|Wlo (4 x 8KB).
// Passes per chunk: Ahi*Whi, Alo*Whi (reuse W frags), Ahi*Wlo.
#define NCHUNK 8
#define T_AHI 0
#define T_ALO 8192
#define T_WHI 16384
#define T_WLO 24576
#define STAGE_B 32768
#define SMEM_GEMM (3 * STAGE_B)      // 98304 -> 2 CTAs/SM

__global__ __launch_bounds__(256, 2)
void gemm_mma(const __nv_bfloat16* __restrict__ A, const __nv_bfloat16* __restrict__ W,
              const float* __restrict__ bias,
              __nv_bfloat16* __restrict__ Obf, float* __restrict__ Of32,
              int Nreal, int act, float oscale)
{
    extern __shared__ __align__(16) char smem[];

    const int tid  = threadIdx.x;
    const int warp = tid >> 5, lane = tid & 31;
    const int m0 = blockIdx.y << 7;
    const int n0 = blockIdx.x << 7;
    const int wm = warp & 3, wn = warp >> 2;

    const uint32_t s0 = smem_u32(smem);

    // loader: c = tid&3 (16B chunk in row), rows rbase and rbase+64
    const int rbase = tid >> 2;
    const int cc    = tid & 3;
    const __nv_bfloat16* pA = A + (size_t)(m0 + rbase) * 512 + cc * 8;
    const __nv_bfloat16* pW = W + (size_t)(n0 + rbase) * 512 + cc * 8;
    const uint32_t so0 = (uint32_t)(rbase * 64) + (((uint32_t)cc ^ (((uint32_t)rbase >> 1) & 3)) << 4);

    auto load_stage = [&](int kc, int stg) {
        uint32_t sb = s0 + stg * STAGE_B;
        int k32 = kc << 5;
        cp16(sb + T_AHI + so0,        pA + k32);
        cp16(sb + T_AHI + so0 + 4096, pA + 64 * 512 + k32);
        cp16(sb + T_ALO + so0,        pA + 256 + k32);
        cp16(sb + T_ALO + so0 + 4096, pA + 64 * 512 + 256 + k32);
        cp16(sb + T_WHI + so0,        pW + k32);
        cp16(sb + T_WHI + so0 + 4096, pW + 64 * 512 + k32);
        cp16(sb + T_WLO + so0,        pW + 256 + k32);
        cp16(sb + T_WLO + so0 + 4096, pW + 64 * 512 + 256 + k32);
    };

    float c[2][8][4];
#pragma unroll
    for (int mi = 0; mi < 2; ++mi)
#pragma unroll
        for (int nf = 0; nf < 8; ++nf)
#pragma unroll
            for (int r = 0; r < 4; ++r) c[mi][nf][r] = 0.0f;

    load_stage(0, 0); CP_COMMIT();
    load_stage(1, 1); CP_COMMIT();

    // per-lane ldsm row terms (64B rows, 4-chunk swizzle key (row>>1)&3)
    const int lrow = lane & 15;
    const uint32_t lhi = (uint32_t)(lane >> 4);
    uint32_t rowA[2], rqA[2], rowB[4], rqB[4];
#pragma unroll
    for (int mi = 0; mi < 2; ++mi) {
        int R = wm * 32 + mi * 16 + lrow;
        rowA[mi] = (uint32_t)(R * 64); rqA[mi] = (uint32_t)((R >> 1) & 3);
    }
#pragma unroll
    for (int nb = 0; nb < 4; ++nb) {
        int R = wn * 64 + nb * 16 + lrow;
        rowB[nb] = (uint32_t)(R * 64); rqB[nb] = (uint32_t)((R >> 1) & 3);
    }

#pragma unroll
    for (int t = 0; t < NCHUNK; ++t) {
        CP_WAIT1();
        __syncthreads();
        if (t + 2 < NCHUNK) load_stage(t + 2, (t + 2) % 3);
        CP_COMMIT();

        const uint32_t sb = s0 + (t % 3) * STAGE_B;
        uint32_t aF[2][4], bF[4][4];

        // passes 0 (Ahi*Whi) and 1 (Alo*Whi), W frags reused
#pragma unroll
        for (int ks = 0; ks < 2; ++ks) {
            const uint32_t ch = (uint32_t)(2 * ks) + lhi;
#pragma unroll
            for (int nb = 0; nb < 4; ++nb)
                ldsm4(bF[nb], sb + T_WHI + rowB[nb] + ((ch ^ rqB[nb]) << 4));
#pragma unroll
            for (int mi = 0; mi < 2; ++mi)
                ldsm4(aF[mi], sb + T_AHI + rowA[mi] + ((ch ^ rqA[mi]) << 4));
#pragma unroll
            for (int mi = 0; mi < 2; ++mi)
#pragma unroll
                for (int nb = 0; nb < 4; ++nb) {
                    mma16816(c[mi][nb * 2],     aF[mi], bF[nb][0], bF[nb][2]);
                    mma16816(c[mi][nb * 2 + 1], aF[mi], bF[nb][1], bF[nb][3]);
                }
#pragma unroll
            for (int mi = 0; mi < 2; ++mi)
                ldsm4(aF[mi], sb + T_ALO + rowA[mi] + ((ch ^ rqA[mi]) << 4));
#pragma unroll
            for (int mi = 0; mi < 2; ++mi)
#pragma unroll
                for (int nb = 0; nb < 4; ++nb) {
                    mma16816(c[mi][nb * 2],     aF[mi], bF[nb][0], bF[nb][2]);
                    mma16816(c[mi][nb * 2 + 1], aF[mi], bF[nb][1], bF[nb][3]);
                }
        }
        // pass 2 (Ahi*Wlo)
#pragma unroll
        for (int ks = 0; ks < 2; ++ks) {
            const uint32_t ch = (uint32_t)(2 * ks) + lhi;
#pragma unroll
            for (int nb = 0; nb < 4; ++nb)
                ldsm4(bF[nb], sb + T_WLO + rowB[nb] + ((ch ^ rqB[nb]) << 4));
#pragma unroll
            for (int mi = 0; mi < 2; ++mi)
                ldsm4(aF[mi], sb + T_AHI + rowA[mi] + ((ch ^ rqA[mi]) << 4));
#pragma unroll
            for (int mi = 0; mi < 2; ++mi)
#pragma unroll
                for (int nb = 0; nb < 4; ++nb) {
                    mma16816(c[mi][nb * 2],     aF[mi], bF[nb][0], bF[nb][2]);
                    mma16816(c[mi][nb * 2 + 1], aF[mi], bF[nb][1], bF[nb][3]);
                }
        }
    }

    // ---- epilogue: direct stores ------------------------------------------
#pragma unroll
    for (int mi = 0; mi < 2; ++mi) {
        int mbase = m0 + wm * 32 + mi * 16 + (lane >> 2);
#pragma unroll
        for (int nf = 0; nf < 8; ++nf) {
            int n = n0 + wn * 64 + nf * 8 + ((lane & 3) << 1);
            if (n >= Nreal && n + 1 >= Nreal) continue;
            float b0 = (n < Nreal)     ? __ldg(bias + n)     : 0.0f;
            float b1 = (n + 1 < Nreal) ? __ldg(bias + n + 1) : 0.0f;
#pragma unroll
            for (int r2 = 0; r2 < 2; ++r2) {
                int m = mbase + r2 * 8;
                float v0 = c[mi][nf][r2 * 2 + 0] + b0;
                float v1 = c[mi][nf][r2 * 2 + 1] + b1;
                if (act) {
                    v0 = softplus100(v0);
                    v1 = softplus100(v1);
                }
                v0 *= oscale; v1 *= oscale;
                if (Of32) {
                    if (n < Nreal)     Of32[(size_t)m * 257 + n]     = v0;
                    if (n + 1 < Nreal) Of32[(size_t)m * 257 + n + 1] = v1;
                } else if (n < Nreal) {
                    __nv_bfloat16 h0 = __float2bfloat16(v0);
                    __nv_bfloat16 h1 = __float2bfloat16(v1);
                    __nv_bfloat16 l0 = __float2bfloat16(v0 - __bfloat162float(h0));
                    __nv_bfloat16 l1 = __float2bfloat16(v1 - __bfloat162float(h1));
                    *(uint32_t*)(Obf + (size_t)m * 512 + n) =
                        (uint32_t)__bfloat16_as_ushort(h0) | ((uint32_t)__bfloat16_as_ushort(h1) << 16);
                    *(uint32_t*)(Obf + (size_t)m * 512 + 256 + n) =
                        (uint32_t)__bfloat16_as_ushort(l0) | ((uint32_t)__bfloat16_as_ushort(l1) << 16);
                }
            }
        }
    }
}

// ---------------- launch ------------------------------------------------------
extern "C" void kernel_launch(void* const* d_in, const int* in_sizes, int n_in,
                              void* d_out, int out_size)
{
    const float* inp   = (const float*)d_in[0];
    const float* parts = (const float*)d_in[1];
    const float* table = (const float*)d_in[2];
    WPtrs wp;
    const float* B[9];
    for (int l = 0; l < 9; ++l) {
        wp.w[l] = (const float*)d_in[3 + 2 * l];
        B[l]    = (const float*)d_in[4 + 2 * l];
    }

    float* xin;
    __nv_bfloat16 *xb, *ab, *bb, *sb, *wbase;
    cudaGetSymbolAddress((void**)&xin, g_xin);
    cudaGetSymbolAddress((void**)&xb, g_x);
    cudaGetSymbolAddress((void**)&ab, g_a);
    cudaGetSymbolAddress((void**)&bb, g_b);
    cudaGetSymbolAddress((void**)&sb, g_s);
    cudaGetSymbolAddress((void**)&wbase, g_w);

    static const int Nout[9]  = {256, 256, 256, 26, 256, 256, 256, 256, 257};
    static const int Nrows[9] = {256, 256, 256, 128, 256, 256, 256, 256, 384};

    __nv_bfloat16* wt[9];
    {
        size_t off = 0;
        for (int l = 0; l < 9; ++l) { wt[l] = wbase + off; off += (size_t)Nrows[l] * 512; }
    }

    cudaFuncSetAttribute(gemm_mma, cudaFuncAttributeMaxDynamicSharedMemorySize, SMEM_GEMM);
    cudaFuncSetAttribute(feature_kernel, cudaFuncAttributeMaxDynamicSharedMemorySize, M_PART * 16);

    prep_w_all<<<(2304 * 256 + 255) / 256, 256>>>(wp, wbase);
    feature_kernel<<<128, 128, M_PART * 16>>>(inp, parts, table, xin);
    conv_tr2<<<dim3(8, P_PTS / 32), dim3(32, 8)>>>(xin, xb, sb);

    auto gemm = [&](const __nv_bfloat16* Ain, int l, __nv_bfloat16* Obf, float* Of,
                    int act, float os) {
        dim3 grid(Nrows[l] / 128, P_PTS / 128);
        gemm_mma<<<grid, 256, SMEM_GEMM>>>(Ain, wt[l], B[l], Obf, Of, Nout[l], act, os);
    };

    gemm(xb, 0, ab, nullptr, 1, 1.0f);
    gemm(ab, 1, bb, nullptr, 1, 1.0f);
    gemm(bb, 2, ab, nullptr, 1, 1.0f);
    gemm(ab, 3, sb, nullptr, 1, INV_SQRT2);   // writes cols 0..25 (pre-scaled)
    gemm(sb, 4, ab, nullptr, 1, 1.0f);
    gemm(ab, 5, bb, nullptr, 1, 1.0f);
    gemm(bb, 6, ab, nullptr, 1, 1.0f);
    gemm(ab, 7, bb, nullptr, 1, 1.0f);
    gemm(bb, 8, nullptr, (float*)d_out, 0, 1.0f);
}

// round 8
// speedup vs baseline: 1.6762x; 1.4657x over previous
#include <cuda_runtime.h>
#include <cuda_bf16.h>
#include <math.h>
#include <stdint.h>

#define P_PTS     16384
#define M_PART    4096
#define HASHMAP_SZ 524288u
#define NUM_LVL   16
#define INV_SQRT2 0.70710678118654752f

// ---------------- scratch (device globals; no allocation allowed) -------------
__device__ __align__(16) float g_xin[232 * P_PTS];
__device__ __align__(16) float g_stats[7 * P_PTS];        // wsum, smx..z, vrx..z
__device__ __align__(16) __nv_bfloat16 g_x[P_PTS * 512];
__device__ __align__(16) __nv_bfloat16 g_a[P_PTS * 512];
__device__ __align__(16) __nv_bfloat16 g_b[P_PTS * 512];
__device__ __align__(16) __nv_bfloat16 g_s[P_PTS * 512];  // layer-4 (skip) input
__device__ __align__(16) __nv_bfloat16 g_w[2304 * 512];

// ---------------- PTX helpers -------------------------------------------------
static __device__ __forceinline__ uint32_t smem_u32(const void* p) {
    uint32_t a;
    asm("{ .reg .u64 t; cvta.to.shared.u64 t, %1; cvt.u32.u64 %0, t; }" : "=r"(a) : "l"(p));
    return a;
}
static __device__ __forceinline__ void cp16(uint32_t s, const void* g) {
    asm volatile("cp.async.ca.shared.global [%0], [%1], 16;" :: "r"(s), "l"(g));
}
#define CP_COMMIT()  asm volatile("cp.async.commit_group;" ::: "memory")
#define CP_WAIT1()   asm volatile("cp.async.wait_group 1;" ::: "memory")

static __device__ __forceinline__ void ldsm4(uint32_t* r, uint32_t a) {
    asm volatile("ldmatrix.sync.aligned.m8n8.x4.shared.b16 {%0,%1,%2,%3}, [%4];"
                 : "=r"(r[0]), "=r"(r[1]), "=r"(r[2]), "=r"(r[3]) : "r"(a));
}
static __device__ __forceinline__ void mma16816(float* c, const uint32_t* a,
                                                uint32_t b0, uint32_t b1) {
    asm volatile(
        "mma.sync.aligned.m16n8k16.row.col.f32.bf16.bf16.f32 "
        "{%0,%1,%2,%3}, {%4,%5,%6,%7}, {%8,%9}, {%0,%1,%2,%3};"
        : "+f"(c[0]), "+f"(c[1]), "+f"(c[2]), "+f"(c[3])
        : "r"(a[0]), "r"(a[1]), "r"(a[2]), "r"(a[3]), "r"(b0), "r"(b1));
}
static __device__ __forceinline__ float softplus100(float v) {
    float y = 100.0f * v;
    return (fmaxf(y, 0.0f) + __logf(1.0f + __expf(-fabsf(y)))) * 0.01f;
}

// ---------------- dummy (profiling slot alignment) ----------------------------
__global__ void nop_kernel() {}

// ---------------- fused weight prep -------------------------------------------
struct WPtrs { const float* w[9]; };

__global__ void prep_w_all(WPtrs wp, __nv_bfloat16* __restrict__ out)
{
    int i = blockIdx.x * blockDim.x + threadIdx.x;
    if (i >= 2304 * 256) return;
    int r = i >> 8, k = i & 255;
    const int cum[10]  = {0, 256, 512, 768, 896, 1152, 1408, 1664, 1920, 2304};
    const int nout[9]  = {256, 256, 256, 26, 256, 256, 256, 256, 257};
    const int kact[9]  = {230, 256, 256, 256, 256, 256, 256, 256, 256};
    int l = 0;
#pragma unroll
    for (int t = 1; t < 9; ++t) if (r >= cum[t]) l = t;
    int n = r - cum[l];
    float v = (n < nout[l] && k < kact[l]) ? wp.w[l][n * kact[l] + k] : 0.0f;
    __nv_bfloat16 h = __float2bfloat16(v);
    out[(size_t)r * 512 + k]       = h;
    out[(size_t)r * 512 + 256 + k] = __float2bfloat16(v - __bfloat162float(h));
}

// ---------------- fused transpose + bf16-split: xin -> g_x AND g_s ------------
__global__ void conv_tr2(const float* __restrict__ src,
                         __nv_bfloat16* __restrict__ dx,
                         __nv_bfloat16* __restrict__ ds)
{
    __shared__ float s[32][33];
    int tx = threadIdx.x, ty = threadIdx.y;
    int ct = blockIdx.x, pt = blockIdx.y;
#pragma unroll
    for (int r2 = 0; r2 < 4; ++r2) {
        int ci = ty + r2 * 8;
        int c = ct * 32 + ci;
        int p = pt * 32 + tx;
        s[ci][tx] = (c < 232) ? src[(size_t)c * P_PTS + p] : 0.0f;
    }
    __syncthreads();
#pragma unroll
    for (int r2 = 0; r2 < 4; ++r2) {
        int pi = ty + r2 * 8;
        int p = pt * 32 + pi;
        int c = ct * 32 + tx;
        float v = s[tx][pi];
        __nv_bfloat16 h = __float2bfloat16(v);
        dx[(size_t)p * 512 + c]       = h;
        dx[(size_t)p * 512 + 256 + c] = __float2bfloat16(v - __bfloat162float(h));
        if (c < 230) {
            float vs = v * INV_SQRT2;
            __nv_bfloat16 hs = __float2bfloat16(vs);
            ds[(size_t)p * 512 + c + 26]       = hs;
            ds[(size_t)p * 512 + 256 + c + 26] = __float2bfloat16(vs - __bfloat162float(hs));
        }
    }
}

// ---------------- ball query: 4-way particle split, exact first-32 ------------
// block: 256 thr = 4 chunks x 64 points. grid: 256.
__global__ __launch_bounds__(256)
void ball_query_kernel(const float* __restrict__ inp,
                       const float* __restrict__ parts,
                       float* __restrict__ stats)
{
    extern __shared__ float fsm[];             // sp4: 16384 floats, ex: 2560 floats
    float4* sp4 = (float4*)fsm;
    float*  ex  = fsm + 16384;
    int tid = threadIdx.x;
    for (int i = tid; i < M_PART; i += 256) {
        float px = parts[3 * i], py = parts[3 * i + 1], pz = parts[3 * i + 2];
        sp4[i] = make_float4(px, py, pz, (px * px + py * py) + pz * pz);
    }
    __syncthreads();

    const int c  = tid >> 6;                   // chunk 0..3
    const int pl = tid & 63;
    const int p  = blockIdx.x * 64 + pl;
    const float x = inp[3 * p], y = inp[3 * p + 1], z = inp[3 * p + 2];
    const float q1 = (x * x + y * y) + z * z;
    const float R2 = 0.01f;
    const int j0 = c << 10, j1 = j0 + 1024;

    // phase 1: all hits in chunk
    int h = 0;
    float wsum = 0.f, swx = 0.f, swy = 0.f, swz = 0.f;
    float sdx = 0.f, sdy = 0.f, sdz = 0.f;
    float s2x = 0.f, s2y = 0.f, s2z = 0.f;
#pragma unroll 8
    for (int j = j0; j < j1; ++j) {
        float4 q = sp4[j];
        float dot = x * q.x + y * q.y + z * q.z;
        float d2e = (q1 + q.w) - 2.0f * dot;
        if (d2e < R2) {
            ++h;
            float dx = q.x - x, dy = q.y - y, dz = q.z - z;
            float d2 = dx * dx + dy * dy + dz * dz;
            float d  = sqrtf(fmaxf(d2, 1e-24f));
            float dr = d / 0.1f;
            float w  = fmaxf(1.0f - dr * dr * dr, 0.0f);
            wsum += w;
            swx = fmaf(w, q.x, swx); swy = fmaf(w, q.y, swy); swz = fmaf(w, q.z, swz);
            sdx += dx; sdy += dy; sdz += dz;
            s2x = fmaf(dx, dx, s2x); s2y = fmaf(dy, dy, s2y); s2z = fmaf(dz, dz, s2z);
        }
    }
    // exchange counts
    ex[c * 64 + pl] = (float)h;
    __syncthreads();
    int h0 = (int)ex[pl], h1 = (int)ex[64 + pl], h2 = (int)ex[128 + pl], h3 = (int)ex[192 + pl];
    int start = (c > 0 ? h0 : 0) + (c > 1 ? h1 : 0) + (c > 2 ? h2 : 0);
    int total = h0 + h1 + h2 + h3;
    int cnt   = min(32, total);
    int budget = max(0, min(32 - start, h));
    if (budget < h) {
        // truncated chunk: rescan, keep only first `budget` hits
        wsum = swx = swy = swz = 0.f;
        sdx = sdy = sdz = 0.f;
        s2x = s2y = s2z = 0.f;
        int taken = 0;
        for (int j = j0; j < j1 && taken < budget; ++j) {
            float4 q = sp4[j];
            float dot = x * q.x + y * q.y + z * q.z;
            float d2e = (q1 + q.w) - 2.0f * dot;
            if (d2e < R2) {
                ++taken;
                float dx = q.x - x, dy = q.y - y, dz = q.z - z;
                float d2 = dx * dx + dy * dy + dz * dz;
                float d  = sqrtf(fmaxf(d2, 1e-24f));
                float dr = d / 0.1f;
                float w  = fmaxf(1.0f - dr * dr * dr, 0.0f);
                wsum += w;
                swx = fmaf(w, q.x, swx); swy = fmaf(w, q.y, swy); swz = fmaf(w, q.z, swz);
                sdx += dx; sdy += dy; sdz += dz;
                s2x = fmaf(dx, dx, s2x); s2y = fmaf(dy, dy, s2y); s2z = fmaf(dz, dz, s2z);
            }
        }
    }
    __syncthreads();
    float part[10] = {wsum, swx, swy, swz, sdx, sdy, sdz, s2x, s2y, s2z};
#pragma unroll
    for (int f = 0; f < 10; ++f) ex[f * 256 + c * 64 + pl] = part[f];
    __syncthreads();

    if (c == 0) {
        float S[10];
#pragma unroll
        for (int f = 0; f < 10; ++f)
            S[f] = ((ex[f * 256 + pl] + ex[f * 256 + 64 + pl])
                  + ex[f * 256 + 128 + pl]) + ex[f * 256 + 192 + pl];
        int ninv = 32 - cnt;
        if (ninv > 0) {
            float d  = sqrtf(fmaxf(q1, 1e-24f));
            float dr = d / 0.1f;
            float w  = fmaxf(1.0f - dr * dr * dr, 0.0f);
            S[0] += (float)ninv * w;
        }
        float nf  = (float)cnt;
        float wdn = S[0] + 1e-12f;
        float den = nf + 1e-12f;
        float vmx = S[4] / den, vmy = S[5] / den, vmz = S[6] / den;
        stats[0 * P_PTS + p] = S[0];
        stats[1 * P_PTS + p] = S[1] / wdn;
        stats[2 * P_PTS + p] = S[2] / wdn;
        stats[3 * P_PTS + p] = S[3] / wdn;
        stats[4 * P_PTS + p] = (S[7] - 2.0f * vmx * S[4] + nf * vmx * vmx) / den;
        stats[5 * P_PTS + p] = (S[8] - 2.0f * vmy * S[5] + nf * vmy * vmy) / den;
        stats[6 * P_PTS + p] = (S[9] - 2.0f * vmz * S[6] + nf * vmz * vmz) / den;
    }
}

// ---------------- encode: posenc + hash, 8 sections per point -----------------
__device__ __forceinline__ void penc3(float* __restrict__ xin, int p, int base,
                                      float a, float b, float c)
{
    xin[(base + 0) * P_PTS + p] = a;
    xin[(base + 1) * P_PTS + p] = b;
    xin[(base + 2) * P_PTS + p] = c;
    float v[3] = {a, b, c};
#pragma unroll
    for (int f = 0; f < 10; ++f) {
        float fr = (float)(1 << f);
#pragma unroll
        for (int ch = 0; ch < 3; ++ch) {
            float s, co;
            sincosf(v[ch] * fr, &s, &co);
            xin[(base + 3 + f * 6 + ch)     * P_PTS + p] = s;
            xin[(base + 3 + f * 6 + 3 + ch) * P_PTS + p] = co;
        }
    }
}

__global__ __launch_bounds__(256)
void encode_kernel(const float* __restrict__ inp,
                   const float* __restrict__ table,
                   const float* __restrict__ stats,
                   float* __restrict__ xin)
{
    int tid = threadIdx.x;
    int pl = tid & 31, s = tid >> 5;
    int p = blockIdx.x * 32 + pl;
    float x = inp[3 * p], y = inp[3 * p + 1], z = inp[3 * p + 2];

    if (s < 4) {
        float xn[3] = { (x / 1.5f + 1.0f) * 0.5f,
                        (y / 1.5f + 1.0f) * 0.5f,
                        (z / 1.5f + 1.0f) * 0.5f };
#pragma unroll 1
        for (int li = 0; li < 4; ++li) {
            int l = s * 4 + li;
            double scd   = exp2((7.0 * (double)l) / 15.0) * 16.0 - 1.0;
            float  scale = (float)scd;
            unsigned res = (unsigned)ceil(scd) + 1u;
            bool dense   = ((unsigned long long)res * res * res <= (unsigned long long)HASHMAP_SZ);
            unsigned pg[3]; float fr[3];
#pragma unroll
            for (int cc = 0; cc < 3; ++cc) {
                float pos = fmaf(xn[cc], scale, 0.5f);
                float pf  = floorf(pos);
                fr[cc] = pos - pf;
                pg[cc] = (unsigned)pf;
            }
            float wx[2] = {1.f - fr[0], fr[0]};
            float wy[2] = {1.f - fr[1], fr[1]};
            float wz[2] = {1.f - fr[2], fr[2]};
            const float2* tbl = (const float2*)table + (size_t)l * HASHMAP_SZ;
            float f0 = 0.f, f1 = 0.f;
#pragma unroll
            for (int cc = 0; cc < 8; ++cc) {
                unsigned gx = pg[0] + (unsigned)(cc & 1);
                unsigned gy = pg[1] + (unsigned)((cc >> 1) & 1);
                unsigned gz = pg[2] + (unsigned)((cc >> 2) & 1);
                unsigned idx;
                if (dense) idx = gx + gy * res + gz * res * res;
                else       idx = ((gx * 1u) ^ (gy * 2654435761u) ^ (gz * 805459861u)) & (HASHMAP_SZ - 1u);
                float w = (wx[cc & 1] * wy[(cc >> 1) & 1]) * wz[(cc >> 2) & 1];
                float2 t = tbl[idx];
                f0 = fmaf(w, t.x, f0);
                f1 = fmaf(w, t.y, f1);
            }
            xin[(198 + 2 * l) * P_PTS + p] = f0;
            xin[(199 + 2 * l) * P_PTS + p] = f1;
        }
    } else if (s == 4) {
        penc3(xin, p, 0, x, y, z);
    } else if (s == 5) {
        float wsum = stats[p];
        xin[63 * P_PTS + p] = wsum;
#pragma unroll
        for (int f = 0; f < 4; ++f) {
            float sn, co;
            sincosf(wsum * (float)(1 << f), &sn, &co);
            xin[(64 + 2 * f) * P_PTS + p] = sn;
            xin[(65 + 2 * f) * P_PTS + p] = co;
        }
        xin[230 * P_PTS + p] = 0.0f;
        xin[231 * P_PTS + p] = 0.0f;
    } else if (s == 6) {
        penc3(xin, p, 72, stats[1 * P_PTS + p], stats[2 * P_PTS + p], stats[3 * P_PTS + p]);
    } else {
        penc3(xin, p, 135, stats[4 * P_PTS + p], stats[5 * P_PTS + p], stats[6 * P_PTS + p]);
    }
}

// ---------------- bf16x3 GEMM (unchanged from R7) -----------------------------
#define NCHUNK 8
#define T_AHI 0
#define T_ALO 8192
#define T_WHI 16384
#define T_WLO 24576
#define STAGE_B 32768
#define SMEM_GEMM (3 * STAGE_B)

__global__ __launch_bounds__(256, 2)
void gemm_mma(const __nv_bfloat16* __restrict__ A, const __nv_bfloat16* __restrict__ W,
              const float* __restrict__ bias,
              __nv_bfloat16* __restrict__ Obf, float* __restrict__ Of32,
              int Nreal, int act, float oscale)
{
    extern __shared__ __align__(16) char smem[];

    const int tid  = threadIdx.x;
    const int warp = tid >> 5, lane = tid & 31;
    const int m0 = blockIdx.y << 7;
    const int n0 = blockIdx.x << 7;
    const int wm = warp & 3, wn = warp >> 2;

    const uint32_t s0 = smem_u32(smem);

    const int rbase = tid >> 2;
    const int cc    = tid & 3;
    const __nv_bfloat16* pA = A + (size_t)(m0 + rbase) * 512 + cc * 8;
    const __nv_bfloat16* pW = W + (size_t)(n0 + rbase) * 512 + cc * 8;
    const uint32_t so0 = (uint32_t)(rbase * 64) + (((uint32_t)cc ^ (((uint32_t)rbase >> 1) & 3)) << 4);

    auto load_stage = [&](int kc, int stg) {
        uint32_t sb = s0 + stg * STAGE_B;
        int k32 = kc << 5;
        cp16(sb + T_AHI + so0,        pA + k32);
        cp16(sb + T_AHI + so0 + 4096, pA + 64 * 512 + k32);
        cp16(sb + T_ALO + so0,        pA + 256 + k32);
        cp16(sb + T_ALO + so0 + 4096, pA + 64 * 512 + 256 + k32);
        cp16(sb + T_WHI + so0,        pW + k32);
        cp16(sb + T_WHI + so0 + 4096, pW + 64 * 512 + k32);
        cp16(sb + T_WLO + so0,        pW + 256 + k32);
        cp16(sb + T_WLO + so0 + 4096, pW + 64 * 512 + 256 + k32);
    };

    float c[2][8][4];
#pragma unroll
    for (int mi = 0; mi < 2; ++mi)
#pragma unroll
        for (int nf = 0; nf < 8; ++nf)
#pragma unroll
            for (int r = 0; r < 4; ++r) c[mi][nf][r] = 0.0f;

    load_stage(0, 0); CP_COMMIT();
    load_stage(1, 1); CP_COMMIT();

    const int lrow = lane & 15;
    const uint32_t lhi = (uint32_t)(lane >> 4);
    uint32_t rowA[2], rqA[2], rowB[4], rqB[4];
#pragma unroll
    for (int mi = 0; mi < 2; ++mi) {
        int R = wm * 32 + mi * 16 + lrow;
        rowA[mi] = (uint32_t)(R * 64); rqA[mi] = (uint32_t)((R >> 1) & 3);
    }
#pragma unroll
    for (int nb = 0; nb < 4; ++nb) {
        int R = wn * 64 + nb * 16 + lrow;
        rowB[nb] = (uint32_t)(R * 64); rqB[nb] = (uint32_t)((R >> 1) & 3);
    }

#pragma unroll
    for (int t = 0; t < NCHUNK; ++t) {
        CP_WAIT1();
        __syncthreads();
        if (t + 2 < NCHUNK) load_stage(t + 2, (t + 2) % 3);
        CP_COMMIT();

        const uint32_t sb = s0 + (t % 3) * STAGE_B;
        uint32_t aF[2][4], bF[4][4];

#pragma unroll
        for (int ks = 0; ks < 2; ++ks) {
            const uint32_t ch = (uint32_t)(2 * ks) + lhi;
#pragma unroll
            for (int nb = 0; nb < 4; ++nb)
                ldsm4(bF[nb], sb + T_WHI + rowB[nb] + ((ch ^ rqB[nb]) << 4));
#pragma unroll
            for (int mi = 0; mi < 2; ++mi)
                ldsm4(aF[mi], sb + T_AHI + rowA[mi] + ((ch ^ rqA[mi]) << 4));
#pragma unroll
            for (int mi = 0; mi < 2; ++mi)
#pragma unroll
                for (int nb = 0; nb < 4; ++nb) {
                    mma16816(c[mi][nb * 2],     aF[mi], bF[nb][0], bF[nb][2]);
                    mma16816(c[mi][nb * 2 + 1], aF[mi], bF[nb][1], bF[nb][3]);
                }
#pragma unroll
            for (int mi = 0; mi < 2; ++mi)
                ldsm4(aF[mi], sb + T_ALO + rowA[mi] + ((ch ^ rqA[mi]) << 4));
#pragma unroll
            for (int mi = 0; mi < 2; ++mi)
#pragma unroll
                for (int nb = 0; nb < 4; ++nb) {
                    mma16816(c[mi][nb * 2],     aF[mi], bF[nb][0], bF[nb][2]);
                    mma16816(c[mi][nb * 2 + 1], aF[mi], bF[nb][1], bF[nb][3]);
                }
        }
#pragma unroll
        for (int ks = 0; ks < 2; ++ks) {
            const uint32_t ch = (uint32_t)(2 * ks) + lhi;
#pragma unroll
            for (int nb = 0; nb < 4; ++nb)
                ldsm4(bF[nb], sb + T_WLO + rowB[nb] + ((ch ^ rqB[nb]) << 4));
#pragma unroll
            for (int mi = 0; mi < 2; ++mi)
                ldsm4(aF[mi], sb + T_AHI + rowA[mi] + ((ch ^ rqA[mi]) << 4));
#pragma unroll
            for (int mi = 0; mi < 2; ++mi)
#pragma unroll
                for (int nb = 0; nb < 4; ++nb) {
                    mma16816(c[mi][nb * 2],     aF[mi], bF[nb][0], bF[nb][2]);
                    mma16816(c[mi][nb * 2 + 1], aF[mi], bF[nb][1], bF[nb][3]);
                }
        }
    }

    // ---- epilogue ---------------------------------------------------------
#pragma unroll
    for (int mi = 0; mi < 2; ++mi) {
        int mbase = m0 + wm * 32 + mi * 16 + (lane >> 2);
#pragma unroll
        for (int nf = 0; nf < 8; ++nf) {
            int n = n0 + wn * 64 + nf * 8 + ((lane & 3) << 1);
            if (n >= Nreal && n + 1 >= Nreal) continue;
            float b0 = (n < Nreal)     ? __ldg(bias + n)     : 0.0f;
            float b1 = (n + 1 < Nreal) ? __ldg(bias + n + 1) : 0.0f;
#pragma unroll
            for (int r2 = 0; r2 < 2; ++r2) {
                int m = mbase + r2 * 8;
                float v0 = c[mi][nf][r2 * 2 + 0] + b0;
                float v1 = c[mi][nf][r2 * 2 + 1] + b1;
                if (act) {
                    v0 = softplus100(v0);
                    v1 = softplus100(v1);
                }
                v0 *= oscale; v1 *= oscale;
                if (Of32) {
                    if (n < Nreal)     Of32[(size_t)m * 257 + n]     = v0;
                    if (n + 1 < Nreal) Of32[(size_t)m * 257 + n + 1] = v1;
                } else if (n < Nreal) {
                    __nv_bfloat16 h0 = __float2bfloat16(v0);
                    __nv_bfloat16 h1 = __float2bfloat16(v1);
                    __nv_bfloat16 l0 = __float2bfloat16(v0 - __bfloat162float(h0));
                    __nv_bfloat16 l1 = __float2bfloat16(v1 - __bfloat162float(h1));
                    *(uint32_t*)(Obf + (size_t)m * 512 + n) =
                        (uint32_t)__bfloat16_as_ushort(h0) | ((uint32_t)__bfloat16_as_ushort(h1) << 16);
                    *(uint32_t*)(Obf + (size_t)m * 512 + 256 + n) =
                        (uint32_t)__bfloat16_as_ushort(l0) | ((uint32_t)__bfloat16_as_ushort(l1) << 16);
                }
            }
        }
    }
}

// ---------------- launch ------------------------------------------------------
extern "C" void kernel_launch(void* const* d_in, const int* in_sizes, int n_in,
                              void* d_out, int out_size)
{
    const float* inp   = (const float*)d_in[0];
    const float* parts = (const float*)d_in[1];
    const float* table = (const float*)d_in[2];
    WPtrs wp;
    const float* B[9];
    for (int l = 0; l < 9; ++l) {
        wp.w[l] = (const float*)d_in[3 + 2 * l];
        B[l]    = (const float*)d_in[4 + 2 * l];
    }

    float *xin, *st;
    __nv_bfloat16 *xb, *ab, *bb, *sb, *wbase;
    cudaGetSymbolAddress((void**)&xin, g_xin);
    cudaGetSymbolAddress((void**)&st,  g_stats);
    cudaGetSymbolAddress((void**)&xb, g_x);
    cudaGetSymbolAddress((void**)&ab, g_a);
    cudaGetSymbolAddress((void**)&bb, g_b);
    cudaGetSymbolAddress((void**)&sb, g_s);
    cudaGetSymbolAddress((void**)&wbase, g_w);

    static const int Nout[9]  = {256, 256, 256, 26, 256, 256, 256, 256, 257};
    static const int Nrows[9] = {256, 256, 256, 128, 256, 256, 256, 256, 384};

    __nv_bfloat16* wt[9];
    {
        size_t off = 0;
        for (int l = 0; l < 9; ++l) { wt[l] = wbase + off; off += (size_t)Nrows[l] * 512; }
    }

    const int BQ_SMEM = (16384 + 2560) * 4;   // 75776 B
    cudaFuncSetAttribute(gemm_mma, cudaFuncAttributeMaxDynamicSharedMemorySize, SMEM_GEMM);
    cudaFuncSetAttribute(ball_query_kernel, cudaFuncAttributeMaxDynamicSharedMemorySize, BQ_SMEM);

    prep_w_all<<<(2304 * 256 + 255) / 256, 256>>>(wp, wbase);
    nop_kernel<<<1, 32>>>();
    nop_kernel<<<1, 32>>>();
    nop_kernel<<<1, 32>>>();
    nop_kernel<<<1, 32>>>();
    ball_query_kernel<<<P_PTS / 64, 256, BQ_SMEM>>>(inp, parts, st);   // capture slot 6
    encode_kernel<<<P_PTS / 32, 256>>>(inp, table, st, xin);
    conv_tr2<<<dim3(8, P_PTS / 32), dim3(32, 8)>>>(xin, xb, sb);

    auto gemm = [&](const __nv_bfloat16* Ain, int l, __nv_bfloat16* Obf, float* Of,
                    int act, float os) {
        dim3 grid(Nrows[l] / 128, P_PTS / 128);
        gemm_mma<<<grid, 256, SMEM_GEMM>>>(Ain, wt[l], B[l], Obf, Of, Nout[l], act, os);
    };

    gemm(xb, 0, ab, nullptr, 1, 1.0f);
    gemm(ab, 1, bb, nullptr, 1, 1.0f);
    gemm(bb, 2, ab, nullptr, 1, 1.0f);
    gemm(ab, 3, sb, nullptr, 1, INV_SQRT2);   // writes cols 0..25 (pre-scaled)
    gemm(sb, 4, ab, nullptr, 1, 1.0f);
    gemm(ab, 5, bb, nullptr, 1, 1.0f);
    gemm(bb, 6, ab, nullptr, 1, 1.0f);
    gemm(ab, 7, bb, nullptr, 1, 1.0f);
    gemm(bb, 8, nullptr, (float*)d_out, 0, 1.0f);
}

// round 9
// speedup vs baseline: 1.7283x; 1.0310x over previous
#include <cuda_runtime.h>
#include <cuda_bf16.h>
#include <math.h>
#include <stdint.h>

#define P_PTS     16384
#define M_PART    4096
#define HASHMAP_SZ 524288u
#define NUM_LVL   16
#define INV_SQRT2 0.70710678118654752f

// ---------------- scratch (device globals; no allocation allowed) -------------
__device__ __align__(16) float g_xin[232 * P_PTS];
__device__ __align__(16) float g_stats[7 * P_PTS];        // wsum, smx..z, vrx..z
__device__ __align__(16) __nv_bfloat16 g_x[P_PTS * 512];
__device__ __align__(16) __nv_bfloat16 g_a[P_PTS * 512];
__device__ __align__(16) __nv_bfloat16 g_b[P_PTS * 512];
__device__ __align__(16) __nv_bfloat16 g_s[P_PTS * 512];  // layer-4 (skip) input
__device__ __align__(16) __nv_bfloat16 g_w[2304 * 512];

// ---------------- PTX helpers -------------------------------------------------
static __device__ __forceinline__ uint32_t smem_u32(const void* p) {
    uint32_t a;
    asm("{ .reg .u64 t; cvta.to.shared.u64 t, %1; cvt.u32.u64 %0, t; }" : "=r"(a) : "l"(p));
    return a;
}
static __device__ __forceinline__ void cp16(uint32_t s, const void* g) {
    asm volatile("cp.async.ca.shared.global [%0], [%1], 16;" :: "r"(s), "l"(g));
}
#define CP_COMMIT()  asm volatile("cp.async.commit_group;" ::: "memory")
#define CP_WAIT1()   asm volatile("cp.async.wait_group 1;" ::: "memory")

static __device__ __forceinline__ void ldsm4(uint32_t* r, uint32_t a) {
    asm volatile("ldmatrix.sync.aligned.m8n8.x4.shared.b16 {%0,%1,%2,%3}, [%4];"
                 : "=r"(r[0]), "=r"(r[1]), "=r"(r[2]), "=r"(r[3]) : "r"(a));
}
static __device__ __forceinline__ void mma16816(float* c, const uint32_t* a,
                                                uint32_t b0, uint32_t b1) {
    asm volatile(
        "mma.sync.aligned.m16n8k16.row.col.f32.bf16.bf16.f32 "
        "{%0,%1,%2,%3}, {%4,%5,%6,%7}, {%8,%9}, {%0,%1,%2,%3};"
        : "+f"(c[0]), "+f"(c[1]), "+f"(c[2]), "+f"(c[3])
        : "r"(a[0]), "r"(a[1]), "r"(a[2]), "r"(a[3]), "r"(b0), "r"(b1));
}
static __device__ __forceinline__ float softplus100(float v) {
    float y = 100.0f * v;
    return (fmaxf(y, 0.0f) + __logf(1.0f + __expf(-fabsf(y)))) * 0.01f;
}

// ---------------- fused weight prep -------------------------------------------
struct WPtrs { const float* w[9]; };

__global__ void prep_w_all(WPtrs wp, __nv_bfloat16* __restrict__ out)
{
    int i = blockIdx.x * blockDim.x + threadIdx.x;
    if (i >= 2304 * 256) return;
    int r = i >> 8, k = i & 255;
    const int cum[10]  = {0, 256, 512, 768, 896, 1152, 1408, 1664, 1920, 2304};
    const int nout[9]  = {256, 256, 256, 26, 256, 256, 256, 256, 257};
    const int kact[9]  = {230, 256, 256, 256, 256, 256, 256, 256, 256};
    int l = 0;
#pragma unroll
    for (int t = 1; t < 9; ++t) if (r >= cum[t]) l = t;
    int n = r - cum[l];
    float v = (n < nout[l] && k < kact[l]) ? wp.w[l][n * kact[l] + k] : 0.0f;
    __nv_bfloat16 h = __float2bfloat16(v);
    out[(size_t)r * 512 + k]       = h;
    out[(size_t)r * 512 + 256 + k] = __float2bfloat16(v - __bfloat162float(h));
}

// ---------------- fused transpose + bf16-split: xin -> g_x AND g_s ------------
__global__ void conv_tr2(const float* __restrict__ src,
                         __nv_bfloat16* __restrict__ dx,
                         __nv_bfloat16* __restrict__ ds)
{
    __shared__ float s[32][33];
    int tx = threadIdx.x, ty = threadIdx.y;
    int ct = blockIdx.x, pt = blockIdx.y;
#pragma unroll
    for (int r2 = 0; r2 < 4; ++r2) {
        int ci = ty + r2 * 8;
        int c = ct * 32 + ci;
        int p = pt * 32 + tx;
        s[ci][tx] = (c < 232) ? src[(size_t)c * P_PTS + p] : 0.0f;
    }
    __syncthreads();
#pragma unroll
    for (int r2 = 0; r2 < 4; ++r2) {
        int pi = ty + r2 * 8;
        int p = pt * 32 + pi;
        int c = ct * 32 + tx;
        float v = s[tx][pi];
        __nv_bfloat16 h = __float2bfloat16(v);
        dx[(size_t)p * 512 + c]       = h;
        dx[(size_t)p * 512 + 256 + c] = __float2bfloat16(v - __bfloat162float(h));
        if (c < 230) {
            float vs = v * INV_SQRT2;
            __nv_bfloat16 hs = __float2bfloat16(vs);
            ds[(size_t)p * 512 + c + 26]       = hs;
            ds[(size_t)p * 512 + 256 + c + 26] = __float2bfloat16(vs - __bfloat162float(hs));
        }
    }
}

// ---------------- ball query: 4-way particle split, exact first-32 ------------
__global__ __launch_bounds__(256)
void ball_query_kernel(const float* __restrict__ inp,
                       const float* __restrict__ parts,
                       float* __restrict__ stats)
{
    extern __shared__ float fsm[];             // sp4: 16384 floats, ex: 2560 floats
    float4* sp4 = (float4*)fsm;
    float*  ex  = fsm + 16384;
    int tid = threadIdx.x;
    for (int i = tid; i < M_PART; i += 256) {
        float px = parts[3 * i], py = parts[3 * i + 1], pz = parts[3 * i + 2];
        sp4[i] = make_float4(px, py, pz, (px * px + py * py) + pz * pz);
    }
    __syncthreads();

    const int c  = tid >> 6;
    const int pl = tid & 63;
    const int p  = blockIdx.x * 64 + pl;
    const float x = inp[3 * p], y = inp[3 * p + 1], z = inp[3 * p + 2];
    const float q1 = (x * x + y * y) + z * z;
    const float R2 = 0.01f;
    const int j0 = c << 10, j1 = j0 + 1024;

    int h = 0;
    float wsum = 0.f, swx = 0.f, swy = 0.f, swz = 0.f;
    float sdx = 0.f, sdy = 0.f, sdz = 0.f;
    float s2x = 0.f, s2y = 0.f, s2z = 0.f;
#pragma unroll 8
    for (int j = j0; j < j1; ++j) {
        float4 q = sp4[j];
        float dot = x * q.x + y * q.y + z * q.z;
        float d2e = (q1 + q.w) - 2.0f * dot;
        if (d2e < R2) {
            ++h;
            float dx = q.x - x, dy = q.y - y, dz = q.z - z;
            float d2 = dx * dx + dy * dy + dz * dz;
            float d  = sqrtf(fmaxf(d2, 1e-24f));
            float dr = d / 0.1f;
            float w  = fmaxf(1.0f - dr * dr * dr, 0.0f);
            wsum += w;
            swx = fmaf(w, q.x, swx); swy = fmaf(w, q.y, swy); swz = fmaf(w, q.z, swz);
            sdx += dx; sdy += dy; sdz += dz;
            s2x = fmaf(dx, dx, s2x); s2y = fmaf(dy, dy, s2y); s2z = fmaf(dz, dz, s2z);
        }
    }
    ex[c * 64 + pl] = (float)h;
    __syncthreads();
    int h0 = (int)ex[pl], h1 = (int)ex[64 + pl], h2 = (int)ex[128 + pl], h3 = (int)ex[192 + pl];
    int start = (c > 0 ? h0 : 0) + (c > 1 ? h1 : 0) + (c > 2 ? h2 : 0);
    int total = h0 + h1 + h2 + h3;
    int cnt   = min(32, total);
    int budget = max(0, min(32 - start, h));
    if (budget < h) {
        wsum = swx = swy = swz = 0.f;
        sdx = sdy = sdz = 0.f;
        s2x = s2y = s2z = 0.f;
        int taken = 0;
        for (int j = j0; j < j1 && taken < budget; ++j) {
            float4 q = sp4[j];
            float dot = x * q.x + y * q.y + z * q.z;
            float d2e = (q1 + q.w) - 2.0f * dot;
            if (d2e < R2) {
                ++taken;
                float dx = q.x - x, dy = q.y - y, dz = q.z - z;
                float d2 = dx * dx + dy * dy + dz * dz;
                float d  = sqrtf(fmaxf(d2, 1e-24f));
                float dr = d / 0.1f;
                float w  = fmaxf(1.0f - dr * dr * dr, 0.0f);
                wsum += w;
                swx = fmaf(w, q.x, swx); swy = fmaf(w, q.y, swy); swz = fmaf(w, q.z, swz);
                sdx += dx; sdy += dy; sdz += dz;
                s2x = fmaf(dx, dx, s2x); s2y = fmaf(dy, dy, s2y); s2z = fmaf(dz, dz, s2z);
            }
        }
    }
    __syncthreads();
    float part[10] = {wsum, swx, swy, swz, sdx, sdy, sdz, s2x, s2y, s2z};
#pragma unroll
    for (int f = 0; f < 10; ++f) ex[f * 256 + c * 64 + pl] = part[f];
    __syncthreads();

    if (c == 0) {
        float S[10];
#pragma unroll
        for (int f = 0; f < 10; ++f)
            S[f] = ((ex[f * 256 + pl] + ex[f * 256 + 64 + pl])
                  + ex[f * 256 + 128 + pl]) + ex[f * 256 + 192 + pl];
        int ninv = 32 - cnt;
        if (ninv > 0) {
            float d  = sqrtf(fmaxf(q1, 1e-24f));
            float dr = d / 0.1f;
            float w  = fmaxf(1.0f - dr * dr * dr, 0.0f);
            S[0] += (float)ninv * w;
        }
        float nf  = (float)cnt;
        float wdn = S[0] + 1e-12f;
        float den = nf + 1e-12f;
        float vmx = S[4] / den, vmy = S[5] / den, vmz = S[6] / den;
        stats[0 * P_PTS + p] = S[0];
        stats[1 * P_PTS + p] = S[1] / wdn;
        stats[2 * P_PTS + p] = S[2] / wdn;
        stats[3 * P_PTS + p] = S[3] / wdn;
        stats[4 * P_PTS + p] = (S[7] - 2.0f * vmx * S[4] + nf * vmx * vmx) / den;
        stats[5 * P_PTS + p] = (S[8] - 2.0f * vmy * S[5] + nf * vmy * vmy) / den;
        stats[6 * P_PTS + p] = (S[9] - 2.0f * vmz * S[6] + nf * vmz * vmz) / den;
    }
}

// ---------------- encode: posenc + hash, 8 sections per point -----------------
__device__ __forceinline__ void penc3(float* __restrict__ xin, int p, int base,
                                      float a, float b, float c)
{
    xin[(base + 0) * P_PTS + p] = a;
    xin[(base + 1) * P_PTS + p] = b;
    xin[(base + 2) * P_PTS + p] = c;
    float v[3] = {a, b, c};
#pragma unroll
    for (int f = 0; f < 10; ++f) {
        float fr = (float)(1 << f);
#pragma unroll
        for (int ch = 0; ch < 3; ++ch) {
            float s, co;
            sincosf(v[ch] * fr, &s, &co);
            xin[(base + 3 + f * 6 + ch)     * P_PTS + p] = s;
            xin[(base + 3 + f * 6 + 3 + ch) * P_PTS + p] = co;
        }
    }
}

__global__ __launch_bounds__(256)
void encode_kernel(const float* __restrict__ inp,
                   const float* __restrict__ table,
                   const float* __restrict__ stats,
                   float* __restrict__ xin)
{
    int tid = threadIdx.x;
    int pl = tid & 31, s = tid >> 5;
    int p = blockIdx.x * 32 + pl;
    float x = inp[3 * p], y = inp[3 * p + 1], z = inp[3 * p + 2];

    if (s < 4) {
        float xn[3] = { (x / 1.5f + 1.0f) * 0.5f,
                        (y / 1.5f + 1.0f) * 0.5f,
                        (z / 1.5f + 1.0f) * 0.5f };
#pragma unroll 1
        for (int li = 0; li < 4; ++li) {
            int l = s * 4 + li;
            double scd   = exp2((7.0 * (double)l) / 15.0) * 16.0 - 1.0;
            float  scale = (float)scd;
            unsigned res = (unsigned)ceil(scd) + 1u;
            bool dense   = ((unsigned long long)res * res * res <= (unsigned long long)HASHMAP_SZ);
            unsigned pg[3]; float fr[3];
#pragma unroll
            for (int cc = 0; cc < 3; ++cc) {
                float pos = fmaf(xn[cc], scale, 0.5f);
                float pf  = floorf(pos);
                fr[cc] = pos - pf;
                pg[cc] = (unsigned)pf;
            }
            float wx[2] = {1.f - fr[0], fr[0]};
            float wy[2] = {1.f - fr[1], fr[1]};
            float wz[2] = {1.f - fr[2], fr[2]};
            const float2* tbl = (const float2*)table + (size_t)l * HASHMAP_SZ;
            float f0 = 0.f, f1 = 0.f;
#pragma unroll
            for (int cc = 0; cc < 8; ++cc) {
                unsigned gx = pg[0] + (unsigned)(cc & 1);
                unsigned gy = pg[1] + (unsigned)((cc >> 1) & 1);
                unsigned gz = pg[2] + (unsigned)((cc >> 2) & 1);
                unsigned idx;
                if (dense) idx = gx + gy * res + gz * res * res;
                else       idx = ((gx * 1u) ^ (gy * 2654435761u) ^ (gz * 805459861u)) & (HASHMAP_SZ - 1u);
                float w = (wx[cc & 1] * wy[(cc >> 1) & 1]) * wz[(cc >> 2) & 1];
                float2 t = tbl[idx];
                f0 = fmaf(w, t.x, f0);
                f1 = fmaf(w, t.y, f1);
            }
            xin[(198 + 2 * l) * P_PTS + p] = f0;
            xin[(199 + 2 * l) * P_PTS + p] = f1;
        }
    } else if (s == 4) {
        penc3(xin, p, 0, x, y, z);
    } else if (s == 5) {
        float wsum = stats[p];
        xin[63 * P_PTS + p] = wsum;
#pragma unroll
        for (int f = 0; f < 4; ++f) {
            float sn, co;
            sincosf(wsum * (float)(1 << f), &sn, &co);
            xin[(64 + 2 * f) * P_PTS + p] = sn;
            xin[(65 + 2 * f) * P_PTS + p] = co;
        }
        xin[230 * P_PTS + p] = 0.0f;
        xin[231 * P_PTS + p] = 0.0f;
    } else if (s == 6) {
        penc3(xin, p, 72, stats[1 * P_PTS + p], stats[2 * P_PTS + p], stats[3 * P_PTS + p]);
    } else {
        penc3(xin, p, 135, stats[4 * P_PTS + p], stats[5 * P_PTS + p], stats[6 * P_PTS + p]);
    }
}

// ---------------- bf16x3 GEMM: pipelined fragment loads -----------------------
#define NCHUNK 8
#define T_AHI 0
#define T_ALO 8192
#define T_WHI 16384
#define T_WLO 24576
#define STAGE_B 32768
#define SMEM_GEMM (3 * STAGE_B)

__global__ __launch_bounds__(256, 2)
void gemm_mma(const __nv_bfloat16* __restrict__ A, const __nv_bfloat16* __restrict__ W,
              const float* __restrict__ bias,
              __nv_bfloat16* __restrict__ Obf, float* __restrict__ Of32,
              int Nreal, int act, float oscale)
{
    extern __shared__ __align__(16) char smem[];

    const int tid  = threadIdx.x;
    const int warp = tid >> 5, lane = tid & 31;
    const int m0 = blockIdx.y << 7;
    const int n0 = blockIdx.x << 7;
    const int wm = warp & 3, wn = warp >> 2;

    const uint32_t s0 = smem_u32(smem);

    const int rbase = tid >> 2;
    const int cc    = tid & 3;
    const __nv_bfloat16* pA = A + (size_t)(m0 + rbase) * 512 + cc * 8;
    const __nv_bfloat16* pW = W + (size_t)(n0 + rbase) * 512 + cc * 8;
    const uint32_t so0 = (uint32_t)(rbase * 64) + (((uint32_t)cc ^ (((uint32_t)rbase >> 1) & 3)) << 4);

    auto load_stage = [&](int kc, int stg) {
        uint32_t sb = s0 + stg * STAGE_B;
        int k32 = kc << 5;
        cp16(sb + T_AHI + so0,        pA + k32);
        cp16(sb + T_AHI + so0 + 4096, pA + 64 * 512 + k32);
        cp16(sb + T_ALO + so0,        pA + 256 + k32);
        cp16(sb + T_ALO + so0 + 4096, pA + 64 * 512 + 256 + k32);
        cp16(sb + T_WHI + so0,        pW + k32);
        cp16(sb + T_WHI + so0 + 4096, pW + 64 * 512 + k32);
        cp16(sb + T_WLO + so0,        pW + 256 + k32);
        cp16(sb + T_WLO + so0 + 4096, pW + 64 * 512 + 256 + k32);
    };

    float c[2][8][4];
#pragma unroll
    for (int mi = 0; mi < 2; ++mi)
#pragma unroll
        for (int nf = 0; nf < 8; ++nf)
#pragma unroll
            for (int r = 0; r < 4; ++r) c[mi][nf][r] = 0.0f;

    load_stage(0, 0); CP_COMMIT();
    load_stage(1, 1); CP_COMMIT();

    const int lrow = lane & 15;
    const uint32_t lhi = (uint32_t)(lane >> 4);
    uint32_t rowA[2], rqA[2], rowB[4], rqB[4];
#pragma unroll
    for (int mi = 0; mi < 2; ++mi) {
        int R = wm * 32 + mi * 16 + lrow;
        rowA[mi] = (uint32_t)(R * 64); rqA[mi] = (uint32_t)((R >> 1) & 3);
    }
#pragma unroll
    for (int nb = 0; nb < 4; ++nb) {
        int R = wn * 64 + nb * 16 + lrow;
        rowB[nb] = (uint32_t)(R * 64); rqB[nb] = (uint32_t)((R >> 1) & 3);
    }

    uint32_t aF[2][2][4], bF[4][4];

#define LD_A(buf, tile, ks) do {                                             \
    uint32_t ch = (uint32_t)(2 * (ks)) + lhi;                                \
    _Pragma("unroll")                                                        \
    for (int mi = 0; mi < 2; ++mi)                                           \
        ldsm4(aF[buf][mi], sb + (tile) + rowA[mi] + ((ch ^ rqA[mi]) << 4));  \
} while (0)
#define LD_B(tile, ks) do {                                                  \
    uint32_t ch = (uint32_t)(2 * (ks)) + lhi;                                \
    _Pragma("unroll")                                                        \
    for (int nb = 0; nb < 4; ++nb)                                           \
        ldsm4(bF[nb], sb + (tile) + rowB[nb] + ((ch ^ rqB[nb]) << 4));       \
} while (0)
#define MMA_BLK(buf) do {                                                    \
    _Pragma("unroll")                                                        \
    for (int mi = 0; mi < 2; ++mi)                                           \
        _Pragma("unroll")                                                    \
        for (int nb = 0; nb < 4; ++nb) {                                     \
            mma16816(c[mi][nb * 2],     aF[buf][mi], bF[nb][0], bF[nb][2]);  \
            mma16816(c[mi][nb * 2 + 1], aF[buf][mi], bF[nb][1], bF[nb][3]);  \
        }                                                                    \
} while (0)

#pragma unroll
    for (int t = 0; t < NCHUNK; ++t) {
        CP_WAIT1();
        __syncthreads();
        const uint32_t sb = s0 + (t % 3) * STAGE_B;

        // fragments for step 0 first (tensor starts ASAP after barrier)
        LD_B(T_WHI, 0);
        LD_A(0, T_AHI, 0);
        if (t + 2 < NCHUNK) load_stage(t + 2, (t + 2) % 3);
        CP_COMMIT();

        LD_A(1, T_ALO, 0);   // prefetch step1 A
        MMA_BLK(0);          // step0: AHI ks0 * WHI ks0
        LD_A(0, T_AHI, 1);   // prefetch step2 A
        MMA_BLK(1);          // step1: ALO ks0 * WHI ks0
        LD_B(T_WHI, 1);      // B for steps 2,3
        LD_A(1, T_ALO, 1);   // prefetch step3 A
        MMA_BLK(0);          // step2: AHI ks1 * WHI ks1
        LD_A(0, T_AHI, 0);   // prefetch step4 A
        MMA_BLK(1);          // step3: ALO ks1 * WHI ks1
        LD_B(T_WLO, 0);      // B for step4
        LD_A(1, T_AHI, 1);   // prefetch step5 A
        MMA_BLK(0);          // step4: AHI ks0 * WLO ks0
        LD_B(T_WLO, 1);      // B for step5
        MMA_BLK(1);          // step5: AHI ks1 * WLO ks1
    }

    // ---- epilogue ---------------------------------------------------------
#pragma unroll
    for (int mi = 0; mi < 2; ++mi) {
        int mbase = m0 + wm * 32 + mi * 16 + (lane >> 2);
#pragma unroll
        for (int nf = 0; nf < 8; ++nf) {
            int n = n0 + wn * 64 + nf * 8 + ((lane & 3) << 1);
            if (n >= Nreal && n + 1 >= Nreal) continue;
            float b0 = (n < Nreal)     ? __ldg(bias + n)     : 0.0f;
            float b1 = (n + 1 < Nreal) ? __ldg(bias + n + 1) : 0.0f;
#pragma unroll
            for (int r2 = 0; r2 < 2; ++r2) {
                int m = mbase + r2 * 8;
                float v0 = c[mi][nf][r2 * 2 + 0] + b0;
                float v1 = c[mi][nf][r2 * 2 + 1] + b1;
                if (act) {
                    v0 = softplus100(v0);
                    v1 = softplus100(v1);
                }
                v0 *= oscale; v1 *= oscale;
                if (Of32) {
                    if (n < Nreal)     Of32[(size_t)m * 257 + n]     = v0;
                    if (n + 1 < Nreal) Of32[(size_t)m * 257 + n + 1] = v1;
                } else if (n < Nreal) {
                    __nv_bfloat16 h0 = __float2bfloat16(v0);
                    __nv_bfloat16 h1 = __float2bfloat16(v1);
                    __nv_bfloat16 l0 = __float2bfloat16(v0 - __bfloat162float(h0));
                    __nv_bfloat16 l1 = __float2bfloat16(v1 - __bfloat162float(h1));
                    *(uint32_t*)(Obf + (size_t)m * 512 + n) =
                        (uint32_t)__bfloat16_as_ushort(h0) | ((uint32_t)__bfloat16_as_ushort(h1) << 16);
                    *(uint32_t*)(Obf + (size_t)m * 512 + 256 + n) =
                        (uint32_t)__bfloat16_as_ushort(l0) | ((uint32_t)__bfloat16_as_ushort(l1) << 16);
                }
            }
        }
    }
}

// ---------------- launch ------------------------------------------------------
extern "C" void kernel_launch(void* const* d_in, const int* in_sizes, int n_in,
                              void* d_out, int out_size)
{
    const float* inp   = (const float*)d_in[0];
    const float* parts = (const float*)d_in[1];
    const float* table = (const float*)d_in[2];
    WPtrs wp;
    const float* B[9];
    for (int l = 0; l < 9; ++l) {
        wp.w[l] = (const float*)d_in[3 + 2 * l];
        B[l]    = (const float*)d_in[4 + 2 * l];
    }

    float *xin, *st;
    __nv_bfloat16 *xb, *ab, *bb, *sb, *wbase;
    cudaGetSymbolAddress((void**)&xin, g_xin);
    cudaGetSymbolAddress((void**)&st,  g_stats);
    cudaGetSymbolAddress((void**)&xb, g_x);
    cudaGetSymbolAddress((void**)&ab, g_a);
    cudaGetSymbolAddress((void**)&bb, g_b);
    cudaGetSymbolAddress((void**)&sb, g_s);
    cudaGetSymbolAddress((void**)&wbase, g_w);

    static const int Nout[9]  = {256, 256, 256, 26, 256, 256, 256, 256, 257};
    static const int Nrows[9] = {256, 256, 256, 128, 256, 256, 256, 256, 384};

    __nv_bfloat16* wt[9];
    {
        size_t off = 0;
        for (int l = 0; l < 9; ++l) { wt[l] = wbase + off; off += (size_t)Nrows[l] * 512; }
    }

    const int BQ_SMEM = (16384 + 2560) * 4;
    cudaFuncSetAttribute(gemm_mma, cudaFuncAttributeMaxDynamicSharedMemorySize, SMEM_GEMM);
    cudaFuncSetAttribute(ball_query_kernel, cudaFuncAttributeMaxDynamicSharedMemorySize, BQ_SMEM);

    prep_w_all<<<(2304 * 256 + 255) / 256, 256>>>(wp, wbase);
    ball_query_kernel<<<P_PTS / 64, 256, BQ_SMEM>>>(inp, parts, st);
    encode_kernel<<<P_PTS / 32, 256>>>(inp, table, st, xin);
    conv_tr2<<<dim3(8, P_PTS / 32), dim3(32, 8)>>>(xin, xb, sb);

    auto gemm = [&](const __nv_bfloat16* Ain, int l, __nv_bfloat16* Obf, float* Of,
                    int act, float os) {
        dim3 grid(Nrows[l] / 128, P_PTS / 128);
        gemm_mma<<<grid, 256, SMEM_GEMM>>>(Ain, wt[l], B[l], Obf, Of, Nout[l], act, os);
    };

    gemm(xb, 0, ab, nullptr, 1, 1.0f);
    gemm(ab, 1, bb, nullptr, 1, 1.0f);
    gemm(bb, 2, ab, nullptr, 1, 1.0f);
    gemm(ab, 3, sb, nullptr, 1, INV_SQRT2);   // writes cols 0..25 (pre-scaled)
    gemm(sb, 4, ab, nullptr, 1, 1.0f);
    gemm(ab, 5, bb, nullptr, 1, 1.0f);
    gemm(bb, 6, ab, nullptr, 1, 1.0f);
    gemm(ab, 7, bb, nullptr, 1, 1.0f);
    gemm(bb, 8, nullptr, (float*)d_out, 0, 1.0f);
}

// round 11
// speedup vs baseline: 1.7535x; 1.0146x over previous
#include <cuda_runtime.h>
#include <cuda_bf16.h>
#include <math.h>
#include <stdint.h>

#define P_PTS     16384
#define M_PART    4096
#define HASHMAP_SZ 524288u
#define NUM_LVL   16
#define INV_SQRT2 0.70710678118654752f

// ---------------- scratch (device globals; no allocation allowed) -------------
__device__ __align__(16) float g_xin[232 * P_PTS];
__device__ __align__(16) float g_stats[7 * P_PTS];
__device__ __align__(16) __nv_bfloat16 g_x[P_PTS * 512];
__device__ __align__(16) __nv_bfloat16 g_s[P_PTS * 512];   // skip input (cols 26..255)
__device__ __align__(16) __nv_bfloat16 g_w[2304 * 512];

// ---------------- PTX helpers -------------------------------------------------
static __device__ __forceinline__ uint32_t smem_u32(const void* p) {
    uint32_t a;
    asm("{ .reg .u64 t; cvta.to.shared.u64 t, %1; cvt.u32.u64 %0, t; }" : "=r"(a) : "l"(p));
    return a;
}
static __device__ __forceinline__ void cp16(uint32_t s, const void* g) {
    asm volatile("cp.async.ca.shared.global [%0], [%1], 16;" :: "r"(s), "l"(g));
}
#define CP_COMMIT()  asm volatile("cp.async.commit_group;" ::: "memory")
#define CP_WAIT0()   asm volatile("cp.async.wait_group 0;" ::: "memory")

static __device__ __forceinline__ void ldsm4(uint32_t* r, uint32_t a) {
    asm volatile("ldmatrix.sync.aligned.m8n8.x4.shared.b16 {%0,%1,%2,%3}, [%4];"
                 : "=r"(r[0]), "=r"(r[1]), "=r"(r[2]), "=r"(r[3]) : "r"(a));
}
static __device__ __forceinline__ void mma16816(float* c, const uint32_t* a,
                                                uint32_t b0, uint32_t b1) {
    asm volatile(
        "mma.sync.aligned.m16n8k16.row.col.f32.bf16.bf16.f32 "
        "{%0,%1,%2,%3}, {%4,%5,%6,%7}, {%8,%9}, {%0,%1,%2,%3};"
        : "+f"(c[0]), "+f"(c[1]), "+f"(c[2]), "+f"(c[3])
        : "r"(a[0]), "r"(a[1]), "r"(a[2]), "r"(a[3]), "r"(b0), "r"(b1));
}
static __device__ __forceinline__ float softplus100(float v) {
    float y = 100.0f * v;
    return (fmaxf(y, 0.0f) + __logf(1.0f + __expf(-fabsf(y)))) * 0.01f;
}

// ---------------- fused weight prep -------------------------------------------
struct WPtrs { const float* w[9]; };
struct BPtrs { const float* b[9]; };

__global__ void prep_w_all(WPtrs wp, __nv_bfloat16* __restrict__ out)
{
    int i = blockIdx.x * blockDim.x + threadIdx.x;
    if (i >= 2304 * 256) return;
    int r = i >> 8, k = i & 255;
    const int cum[10]  = {0, 256, 512, 768, 896, 1152, 1408, 1664, 1920, 2304};
    const int nout[9]  = {256, 256, 256, 26, 256, 256, 256, 256, 257};
    const int kact[9]  = {230, 256, 256, 256, 256, 256, 256, 256, 256};
    int l = 0;
#pragma unroll
    for (int t = 1; t < 9; ++t) if (r >= cum[t]) l = t;
    int n = r - cum[l];
    float v = (n < nout[l] && k < kact[l]) ? wp.w[l][n * kact[l] + k] : 0.0f;
    __nv_bfloat16 h = __float2bfloat16(v);
    out[(size_t)r * 512 + k]       = h;
    out[(size_t)r * 512 + 256 + k] = __float2bfloat16(v - __bfloat162float(h));
}

// ---------------- fused transpose + bf16-split: xin -> g_x AND g_s ------------
__global__ void conv_tr2(const float* __restrict__ src,
                         __nv_bfloat16* __restrict__ dx,
                         __nv_bfloat16* __restrict__ ds)
{
    __shared__ float s[32][33];
    int tx = threadIdx.x, ty = threadIdx.y;
    int ct = blockIdx.x, pt = blockIdx.y;
#pragma unroll
    for (int r2 = 0; r2 < 4; ++r2) {
        int ci = ty + r2 * 8;
        int c = ct * 32 + ci;
        int p = pt * 32 + tx;
        s[ci][tx] = (c < 232) ? src[(size_t)c * P_PTS + p] : 0.0f;
    }
    __syncthreads();
#pragma unroll
    for (int r2 = 0; r2 < 4; ++r2) {
        int pi = ty + r2 * 8;
        int p = pt * 32 + pi;
        int c = ct * 32 + tx;
        float v = s[tx][pi];
        __nv_bfloat16 h = __float2bfloat16(v);
        dx[(size_t)p * 512 + c]       = h;
        dx[(size_t)p * 512 + 256 + c] = __float2bfloat16(v - __bfloat162float(h));
        if (c < 230) {
            float vs = v * INV_SQRT2;
            __nv_bfloat16 hs = __float2bfloat16(vs);
            ds[(size_t)p * 512 + c + 26]       = hs;
            ds[(size_t)p * 512 + 256 + c + 26] = __float2bfloat16(vs - __bfloat162float(hs));
        }
    }
}

// ---------------- ball query (unchanged, passing) ------------------------------
__global__ __launch_bounds__(256)
void ball_query_kernel(const float* __restrict__ inp,
                       const float* __restrict__ parts,
                       float* __restrict__ stats)
{
    extern __shared__ float fsm[];
    float4* sp4 = (float4*)fsm;
    float*  ex  = fsm + 16384;
    int tid = threadIdx.x;
    for (int i = tid; i < M_PART; i += 256) {
        float px = parts[3 * i], py = parts[3 * i + 1], pz = parts[3 * i + 2];
        sp4[i] = make_float4(px, py, pz, (px * px + py * py) + pz * pz);
    }
    __syncthreads();

    const int c  = tid >> 6;
    const int pl = tid & 63;
    const int p  = blockIdx.x * 64 + pl;
    const float x = inp[3 * p], y = inp[3 * p + 1], z = inp[3 * p + 2];
    const float q1 = (x * x + y * y) + z * z;
    const float R2 = 0.01f;
    const int j0 = c << 10, j1 = j0 + 1024;

    int h = 0;
    float wsum = 0.f, swx = 0.f, swy = 0.f, swz = 0.f;
    float sdx = 0.f, sdy = 0.f, sdz = 0.f;
    float s2x = 0.f, s2y = 0.f, s2z = 0.f;
#pragma unroll 8
    for (int j = j0; j < j1; ++j) {
        float4 q = sp4[j];
        float dot = x * q.x + y * q.y + z * q.z;
        float d2e = (q1 + q.w) - 2.0f * dot;
        if (d2e < R2) {
            ++h;
            float dx = q.x - x, dy = q.y - y, dz = q.z - z;
            float d2 = dx * dx + dy * dy + dz * dz;
            float d  = sqrtf(fmaxf(d2, 1e-24f));
            float dr = d / 0.1f;
            float w  = fmaxf(1.0f - dr * dr * dr, 0.0f);
            wsum += w;
            swx = fmaf(w, q.x, swx); swy = fmaf(w, q.y, swy); swz = fmaf(w, q.z, swz);
            sdx += dx; sdy += dy; sdz += dz;
            s2x = fmaf(dx, dx, s2x); s2y = fmaf(dy, dy, s2y); s2z = fmaf(dz, dz, s2z);
        }
    }
    ex[c * 64 + pl] = (float)h;
    __syncthreads();
    int h0 = (int)ex[pl], h1 = (int)ex[64 + pl], h2 = (int)ex[128 + pl], h3 = (int)ex[192 + pl];
    int start = (c > 0 ? h0 : 0) + (c > 1 ? h1 : 0) + (c > 2 ? h2 : 0);
    int total = h0 + h1 + h2 + h3;
    int cnt   = min(32, total);
    int budget = max(0, min(32 - start, h));
    if (budget < h) {
        wsum = swx = swy = swz = 0.f;
        sdx = sdy = sdz = 0.f;
        s2x = s2y = s2z = 0.f;
        int taken = 0;
        for (int j = j0; j < j1 && taken < budget; ++j) {
            float4 q = sp4[j];
            float dot = x * q.x + y * q.y + z * q.z;
            float d2e = (q1 + q.w) - 2.0f * dot;
            if (d2e < R2) {
                ++taken;
                float dx = q.x - x, dy = q.y - y, dz = q.z - z;
                float d2 = dx * dx + dy * dy + dz * dz;
                float d  = sqrtf(fmaxf(d2, 1e-24f));
                float dr = d / 0.1f;
                float w  = fmaxf(1.0f - dr * dr * dr, 0.0f);
                wsum += w;
                swx = fmaf(w, q.x, swx); swy = fmaf(w, q.y, swy); swz = fmaf(w, q.z, swz);
                sdx += dx; sdy += dy; sdz += dz;
                s2x = fmaf(dx, dx, s2x); s2y = fmaf(dy, dy, s2y); s2z = fmaf(dz, dz, s2z);
            }
        }
    }
    __syncthreads();
    float part[10] = {wsum, swx, swy, swz, sdx, sdy, sdz, s2x, s2y, s2z};
#pragma unroll
    for (int f = 0; f < 10; ++f) ex[f * 256 + c * 64 + pl] = part[f];
    __syncthreads();

    if (c == 0) {
        float S[10];
#pragma unroll
        for (int f = 0; f < 10; ++f)
            S[f] = ((ex[f * 256 + pl] + ex[f * 256 + 64 + pl])
                  + ex[f * 256 + 128 + pl]) + ex[f * 256 + 192 + pl];
        int ninv = 32 - cnt;
        if (ninv > 0) {
            float d  = sqrtf(fmaxf(q1, 1e-24f));
            float dr = d / 0.1f;
            float w  = fmaxf(1.0f - dr * dr * dr, 0.0f);
            S[0] += (float)ninv * w;
        }
        float nf  = (float)cnt;
        float wdn = S[0] + 1e-12f;
        float den = nf + 1e-12f;
        float vmx = S[4] / den, vmy = S[5] / den, vmz = S[6] / den;
        stats[0 * P_PTS + p] = S[0];
        stats[1 * P_PTS + p] = S[1] / wdn;
        stats[2 * P_PTS + p] = S[2] / wdn;
        stats[3 * P_PTS + p] = S[3] / wdn;
        stats[4 * P_PTS + p] = (S[7] - 2.0f * vmx * S[4] + nf * vmx * vmx) / den;
        stats[5 * P_PTS + p] = (S[8] - 2.0f * vmy * S[5] + nf * vmy * vmy) / den;
        stats[6 * P_PTS + p] = (S[9] - 2.0f * vmz * S[6] + nf * vmz * vmz) / den;
    }
}

// ---------------- encode (unchanged, passing) ----------------------------------
__device__ __forceinline__ void penc3(float* __restrict__ xin, int p, int base,
                                      float a, float b, float c)
{
    xin[(base + 0) * P_PTS + p] = a;
    xin[(base + 1) * P_PTS + p] = b;
    xin[(base + 2) * P_PTS + p] = c;
    float v[3] = {a, b, c};
#pragma unroll
    for (int f = 0; f < 10; ++f) {
        float fr = (float)(1 << f);
#pragma unroll
        for (int ch = 0; ch < 3; ++ch) {
            float s, co;
            sincosf(v[ch] * fr, &s, &co);
            xin[(base + 3 + f * 6 + ch)     * P_PTS + p] = s;
            xin[(base + 3 + f * 6 + 3 + ch) * P_PTS + p] = co;
        }
    }
}

__global__ __launch_bounds__(256)
void encode_kernel(const float* __restrict__ inp,
                   const float* __restrict__ table,
                   const float* __restrict__ stats,
                   float* __restrict__ xin)
{
    int tid = threadIdx.x;
    int pl = tid & 31, s = tid >> 5;
    int p = blockIdx.x * 32 + pl;
    float x = inp[3 * p], y = inp[3 * p + 1], z = inp[3 * p + 2];

    if (s < 4) {
        float xn[3] = { (x / 1.5f + 1.0f) * 0.5f,
                        (y / 1.5f + 1.0f) * 0.5f,
                        (z / 1.5f + 1.0f) * 0.5f };
#pragma unroll 1
        for (int li = 0; li < 4; ++li) {
            int l = s * 4 + li;
            double scd   = exp2((7.0 * (double)l) / 15.0) * 16.0 - 1.0;
            float  scale = (float)scd;
            unsigned res = (unsigned)ceil(scd) + 1u;
            bool dense   = ((unsigned long long)res * res * res <= (unsigned long long)HASHMAP_SZ);
            unsigned pg[3]; float fr[3];
#pragma unroll
            for (int cc = 0; cc < 3; ++cc) {
                float pos = fmaf(xn[cc], scale, 0.5f);
                float pf  = floorf(pos);
                fr[cc] = pos - pf;
                pg[cc] = (unsigned)pf;
            }
            float wx[2] = {1.f - fr[0], fr[0]};
            float wy[2] = {1.f - fr[1], fr[1]};
            float wz[2] = {1.f - fr[2], fr[2]};
            const float2* tbl = (const float2*)table + (size_t)l * HASHMAP_SZ;
            float f0 = 0.f, f1 = 0.f;
#pragma unroll
            for (int cc = 0; cc < 8; ++cc) {
                unsigned gx = pg[0] + (unsigned)(cc & 1);
                unsigned gy = pg[1] + (unsigned)((cc >> 1) & 1);
                unsigned gz = pg[2] + (unsigned)((cc >> 2) & 1);
                unsigned idx;
                if (dense) idx = gx + gy * res + gz * res * res;
                else       idx = ((gx * 1u) ^ (gy * 2654435761u) ^ (gz * 805459861u)) & (HASHMAP_SZ - 1u);
                float w = (wx[cc & 1] * wy[(cc >> 1) & 1]) * wz[(cc >> 2) & 1];
                float2 t = tbl[idx];
                f0 = fmaf(w, t.x, f0);
                f1 = fmaf(w, t.y, f1);
            }
            xin[(198 + 2 * l) * P_PTS + p] = f0;
            xin[(199 + 2 * l) * P_PTS + p] = f1;
        }
    } else if (s == 4) {
        penc3(xin, p, 0, x, y, z);
    } else if (s == 5) {
        float wsum = stats[p];
        xin[63 * P_PTS + p] = wsum;
#pragma unroll
        for (int f = 0; f < 4; ++f) {
            float sn, co;
            sincosf(wsum * (float)(1 << f), &sn, &co);
            xin[(64 + 2 * f) * P_PTS + p] = sn;
            xin[(65 + 2 * f) * P_PTS + p] = co;
        }
        xin[230 * P_PTS + p] = 0.0f;
        xin[231 * P_PTS + p] = 0.0f;
    } else if (s == 6) {
        penc3(xin, p, 72, stats[1 * P_PTS + p], stats[2 * P_PTS + p], stats[3 * P_PTS + p]);
    } else {
        penc3(xin, p, 135, stats[4 * P_PTS + p], stats[5 * P_PTS + p], stats[6 * P_PTS + p]);
    }
}

// ---------------- fused persistent MLP ----------------------------------------
// smem regions (bytes): LOW0 [0,64K), LOW1 [64K,128K), HIGH [128K,192K),
// W stages [192K, 224K). Each act region: 4 HI tiles (8KB each) then 4 LO tiles.
#define R_LOW0 0
#define R_LOW1 65536
#define R_HIGH 131072
#define R_W    196608
#define SMEM_FUSED 229376

__global__ __launch_bounds__(256, 1)
void fused_mlp(const __nv_bfloat16* __restrict__ gx,
               const __nv_bfloat16* __restrict__ gs,
               const __nv_bfloat16* __restrict__ gw,
               BPtrs bp, float* __restrict__ out)
{
    extern __shared__ __align__(16) char smem[];
    const uint32_t s0 = smem_u32(smem);
    const int tid = threadIdx.x, warp = tid >> 5, lane = tid & 31;
    const int wm = warp & 3, wn = warp >> 2;
    const int m0 = blockIdx.x << 7;

    const int rbase = tid >> 2, cc = tid & 3;
    const uint32_t so0 = (uint32_t)(rbase * 64) +
                         (((uint32_t)cc ^ (((uint32_t)rbase >> 1) & 3)) << 4);

    const int lrow = lane & 15;
    const uint32_t lhi = (uint32_t)(lane >> 4);
    uint32_t rowA[2], rqA[2], rowB[4], rqB[4];
#pragma unroll
    for (int mi = 0; mi < 2; ++mi) {
        int R = wm * 32 + mi * 16 + lrow;
        rowA[mi] = (uint32_t)(R * 64); rqA[mi] = (uint32_t)((R >> 1) & 3);
    }
#pragma unroll
    for (int nb = 0; nb < 4; ++nb) {
        int R = wn * 64 + nb * 16 + lrow;
        rowB[nb] = (uint32_t)(R * 64); rqB[nb] = (uint32_t)((R >> 1) & 3);
    }

    // load a full activation set (8 K-chunks, hi+lo) from global [P][512]
    auto load_full_act = [&](const __nv_bfloat16* src, uint32_t lowR) {
        const __nv_bfloat16* pS = src + (size_t)(m0 + rbase) * 512 + cc * 8;
#pragma unroll
        for (int kc = 0; kc < 8; ++kc) {
            uint32_t hiT = (kc < 4) ? (lowR + (uint32_t)kc * 8192)
                                    : (R_HIGH + (uint32_t)(kc - 4) * 8192);
            int k32 = kc << 5;
            cp16(s0 + hiT + so0,                pS + k32);
            cp16(s0 + hiT + so0 + 4096,         pS + 64 * 512 + k32);
            cp16(s0 + hiT + 32768 + so0,        pS + 256 + k32);
            cp16(s0 + hiT + 32768 + so0 + 4096, pS + 64 * 512 + 256 + k32);
        }
    };
    auto load_w = [&](const __nv_bfloat16* Wl, int n0w, int kc, int stg) {
        const __nv_bfloat16* pW = Wl + (size_t)(n0w + rbase) * 512 + cc * 8;
        uint32_t wb = s0 + R_W + (uint32_t)stg * 16384;
        int k32 = kc << 5;
        cp16(wb + so0,               pW + k32);
        cp16(wb + so0 + 4096,        pW + 64 * 512 + k32);
        cp16(wb + 8192 + so0,        pW + 256 + k32);
        cp16(wb + 8192 + so0 + 4096, pW + 64 * 512 + 256 + k32);
    };

    float c[2][8][4];
    uint32_t aF[2][8], bF[16];

    auto ldA = [&](int buf, uint32_t tile, int ks) {
        uint32_t ch = (uint32_t)(2 * ks) + lhi;
        ldsm4(&aF[buf][0], tile + rowA[0] + ((ch ^ rqA[0]) << 4));
        ldsm4(&aF[buf][4], tile + rowA[1] + ((ch ^ rqA[1]) << 4));
    };
    auto ldB = [&](uint32_t tile, int ks) {
        uint32_t ch = (uint32_t)(2 * ks) + lhi;
#pragma unroll
        for (int nb = 0; nb < 4; ++nb)
            ldsm4(&bF[nb * 4], tile + rowB[nb] + ((ch ^ rqB[nb]) << 4));
    };
    auto mmaBlk = [&](int buf) {
#pragma unroll
        for (int mi = 0; mi < 2; ++mi)
#pragma unroll
            for (int nb = 0; nb < 4; ++nb) {
                mma16816(c[mi][nb * 2],     &aF[buf][mi * 4], bF[nb * 4 + 0], bF[nb * 4 + 2]);
                mma16816(c[mi][nb * 2 + 1], &aF[buf][mi * 4], bF[nb * 4 + 1], bF[nb * 4 + 3]);
            }
    };

    // one N-half (128 cols): full K=256 bf16x3 mainloop, accumulators in c
    auto run_half = [&](const __nv_bfloat16* Wl, int n0w, uint32_t lowR) {
#pragma unroll
        for (int mi = 0; mi < 2; ++mi)
#pragma unroll
            for (int nf = 0; nf < 8; ++nf)
#pragma unroll
                for (int r = 0; r < 4; ++r) c[mi][nf][r] = 0.0f;
        load_w(Wl, n0w, 0, 0); CP_COMMIT();
#pragma unroll 1
        for (int kc = 0; kc < 8; ++kc) {
            CP_WAIT0();
            __syncthreads();
            if (kc + 1 < 8) { load_w(Wl, n0w, kc + 1, (kc + 1) & 1); CP_COMMIT(); }
            uint32_t tHI = s0 + ((kc < 4) ? (lowR + (uint32_t)kc * 8192)
                                          : (R_HIGH + (uint32_t)(kc - 4) * 8192));
            uint32_t tLO = tHI + 32768;
            uint32_t wst = s0 + R_W + (uint32_t)(kc & 1) * 16384;
            uint32_t wlo = wst + 8192;
            ldB(wst, 0); ldA(0, tHI, 0);
            ldA(1, tLO, 0);
            mmaBlk(0);                 // AHI ks0 * WHI ks0
            ldA(0, tHI, 1);
            mmaBlk(1);                 // ALO ks0 * WHI ks0
            ldB(wst, 1); ldA(1, tLO, 1);
            mmaBlk(0);                 // AHI ks1 * WHI ks1
            ldA(0, tHI, 0);
            mmaBlk(1);                 // ALO ks1 * WHI ks1
            ldB(wlo, 0); ldA(1, tHI, 1);
            mmaBlk(0);                 // AHI ks0 * WLO ks0
            ldB(wlo, 1);
            mmaBlk(1);                 // AHI ks1 * WLO ks1
        }
    };

    // epilogue -> smem region (softplus always; scale os; valid cols < validN)
    auto epi_smem = [&](uint32_t destR, const float* bias, int nb0, float os, int validN) {
#pragma unroll
        for (int mi = 0; mi < 2; ++mi)
#pragma unroll
            for (int nf = 0; nf < 8; ++nf) {
                int ncol = wn * 64 + nf * 8 + ((lane & 3) << 1);
                if (ncol >= validN) continue;
                float b0 = __ldg(bias + nb0 + ncol);
                float b1 = __ldg(bias + nb0 + ncol + 1);
                uint32_t chunk = (uint32_t)ncol >> 5;
                uint32_t cpos  = (uint32_t)ncol & 31;
#pragma unroll
                for (int r2 = 0; r2 < 2; ++r2) {
                    int row = wm * 32 + mi * 16 + (lane >> 2) + r2 * 8;
                    float v0 = softplus100(c[mi][nf][r2 * 2 + 0] + b0) * os;
                    float v1 = softplus100(c[mi][nf][r2 * 2 + 1] + b1) * os;
                    __nv_bfloat16 h0 = __float2bfloat16(v0);
                    __nv_bfloat16 h1 = __float2bfloat16(v1);
                    __nv_bfloat16 l0 = __float2bfloat16(v0 - __bfloat162float(h0));
                    __nv_bfloat16 l1 = __float2bfloat16(v1 - __bfloat162float(h1));
                    uint32_t hw = (uint32_t)__bfloat16_as_ushort(h0) |
                                  ((uint32_t)__bfloat16_as_ushort(h1) << 16);
                    uint32_t lw = (uint32_t)__bfloat16_as_ushort(l0) |
                                  ((uint32_t)__bfloat16_as_ushort(l1) << 16);
                    uint32_t off = (uint32_t)(row * 64) +
                                   (((cpos >> 3) ^ (((uint32_t)row >> 1) & 3)) << 4) +
                                   ((cpos & 7) << 1);
                    *(uint32_t*)(smem + destR + chunk * 8192 + off)         = hw;
                    *(uint32_t*)(smem + destR + 32768 + chunk * 8192 + off) = lw;
                }
            }
    };

    // epilogue -> gmem fp32 (final layer, no activation)
    auto epi_gmem = [&](int n0w, const float* bias) {
#pragma unroll
        for (int mi = 0; mi < 2; ++mi)
#pragma unroll
            for (int nf = 0; nf < 8; ++nf) {
                int ncol = wn * 64 + nf * 8 + ((lane & 3) << 1);
                int n = n0w + ncol;
                if (n >= 257) continue;
                float b0 = __ldg(bias + n);
                bool ok1 = (n + 1 < 257);
                float b1 = ok1 ? __ldg(bias + n + 1) : 0.0f;
#pragma unroll
                for (int r2 = 0; r2 < 2; ++r2) {
                    int row = wm * 32 + mi * 16 + (lane >> 2) + r2 * 8;
                    size_t m = (size_t)(m0 + row);
                    out[m * 257 + n] = c[mi][nf][r2 * 2 + 0] + b0;
                    if (ok1) out[m * 257 + n + 1] = c[mi][nf][r2 * 2 + 1] + b1;
                }
            }
    };

    // ---- initial activation load ----
    load_full_act(gx, R_LOW0); CP_COMMIT(); CP_WAIT0(); __syncthreads();
    uint32_t lowR = R_LOW0, altR = R_LOW1;
    const int wrow[9] = {0, 256, 512, 768, 896, 1152, 1408, 1664, 1920};

#pragma unroll 1
    for (int l = 0; l < 9; ++l) {
        const __nv_bfloat16* Wl = gw + (size_t)wrow[l] * 512;
        const float* bias = bp.b[l];
        if (l == 8) {
#pragma unroll 1
            for (int h = 0; h < 3; ++h) {
                run_half(Wl, h * 128, lowR);
                epi_gmem(h * 128, bias);
            }
        } else if (l == 3) {
            run_half(Wl, 0, lowR);
            __syncthreads();                       // all done reading lowR+HIGH
            load_full_act(gs, altR); CP_COMMIT(); CP_WAIT0(); __syncthreads();
            epi_smem(altR, bias, 0, INV_SQRT2, 26);
            __syncthreads();
            uint32_t t = lowR; lowR = altR; altR = t;
        } else {
            run_half(Wl, 0, lowR);
            epi_smem(altR, bias, 0, 1.0f, 128);    // disjoint from reads
            run_half(Wl, 128, lowR);
            __syncthreads();                       // all done reading HIGH
            epi_smem(R_HIGH, bias, 128, 1.0f, 128);
            __syncthreads();
            uint32_t t = lowR; lowR = altR; altR = t;
        }
    }
}

// ---------------- launch ------------------------------------------------------
extern "C" void kernel_launch(void* const* d_in, const int* in_sizes, int n_in,
                              void* d_out, int out_size)
{
    const float* inp   = (const float*)d_in[0];
    const float* parts = (const float*)d_in[1];
    const float* table = (const float*)d_in[2];
    WPtrs wp;
    BPtrs bp;
    for (int l = 0; l < 9; ++l) {
        wp.w[l] = (const float*)d_in[3 + 2 * l];
        bp.b[l] = (const float*)d_in[4 + 2 * l];
    }

    float *xin, *st;
    __nv_bfloat16 *xb, *sb, *wbase;
    cudaGetSymbolAddress((void**)&xin, g_xin);
    cudaGetSymbolAddress((void**)&st,  g_stats);
    cudaGetSymbolAddress((void**)&xb, g_x);
    cudaGetSymbolAddress((void**)&sb, g_s);
    cudaGetSymbolAddress((void**)&wbase, g_w);

    const int BQ_SMEM = (16384 + 2560) * 4;
    cudaFuncSetAttribute(fused_mlp, cudaFuncAttributeMaxDynamicSharedMemorySize, SMEM_FUSED);
    cudaFuncSetAttribute(ball_query_kernel, cudaFuncAttributeMaxDynamicSharedMemorySize, BQ_SMEM);

    prep_w_all<<<(2304 * 256 + 255) / 256, 256>>>(wp, wbase);
    ball_query_kernel<<<P_PTS / 64, 256, BQ_SMEM>>>(inp, parts, st);
    encode_kernel<<<P_PTS / 32, 256>>>(inp, table, st, xin);
    conv_tr2<<<dim3(8, P_PTS / 32), dim3(32, 8)>>>(xin, xb, sb);
    fused_mlp<<<P_PTS / 128, 256, SMEM_FUSED>>>(xb, sb, wbase, bp, (float*)d_out);
}

// round 12
// speedup vs baseline: 1.7583x; 1.0027x over previous
#include <cuda_runtime.h>
#include <cuda_bf16.h>
#include <math.h>
#include <stdint.h>

#define P_PTS     16384
#define M_PART    4096
#define HASHMAP_SZ 524288u
#define NUM_LVL   16
#define INV_SQRT2 0.70710678118654752f

// ---------------- scratch (device globals; no allocation allowed) -------------
__device__ __align__(16) float g_xin[232 * P_PTS];
__device__ __align__(16) float g_stats[7 * P_PTS];
__device__ __align__(16) __nv_bfloat16 g_x[P_PTS * 512];
__device__ __align__(16) __nv_bfloat16 g_s[P_PTS * 512];   // skip input (cols 26..255)
__device__ __align__(16) __nv_bfloat16 g_w[2304 * 512];

// ---------------- PTX helpers -------------------------------------------------
static __device__ __forceinline__ uint32_t smem_u32(const void* p) {
    uint32_t a;
    asm("{ .reg .u64 t; cvta.to.shared.u64 t, %1; cvt.u32.u64 %0, t; }" : "=r"(a) : "l"(p));
    return a;
}
static __device__ __forceinline__ void cp16(uint32_t s, const void* g) {
    asm volatile("cp.async.ca.shared.global [%0], [%1], 16;" :: "r"(s), "l"(g));
}
#define CP_COMMIT()  asm volatile("cp.async.commit_group;" ::: "memory")
#define CP_WAIT0()   asm volatile("cp.async.wait_group 0;" ::: "memory")

static __device__ __forceinline__ void ldsm4(uint32_t* r, uint32_t a) {
    asm volatile("ldmatrix.sync.aligned.m8n8.x4.shared.b16 {%0,%1,%2,%3}, [%4];"
                 : "=r"(r[0]), "=r"(r[1]), "=r"(r[2]), "=r"(r[3]) : "r"(a));
}
static __device__ __forceinline__ void mma16816(float* c, const uint32_t* a,
                                                uint32_t b0, uint32_t b1) {
    asm volatile(
        "mma.sync.aligned.m16n8k16.row.col.f32.bf16.bf16.f32 "
        "{%0,%1,%2,%3}, {%4,%5,%6,%7}, {%8,%9}, {%0,%1,%2,%3};"
        : "+f"(c[0]), "+f"(c[1]), "+f"(c[2]), "+f"(c[3])
        : "r"(a[0]), "r"(a[1]), "r"(a[2]), "r"(a[3]), "r"(b0), "r"(b1));
}
static __device__ __forceinline__ float softplus100(float v) {
    float y = 100.0f * v;
    return (fmaxf(y, 0.0f) + __logf(1.0f + __expf(-fabsf(y)))) * 0.01f;
}

// ---------------- fused weight prep -------------------------------------------
struct WPtrs { const float* w[9]; };
struct BPtrs { const float* b[9]; };

__global__ void prep_w_all(WPtrs wp, __nv_bfloat16* __restrict__ out)
{
    int i = blockIdx.x * blockDim.x + threadIdx.x;
    if (i >= 2304 * 256) return;
    int r = i >> 8, k = i & 255;
    const int cum[10]  = {0, 256, 512, 768, 896, 1152, 1408, 1664, 1920, 2304};
    const int nout[9]  = {256, 256, 256, 26, 256, 256, 256, 256, 257};
    const int kact[9]  = {230, 256, 256, 256, 256, 256, 256, 256, 256};
    int l = 0;
#pragma unroll
    for (int t = 1; t < 9; ++t) if (r >= cum[t]) l = t;
    int n = r - cum[l];
    float v = (n < nout[l] && k < kact[l]) ? wp.w[l][n * kact[l] + k] : 0.0f;
    __nv_bfloat16 h = __float2bfloat16(v);
    out[(size_t)r * 512 + k]       = h;
    out[(size_t)r * 512 + 256 + k] = __float2bfloat16(v - __bfloat162float(h));
}

// ---------------- fused transpose + bf16-split: xin -> g_x AND g_s ------------
__global__ void conv_tr2(const float* __restrict__ src,
                         __nv_bfloat16* __restrict__ dx,
                         __nv_bfloat16* __restrict__ ds)
{
    __shared__ float s[32][33];
    int tx = threadIdx.x, ty = threadIdx.y;
    int ct = blockIdx.x, pt = blockIdx.y;
#pragma unroll
    for (int r2 = 0; r2 < 4; ++r2) {
        int ci = ty + r2 * 8;
        int c = ct * 32 + ci;
        int p = pt * 32 + tx;
        s[ci][tx] = (c < 232) ? src[(size_t)c * P_PTS + p] : 0.0f;
    }
    __syncthreads();
#pragma unroll
    for (int r2 = 0; r2 < 4; ++r2) {
        int pi = ty + r2 * 8;
        int p = pt * 32 + pi;
        int c = ct * 32 + tx;
        float v = s[tx][pi];
        __nv_bfloat16 h = __float2bfloat16(v);
        dx[(size_t)p * 512 + c]       = h;
        dx[(size_t)p * 512 + 256 + c] = __float2bfloat16(v - __bfloat162float(h));
        if (c < 230) {
            float vs = v * INV_SQRT2;
            __nv_bfloat16 hs = __float2bfloat16(vs);
            ds[(size_t)p * 512 + c + 26]       = hs;
            ds[(size_t)p * 512 + 256 + c + 26] = __float2bfloat16(vs - __bfloat162float(hs));
        }
    }
}

// ---------------- ball query (unchanged, passing) ------------------------------
__global__ __launch_bounds__(256)
void ball_query_kernel(const float* __restrict__ inp,
                       const float* __restrict__ parts,
                       float* __restrict__ stats)
{
    extern __shared__ float fsm[];
    float4* sp4 = (float4*)fsm;
    float*  ex  = fsm + 16384;
    int tid = threadIdx.x;
    for (int i = tid; i < M_PART; i += 256) {
        float px = parts[3 * i], py = parts[3 * i + 1], pz = parts[3 * i + 2];
        sp4[i] = make_float4(px, py, pz, (px * px + py * py) + pz * pz);
    }
    __syncthreads();

    const int c  = tid >> 6;
    const int pl = tid & 63;
    const int p  = blockIdx.x * 64 + pl;
    const float x = inp[3 * p], y = inp[3 * p + 1], z = inp[3 * p + 2];
    const float q1 = (x * x + y * y) + z * z;
    const float R2 = 0.01f;
    const int j0 = c << 10, j1 = j0 + 1024;

    int h = 0;
    float wsum = 0.f, swx = 0.f, swy = 0.f, swz = 0.f;
    float sdx = 0.f, sdy = 0.f, sdz = 0.f;
    float s2x = 0.f, s2y = 0.f, s2z = 0.f;
#pragma unroll 8
    for (int j = j0; j < j1; ++j) {
        float4 q = sp4[j];
        float dot = x * q.x + y * q.y + z * q.z;
        float d2e = (q1 + q.w) - 2.0f * dot;
        if (d2e < R2) {
            ++h;
            float dx = q.x - x, dy = q.y - y, dz = q.z - z;
            float d2 = dx * dx + dy * dy + dz * dz;
            float d  = sqrtf(fmaxf(d2, 1e-24f));
            float dr = d / 0.1f;
            float w  = fmaxf(1.0f - dr * dr * dr, 0.0f);
            wsum += w;
            swx = fmaf(w, q.x, swx); swy = fmaf(w, q.y, swy); swz = fmaf(w, q.z, swz);
            sdx += dx; sdy += dy; sdz += dz;
            s2x = fmaf(dx, dx, s2x); s2y = fmaf(dy, dy, s2y); s2z = fmaf(dz, dz, s2z);
        }
    }
    ex[c * 64 + pl] = (float)h;
    __syncthreads();
    int h0 = (int)ex[pl], h1 = (int)ex[64 + pl], h2 = (int)ex[128 + pl], h3 = (int)ex[192 + pl];
    int start = (c > 0 ? h0 : 0) + (c > 1 ? h1 : 0) + (c > 2 ? h2 : 0);
    int total = h0 + h1 + h2 + h3;
    int cnt   = min(32, total);
    int budget = max(0, min(32 - start, h));
    if (budget < h) {
        wsum = swx = swy = swz = 0.f;
        sdx = sdy = sdz = 0.f;
        s2x = s2y = s2z = 0.f;
        int taken = 0;
        for (int j = j0; j < j1 && taken < budget; ++j) {
            float4 q = sp4[j];
            float dot = x * q.x + y * q.y + z * q.z;
            float d2e = (q1 + q.w) - 2.0f * dot;
            if (d2e < R2) {
                ++taken;
                float dx = q.x - x, dy = q.y - y, dz = q.z - z;
                float d2 = dx * dx + dy * dy + dz * dz;
                float d  = sqrtf(fmaxf(d2, 1e-24f));
                float dr = d / 0.1f;
                float w  = fmaxf(1.0f - dr * dr * dr, 0.0f);
                wsum += w;
                swx = fmaf(w, q.x, swx); swy = fmaf(w, q.y, swy); swz = fmaf(w, q.z, swz);
                sdx += dx; sdy += dy; sdz += dz;
                s2x = fmaf(dx, dx, s2x); s2y = fmaf(dy, dy, s2y); s2z = fmaf(dz, dz, s2z);
            }
        }
    }
    __syncthreads();
    float part[10] = {wsum, swx, swy, swz, sdx, sdy, sdz, s2x, s2y, s2z};
#pragma unroll
    for (int f = 0; f < 10; ++f) ex[f * 256 + c * 64 + pl] = part[f];
    __syncthreads();

    if (c == 0) {
        float S[10];
#pragma unroll
        for (int f = 0; f < 10; ++f)
            S[f] = ((ex[f * 256 + pl] + ex[f * 256 + 64 + pl])
                  + ex[f * 256 + 128 + pl]) + ex[f * 256 + 192 + pl];
        int ninv = 32 - cnt;
        if (ninv > 0) {
            float d  = sqrtf(fmaxf(q1, 1e-24f));
            float dr = d / 0.1f;
            float w  = fmaxf(1.0f - dr * dr * dr, 0.0f);
            S[0] += (float)ninv * w;
        }
        float nf  = (float)cnt;
        float wdn = S[0] + 1e-12f;
        float den = nf + 1e-12f;
        float vmx = S[4] / den, vmy = S[5] / den, vmz = S[6] / den;
        stats[0 * P_PTS + p] = S[0];
        stats[1 * P_PTS + p] = S[1] / wdn;
        stats[2 * P_PTS + p] = S[2] / wdn;
        stats[3 * P_PTS + p] = S[3] / wdn;
        stats[4 * P_PTS + p] = (S[7] - 2.0f * vmx * S[4] + nf * vmx * vmx) / den;
        stats[5 * P_PTS + p] = (S[8] - 2.0f * vmy * S[5] + nf * vmy * vmy) / den;
        stats[6 * P_PTS + p] = (S[9] - 2.0f * vmz * S[6] + nf * vmz * vmz) / den;
    }
}

// ---------------- encode (unchanged, passing) ----------------------------------
__device__ __forceinline__ void penc3(float* __restrict__ xin, int p, int base,
                                      float a, float b, float c)
{
    xin[(base + 0) * P_PTS + p] = a;
    xin[(base + 1) * P_PTS + p] = b;
    xin[(base + 2) * P_PTS + p] = c;
    float v[3] = {a, b, c};
#pragma unroll
    for (int f = 0; f < 10; ++f) {
        float fr = (float)(1 << f);
#pragma unroll
        for (int ch = 0; ch < 3; ++ch) {
            float s, co;
            sincosf(v[ch] * fr, &s, &co);
            xin[(base + 3 + f * 6 + ch)     * P_PTS + p] = s;
            xin[(base + 3 + f * 6 + 3 + ch) * P_PTS + p] = co;
        }
    }
}

__global__ __launch_bounds__(256)
void encode_kernel(const float* __restrict__ inp,
                   const float* __restrict__ table,
                   const float* __restrict__ stats,
                   float* __restrict__ xin)
{
    int tid = threadIdx.x;
    int pl = tid & 31, s = tid >> 5;
    int p = blockIdx.x * 32 + pl;
    float x = inp[3 * p], y = inp[3 * p + 1], z = inp[3 * p + 2];

    if (s < 4) {
        float xn[3] = { (x / 1.5f + 1.0f) * 0.5f,
                        (y / 1.5f + 1.0f) * 0.5f,
                        (z / 1.5f + 1.0f) * 0.5f };
#pragma unroll 1
        for (int li = 0; li < 4; ++li) {
            int l = s * 4 + li;
            double scd   = exp2((7.0 * (double)l) / 15.0) * 16.0 - 1.0;
            float  scale = (float)scd;
            unsigned res = (unsigned)ceil(scd) + 1u;
            bool dense   = ((unsigned long long)res * res * res <= (unsigned long long)HASHMAP_SZ);
            unsigned pg[3]; float fr[3];
#pragma unroll
            for (int cc = 0; cc < 3; ++cc) {
                float pos = fmaf(xn[cc], scale, 0.5f);
                float pf  = floorf(pos);
                fr[cc] = pos - pf;
                pg[cc] = (unsigned)pf;
            }
            float wx[2] = {1.f - fr[0], fr[0]};
            float wy[2] = {1.f - fr[1], fr[1]};
            float wz[2] = {1.f - fr[2], fr[2]};
            const float2* tbl = (const float2*)table + (size_t)l * HASHMAP_SZ;
            float f0 = 0.f, f1 = 0.f;
#pragma unroll
            for (int cc = 0; cc < 8; ++cc) {
                unsigned gx = pg[0] + (unsigned)(cc & 1);
                unsigned gy = pg[1] + (unsigned)((cc >> 1) & 1);
                unsigned gz = pg[2] + (unsigned)((cc >> 2) & 1);
                unsigned idx;
                if (dense) idx = gx + gy * res + gz * res * res;
                else       idx = ((gx * 1u) ^ (gy * 2654435761u) ^ (gz * 805459861u)) & (HASHMAP_SZ - 1u);
                float w = (wx[cc & 1] * wy[(cc >> 1) & 1]) * wz[(cc >> 2) & 1];
                float2 t = tbl[idx];
                f0 = fmaf(w, t.x, f0);
                f1 = fmaf(w, t.y, f1);
            }
            xin[(198 + 2 * l) * P_PTS + p] = f0;
            xin[(199 + 2 * l) * P_PTS + p] = f1;
        }
    } else if (s == 4) {
        penc3(xin, p, 0, x, y, z);
    } else if (s == 5) {
        float wsum = stats[p];
        xin[63 * P_PTS + p] = wsum;
#pragma unroll
        for (int f = 0; f < 4; ++f) {
            float sn, co;
            sincosf(wsum * (float)(1 << f), &sn, &co);
            xin[(64 + 2 * f) * P_PTS + p] = sn;
            xin[(65 + 2 * f) * P_PTS + p] = co;
        }
        xin[230 * P_PTS + p] = 0.0f;
        xin[231 * P_PTS + p] = 0.0f;
    } else if (s == 6) {
        penc3(xin, p, 72, stats[1 * P_PTS + p], stats[2 * P_PTS + p], stats[3 * P_PTS + p]);
    } else {
        penc3(xin, p, 135, stats[4 * P_PTS + p], stats[5 * P_PTS + p], stats[6 * P_PTS + p]);
    }
}

// ---------------- fused persistent MLP ----------------------------------------
// smem regions (bytes): LOW0 [0,64K), LOW1 [64K,128K), HIGH [128K,192K),
// W stages [192K, 224K). Each act region: 4 HI tiles (8KB each) then 4 LO tiles.
#define R_LOW0 0
#define R_LOW1 65536
#define R_HIGH 131072
#define R_W    196608
#define SMEM_FUSED 229376

__global__ __launch_bounds__(256, 1)
void fused_mlp(const __nv_bfloat16* __restrict__ gx,
               const __nv_bfloat16* __restrict__ gs,
               const __nv_bfloat16* __restrict__ gw,
               BPtrs bp, float* __restrict__ out)
{
    extern __shared__ __align__(16) char smem[];
    const uint32_t s0 = smem_u32(smem);
    const int tid = threadIdx.x, warp = tid >> 5, lane = tid & 31;
    const int wm = warp & 3, wn = warp >> 2;
    const int m0 = blockIdx.x << 7;

    const int rbase = tid >> 2, cc = tid & 3;
    const uint32_t so0 = (uint32_t)(rbase * 64) +
                         (((uint32_t)cc ^ (((uint32_t)rbase >> 1) & 3)) << 4);

    const int lrow = lane & 15;
    const uint32_t lhi = (uint32_t)(lane >> 4);
    uint32_t rowA[2], rqA[2], rowB[4], rqB[4];
#pragma unroll
    for (int mi = 0; mi < 2; ++mi) {
        int R = wm * 32 + mi * 16 + lrow;
        rowA[mi] = (uint32_t)(R * 64); rqA[mi] = (uint32_t)((R >> 1) & 3);
    }
#pragma unroll
    for (int nb = 0; nb < 4; ++nb) {
        int R = wn * 64 + nb * 16 + lrow;
        rowB[nb] = (uint32_t)(R * 64); rqB[nb] = (uint32_t)((R >> 1) & 3);
    }

    // load a full activation set (8 K-chunks, hi+lo) from global [P][512]
    auto load_full_act = [&](const __nv_bfloat16* src, uint32_t lowR) {
        const __nv_bfloat16* pS = src + (size_t)(m0 + rbase) * 512 + cc * 8;
#pragma unroll
        for (int kc = 0; kc < 8; ++kc) {
            uint32_t hiT = (kc < 4) ? (lowR + (uint32_t)kc * 8192)
                                    : (R_HIGH + (uint32_t)(kc - 4) * 8192);
            int k32 = kc << 5;
            cp16(s0 + hiT + so0,                pS + k32);
            cp16(s0 + hiT + so0 + 4096,         pS + 64 * 512 + k32);
            cp16(s0 + hiT + 32768 + so0,        pS + 256 + k32);
            cp16(s0 + hiT + 32768 + so0 + 4096, pS + 64 * 512 + 256 + k32);
        }
    };
    auto load_w = [&](const __nv_bfloat16* Wl, int n0w, int kc, int stg) {
        const __nv_bfloat16* pW = Wl + (size_t)(n0w + rbase) * 512 + cc * 8;
        uint32_t wb = s0 + R_W + (uint32_t)stg * 16384;
        int k32 = kc << 5;
        cp16(wb + so0,               pW + k32);
        cp16(wb + so0 + 4096,        pW + 64 * 512 + k32);
        cp16(wb + 8192 + so0,        pW + 256 + k32);
        cp16(wb + 8192 + so0 + 4096, pW + 64 * 512 + 256 + k32);
    };

    float c[2][8][4];
    uint32_t aF[2][8], bF[2][16];

    auto ldA = [&](int buf, uint32_t tile, int ks) {
        uint32_t ch = (uint32_t)(2 * ks) + lhi;
        ldsm4(&aF[buf][0], tile + rowA[0] + ((ch ^ rqA[0]) << 4));
        ldsm4(&aF[buf][4], tile + rowA[1] + ((ch ^ rqA[1]) << 4));
    };
    auto ldB = [&](int buf, uint32_t tile, int ks) {
        uint32_t ch = (uint32_t)(2 * ks) + lhi;
#pragma unroll
        for (int nb = 0; nb < 4; ++nb)
            ldsm4(&bF[buf][nb * 4], tile + rowB[nb] + ((ch ^ rqB[nb]) << 4));
    };
    auto mmaBlk = [&](int abuf, int bbuf) {
#pragma unroll
        for (int mi = 0; mi < 2; ++mi)
#pragma unroll
            for (int nb = 0; nb < 4; ++nb) {
                mma16816(c[mi][nb * 2],     &aF[abuf][mi * 4],
                         bF[bbuf][nb * 4 + 0], bF[bbuf][nb * 4 + 2]);
                mma16816(c[mi][nb * 2 + 1], &aF[abuf][mi * 4],
                         bF[bbuf][nb * 4 + 1], bF[bbuf][nb * 4 + 3]);
            }
    };

    // one N-half (128 cols): full K=256 bf16x3 mainloop, accumulators in c.
    // Steps per chunk: s0 AHI0*WHI0, s1 ALO0*WHI0, s2 AHI1*WHI1, s3 ALO1*WHI1,
    //                  s4 AHI0*WLO0, s5 AHI1*WLO1. A and B double-buffered so
    //                  every step's fragments load during the previous MMA block.
    auto run_half = [&](const __nv_bfloat16* Wl, int n0w, uint32_t lowR) {
#pragma unroll
        for (int mi = 0; mi < 2; ++mi)
#pragma unroll
            for (int nf = 0; nf < 8; ++nf)
#pragma unroll
                for (int r = 0; r < 4; ++r) c[mi][nf][r] = 0.0f;
        load_w(Wl, n0w, 0, 0); CP_COMMIT();
#pragma unroll 1
        for (int kc = 0; kc < 8; ++kc) {
            CP_WAIT0();
            __syncthreads();
            if (kc + 1 < 8) { load_w(Wl, n0w, kc + 1, (kc + 1) & 1); CP_COMMIT(); }
            uint32_t tHI = s0 + ((kc < 4) ? (lowR + (uint32_t)kc * 8192)
                                          : (R_HIGH + (uint32_t)(kc - 4) * 8192));
            uint32_t tLO = tHI + 32768;
            uint32_t wst = s0 + R_W + (uint32_t)(kc & 1) * 16384;
            uint32_t wlo = wst + 8192;
            ldB(0, wst, 0); ldA(0, tHI, 0);   // s0 frags
            ldA(1, tLO, 0);                   // s1 A
            mmaBlk(0, 0);                     // s0
            ldB(1, wst, 1);                   // s2/s3 B
            ldA(0, tHI, 1);                   // s2 A
            mmaBlk(1, 0);                     // s1
            ldA(1, tLO, 1);                   // s3 A
            mmaBlk(0, 1);                     // s2
            ldB(0, wlo, 0);                   // s4 B
            ldA(0, tHI, 0);                   // s4 A
            mmaBlk(1, 1);                     // s3
            ldB(1, wlo, 1);                   // s5 B
            ldA(1, tHI, 1);                   // s5 A
            mmaBlk(0, 0);                     // s4
            mmaBlk(1, 1);                     // s5
        }
    };

    // epilogue -> smem region (softplus always; scale os; valid cols < validN)
    auto epi_smem = [&](uint32_t destR, const float* bias, int nb0, float os, int validN) {
#pragma unroll
        for (int mi = 0; mi < 2; ++mi)
#pragma unroll
            for (int nf = 0; nf < 8; ++nf) {
                int ncol = wn * 64 + nf * 8 + ((lane & 3) << 1);
                if (ncol >= validN) continue;
                float b0 = __ldg(bias + nb0 + ncol);
                float b1 = __ldg(bias + nb0 + ncol + 1);
                uint32_t chunk = (uint32_t)ncol >> 5;
                uint32_t cpos  = (uint32_t)ncol & 31;
#pragma unroll
                for (int r2 = 0; r2 < 2; ++r2) {
                    int row = wm * 32 + mi * 16 + (lane >> 2) + r2 * 8;
                    float v0 = softplus100(c[mi][nf][r2 * 2 + 0] + b0) * os;
                    float v1 = softplus100(c[mi][nf][r2 * 2 + 1] + b1) * os;
                    __nv_bfloat16 h0 = __float2bfloat16(v0);
                    __nv_bfloat16 h1 = __float2bfloat16(v1);
                    __nv_bfloat16 l0 = __float2bfloat16(v0 - __bfloat162float(h0));
                    __nv_bfloat16 l1 = __float2bfloat16(v1 - __bfloat162float(h1));
                    uint32_t hw = (uint32_t)__bfloat16_as_ushort(h0) |
                                  ((uint32_t)__bfloat16_as_ushort(h1) << 16);
                    uint32_t lw = (uint32_t)__bfloat16_as_ushort(l0) |
                                  ((uint32_t)__bfloat16_as_ushort(l1) << 16);
                    uint32_t off = (uint32_t)(row * 64) +
                                   (((cpos >> 3) ^ (((uint32_t)row >> 1) & 3)) << 4) +
                                   ((cpos & 7) << 1);
                    *(uint32_t*)(smem + destR + chunk * 8192 + off)         = hw;
                    *(uint32_t*)(smem + destR + 32768 + chunk * 8192 + off) = lw;
                }
            }
    };

    // epilogue -> gmem fp32 (final layer, no activation)
    auto epi_gmem = [&](int n0w, const float* bias) {
#pragma unroll
        for (int mi = 0; mi < 2; ++mi)
#pragma unroll
            for (int nf = 0; nf < 8; ++nf) {
                int ncol = wn * 64 + nf * 8 + ((lane & 3) << 1);
                int n = n0w + ncol;
                if (n >= 257) continue;
                float b0 = __ldg(bias + n);
                bool ok1 = (n + 1 < 257);
                float b1 = ok1 ? __ldg(bias + n + 1) : 0.0f;
#pragma unroll
                for (int r2 = 0; r2 < 2; ++r2) {
                    int row = wm * 32 + mi * 16 + (lane >> 2) + r2 * 8;
                    size_t m = (size_t)(m0 + row);
                    out[m * 257 + n] = c[mi][nf][r2 * 2 + 0] + b0;
                    if (ok1) out[m * 257 + n + 1] = c[mi][nf][r2 * 2 + 1] + b1;
                }
            }
    };

    // ---- initial activation load ----
    load_full_act(gx, R_LOW0); CP_COMMIT(); CP_WAIT0(); __syncthreads();
    uint32_t lowR = R_LOW0, altR = R_LOW1;
    const int wrow[9] = {0, 256, 512, 768, 896, 1152, 1408, 1664, 1920};

#pragma unroll 1
    for (int l = 0; l < 9; ++l) {
        const __nv_bfloat16* Wl = gw + (size_t)wrow[l] * 512;
        const float* bias = bp.b[l];
        if (l == 8) {
#pragma unroll 1
            for (int h = 0; h < 3; ++h) {
                run_half(Wl, h * 128, lowR);
                epi_gmem(h * 128, bias);
            }
        } else if (l == 3) {
            run_half(Wl, 0, lowR);
            __syncthreads();                       // all done reading lowR+HIGH
            load_full_act(gs, altR); CP_COMMIT(); CP_WAIT0(); __syncthreads();
            epi_smem(altR, bias, 0, INV_SQRT2, 26);
            __syncthreads();
            uint32_t t = lowR; lowR = altR; altR = t;
        } else {
            run_half(Wl, 0, lowR);
            epi_smem(altR, bias, 0, 1.0f, 128);    // disjoint from reads
            run_half(Wl, 128, lowR);
            __syncthreads();                       // all done reading HIGH
            epi_smem(R_HIGH, bias, 128, 1.0f, 128);
            __syncthreads();
            uint32_t t = lowR; lowR = altR; altR = t;
        }
    }
}

// ---------------- launch ------------------------------------------------------
extern "C" void kernel_launch(void* const* d_in, const int* in_sizes, int n_in,
                              void* d_out, int out_size)
{
    const float* inp   = (const float*)d_in[0];
    const float* parts = (const float*)d_in[1];
    const float* table = (const float*)d_in[2];
    WPtrs wp;
    BPtrs bp;
    for (int l = 0; l < 9; ++l) {
        wp.w[l] = (const float*)d_in[3 + 2 * l];
        bp.b[l] = (const float*)d_in[4 + 2 * l];
    }

    float *xin, *st;
    __nv_bfloat16 *xb, *sb, *wbase;
    cudaGetSymbolAddress((void**)&xin, g_xin);
    cudaGetSymbolAddress((void**)&st,  g_stats);
    cudaGetSymbolAddress((void**)&xb, g_x);
    cudaGetSymbolAddress((void**)&sb, g_s);
    cudaGetSymbolAddress((void**)&wbase, g_w);

    const int BQ_SMEM = (16384 + 2560) * 4;
    cudaFuncSetAttribute(fused_mlp, cudaFuncAttributeMaxDynamicSharedMemorySize, SMEM_FUSED);
    cudaFuncSetAttribute(ball_query_kernel, cudaFuncAttributeMaxDynamicSharedMemorySize, BQ_SMEM);

    prep_w_all<<<(2304 * 256 + 255) / 256, 256>>>(wp, wbase);
    ball_query_kernel<<<P_PTS / 64, 256, BQ_SMEM>>>(inp, parts, st);
    encode_kernel<<<P_PTS / 32, 256>>>(inp, table, st, xin);
    conv_tr2<<<dim3(8, P_PTS / 32), dim3(32, 8)>>>(xin, xb, sb);
    fused_mlp<<<P_PTS / 128, 256, SMEM_FUSED>>>(xb, sb, wbase, bp, (float*)d_out);
}

// round 13
// speedup vs baseline: 1.8105x; 1.0297x over previous
#include <cuda_runtime.h>
#include <cuda_bf16.h>
#include <math.h>
#include <stdint.h>

#define P_PTS     16384
#define M_PART    4096
#define HASHMAP_SZ 524288u
#define NUM_LVL   16
#define INV_SQRT2 0.70710678118654752f

// ---------------- scratch (device globals; no allocation allowed) -------------
__device__ __align__(16) float g_xin[232 * P_PTS];
__device__ __align__(16) float g_stats[7 * P_PTS];
__device__ __align__(16) __nv_bfloat16 g_x[P_PTS * 512];
__device__ __align__(16) __nv_bfloat16 g_s[P_PTS * 512];   // skip input (cols 26..255)
__device__ __align__(16) __nv_bfloat16 g_w[2304 * 512];

// ---------------- PTX helpers -------------------------------------------------
static __device__ __forceinline__ uint32_t smem_u32(const void* p) {
    uint32_t a;
    asm("{ .reg .u64 t; cvta.to.shared.u64 t, %1; cvt.u32.u64 %0, t; }" : "=r"(a) : "l"(p));
    return a;
}
static __device__ __forceinline__ void cp16(uint32_t s, const void* g) {
    asm volatile("cp.async.ca.shared.global [%0], [%1], 16;" :: "r"(s), "l"(g));
}
#define CP_COMMIT()  asm volatile("cp.async.commit_group;" ::: "memory")
#define CP_WAIT0()   asm volatile("cp.async.wait_group 0;" ::: "memory")

static __device__ __forceinline__ void ldsm4(uint32_t* r, uint32_t a) {
    asm volatile("ldmatrix.sync.aligned.m8n8.x4.shared.b16 {%0,%1,%2,%3}, [%4];"
                 : "=r"(r[0]), "=r"(r[1]), "=r"(r[2]), "=r"(r[3]) : "r"(a));
}
static __device__ __forceinline__ void mma16816(float* c, const uint32_t* a,
                                                uint32_t b0, uint32_t b1) {
    asm volatile(
        "mma.sync.aligned.m16n8k16.row.col.f32.bf16.bf16.f32 "
        "{%0,%1,%2,%3}, {%4,%5,%6,%7}, {%8,%9}, {%0,%1,%2,%3};"
        : "+f"(c[0]), "+f"(c[1]), "+f"(c[2]), "+f"(c[3])
        : "r"(a[0]), "r"(a[1]), "r"(a[2]), "r"(a[3]), "r"(b0), "r"(b1));
}
static __device__ __forceinline__ float softplus100(float v) {
    float y = 100.0f * v;
    return (fmaxf(y, 0.0f) + __logf(1.0f + __expf(-fabsf(y)))) * 0.01f;
}

struct WPtrs { const float* w[9]; };
struct BPtrs { const float* b[9]; };

// ---------------- ball query + fused weight prep ------------------------------
__global__ __launch_bounds__(256)
void ball_prep_kernel(const float* __restrict__ inp,
                      const float* __restrict__ parts,
                      float* __restrict__ stats,
                      WPtrs wp, __nv_bfloat16* __restrict__ wout)
{
    // ---- weight prep: 9 elements per thread (2304*256 = 9*65536) ----
    {
        const int cum[10]  = {0, 256, 512, 768, 896, 1152, 1408, 1664, 1920, 2304};
        const int nout[9]  = {256, 256, 256, 26, 256, 256, 256, 256, 257};
        const int kact[9]  = {230, 256, 256, 256, 256, 256, 256, 256, 256};
        int gid = blockIdx.x * 256 + threadIdx.x;
#pragma unroll
        for (int t9 = 0; t9 < 9; ++t9) {
            int i = gid + t9 * 65536;
            int r = i >> 8, k = i & 255;
            int l = 0;
#pragma unroll
            for (int t = 1; t < 9; ++t) if (r >= cum[t]) l = t;
            int n = r - cum[l];
            float v = (n < nout[l] && k < kact[l]) ? wp.w[l][n * kact[l] + k] : 0.0f;
            __nv_bfloat16 h = __float2bfloat16(v);
            wout[(size_t)r * 512 + k]       = h;
            wout[(size_t)r * 512 + 256 + k] = __float2bfloat16(v - __bfloat162float(h));
        }
    }

    // ---- ball query ----
    extern __shared__ float fsm[];
    float4* sp4 = (float4*)fsm;
    float*  ex  = fsm + 16384;
    int tid = threadIdx.x;
    for (int i = tid; i < M_PART; i += 256) {
        float px = parts[3 * i], py = parts[3 * i + 1], pz = parts[3 * i + 2];
        sp4[i] = make_float4(px, py, pz, (px * px + py * py) + pz * pz);
    }
    __syncthreads();

    const int c  = tid >> 6;
    const int pl = tid & 63;
    const int p  = blockIdx.x * 64 + pl;
    const float x = inp[3 * p], y = inp[3 * p + 1], z = inp[3 * p + 2];
    const float q1 = (x * x + y * y) + z * z;
    const float R2 = 0.01f;
    const int j0 = c << 10, j1 = j0 + 1024;

    int h = 0;
    float wsum = 0.f, swx = 0.f, swy = 0.f, swz = 0.f;
    float sdx = 0.f, sdy = 0.f, sdz = 0.f;
    float s2x = 0.f, s2y = 0.f, s2z = 0.f;
#pragma unroll 8
    for (int j = j0; j < j1; ++j) {
        float4 q = sp4[j];
        float dot = x * q.x + y * q.y + z * q.z;
        float d2e = (q1 + q.w) - 2.0f * dot;
        if (d2e < R2) {
            ++h;
            float dx = q.x - x, dy = q.y - y, dz = q.z - z;
            float d2 = dx * dx + dy * dy + dz * dz;
            float d  = sqrtf(fmaxf(d2, 1e-24f));
            float dr = d / 0.1f;
            float w  = fmaxf(1.0f - dr * dr * dr, 0.0f);
            wsum += w;
            swx = fmaf(w, q.x, swx); swy = fmaf(w, q.y, swy); swz = fmaf(w, q.z, swz);
            sdx += dx; sdy += dy; sdz += dz;
            s2x = fmaf(dx, dx, s2x); s2y = fmaf(dy, dy, s2y); s2z = fmaf(dz, dz, s2z);
        }
    }
    ex[c * 64 + pl] = (float)h;
    __syncthreads();
    int h0 = (int)ex[pl], h1 = (int)ex[64 + pl], h2 = (int)ex[128 + pl], h3 = (int)ex[192 + pl];
    int start = (c > 0 ? h0 : 0) + (c > 1 ? h1 : 0) + (c > 2 ? h2 : 0);
    int total = h0 + h1 + h2 + h3;
    int cnt   = min(32, total);
    int budget = max(0, min(32 - start, h));
    if (budget < h) {
        wsum = swx = swy = swz = 0.f;
        sdx = sdy = sdz = 0.f;
        s2x = s2y = s2z = 0.f;
        int taken = 0;
        for (int j = j0; j < j1 && taken < budget; ++j) {
            float4 q = sp4[j];
            float dot = x * q.x + y * q.y + z * q.z;
            float d2e = (q1 + q.w) - 2.0f * dot;
            if (d2e < R2) {
                ++taken;
                float dx = q.x - x, dy = q.y - y, dz = q.z - z;
                float d2 = dx * dx + dy * dy + dz * dz;
                float d  = sqrtf(fmaxf(d2, 1e-24f));
                float dr = d / 0.1f;
                float w  = fmaxf(1.0f - dr * dr * dr, 0.0f);
                wsum += w;
                swx = fmaf(w, q.x, swx); swy = fmaf(w, q.y, swy); swz = fmaf(w, q.z, swz);
                sdx += dx; sdy += dy; sdz += dz;
                s2x = fmaf(dx, dx, s2x); s2y = fmaf(dy, dy, s2y); s2z = fmaf(dz, dz, s2z);
            }
        }
    }
    __syncthreads();
    float part[10] = {wsum, swx, swy, swz, sdx, sdy, sdz, s2x, s2y, s2z};
#pragma unroll
    for (int f = 0; f < 10; ++f) ex[f * 256 + c * 64 + pl] = part[f];
    __syncthreads();

    if (c == 0) {
        float S[10];
#pragma unroll
        for (int f = 0; f < 10; ++f)
            S[f] = ((ex[f * 256 + pl] + ex[f * 256 + 64 + pl])
                  + ex[f * 256 + 128 + pl]) + ex[f * 256 + 192 + pl];
        int ninv = 32 - cnt;
        if (ninv > 0) {
            float d  = sqrtf(fmaxf(q1, 1e-24f));
            float dr = d / 0.1f;
            float w  = fmaxf(1.0f - dr * dr * dr, 0.0f);
            S[0] += (float)ninv * w;
        }
        float nf  = (float)cnt;
        float wdn = S[0] + 1e-12f;
        float den = nf + 1e-12f;
        float vmx = S[4] / den, vmy = S[5] / den, vmz = S[6] / den;
        stats[0 * P_PTS + p] = S[0];
        stats[1 * P_PTS + p] = S[1] / wdn;
        stats[2 * P_PTS + p] = S[2] / wdn;
        stats[3 * P_PTS + p] = S[3] / wdn;
        stats[4 * P_PTS + p] = (S[7] - 2.0f * vmx * S[4] + nf * vmx * vmx) / den;
        stats[5 * P_PTS + p] = (S[8] - 2.0f * vmy * S[5] + nf * vmy * vmy) / den;
        stats[6 * P_PTS + p] = (S[9] - 2.0f * vmz * S[6] + nf * vmz * vmz) / den;
    }
}

// ---------------- encode (unchanged, passing) ----------------------------------
__device__ __forceinline__ void penc3(float* __restrict__ xin, int p, int base,
                                      float a, float b, float c)
{
    xin[(base + 0) * P_PTS + p] = a;
    xin[(base + 1) * P_PTS + p] = b;
    xin[(base + 2) * P_PTS + p] = c;
    float v[3] = {a, b, c};
#pragma unroll
    for (int f = 0; f < 10; ++f) {
        float fr = (float)(1 << f);
#pragma unroll
        for (int ch = 0; ch < 3; ++ch) {
            float s, co;
            sincosf(v[ch] * fr, &s, &co);
            xin[(base + 3 + f * 6 + ch)     * P_PTS + p] = s;
            xin[(base + 3 + f * 6 + 3 + ch) * P_PTS + p] = co;
        }
    }
}

__global__ __launch_bounds__(256)
void encode_kernel(const float* __restrict__ inp,
                   const float* __restrict__ table,
                   const float* __restrict__ stats,
                   float* __restrict__ xin)
{
    int tid = threadIdx.x;
    int pl = tid & 31, s = tid >> 5;
    int p = blockIdx.x * 32 + pl;
    float x = inp[3 * p], y = inp[3 * p + 1], z = inp[3 * p + 2];

    if (s < 4) {
        float xn[3] = { (x / 1.5f + 1.0f) * 0.5f,
                        (y / 1.5f + 1.0f) * 0.5f,
                        (z / 1.5f + 1.0f) * 0.5f };
#pragma unroll 1
        for (int li = 0; li < 4; ++li) {
            int l = s * 4 + li;
            double scd   = exp2((7.0 * (double)l) / 15.0) * 16.0 - 1.0;
            float  scale = (float)scd;
            unsigned res = (unsigned)ceil(scd) + 1u;
            bool dense   = ((unsigned long long)res * res * res <= (unsigned long long)HASHMAP_SZ);
            unsigned pg[3]; float fr[3];
#pragma unroll
            for (int cc = 0; cc < 3; ++cc) {
                float pos = fmaf(xn[cc], scale, 0.5f);
                float pf  = floorf(pos);
                fr[cc] = pos - pf;
                pg[cc] = (unsigned)pf;
            }
            float wx[2] = {1.f - fr[0], fr[0]};
            float wy[2] = {1.f - fr[1], fr[1]};
            float wz[2] = {1.f - fr[2], fr[2]};
            const float2* tbl = (const float2*)table + (size_t)l * HASHMAP_SZ;
            float f0 = 0.f, f1 = 0.f;
#pragma unroll
            for (int cc = 0; cc < 8; ++cc) {
                unsigned gx = pg[0] + (unsigned)(cc & 1);
                unsigned gy = pg[1] + (unsigned)((cc >> 1) & 1);
                unsigned gz = pg[2] + (unsigned)((cc >> 2) & 1);
                unsigned idx;
                if (dense) idx = gx + gy * res + gz * res * res;
                else       idx = ((gx * 1u) ^ (gy * 2654435761u) ^ (gz * 805459861u)) & (HASHMAP_SZ - 1u);
                float w = (wx[cc & 1] * wy[(cc >> 1) & 1]) * wz[(cc >> 2) & 1];
                float2 t = tbl[idx];
                f0 = fmaf(w, t.x, f0);
                f1 = fmaf(w, t.y, f1);
            }
            xin[(198 + 2 * l) * P_PTS + p] = f0;
            xin[(199 + 2 * l) * P_PTS + p] = f1;
        }
    } else if (s == 4) {
        penc3(xin, p, 0, x, y, z);
    } else if (s == 5) {
        float wsum = stats[p];
        xin[63 * P_PTS + p] = wsum;
#pragma unroll
        for (int f = 0; f < 4; ++f) {
            float sn, co;
            sincosf(wsum * (float)(1 << f), &sn, &co);
            xin[(64 + 2 * f) * P_PTS + p] = sn;
            xin[(65 + 2 * f) * P_PTS + p] = co;
        }
        xin[230 * P_PTS + p] = 0.0f;
        xin[231 * P_PTS + p] = 0.0f;
    } else if (s == 6) {
        penc3(xin, p, 72, stats[1 * P_PTS + p], stats[2 * P_PTS + p], stats[3 * P_PTS + p]);
    } else {
        penc3(xin, p, 135, stats[4 * P_PTS + p], stats[5 * P_PTS + p], stats[6 * P_PTS + p]);
    }
}

// ---------------- fused transpose + bf16-split: xin -> g_x AND g_s ------------
__global__ void conv_tr2(const float* __restrict__ src,
                         __nv_bfloat16* __restrict__ dx,
                         __nv_bfloat16* __restrict__ ds)
{
    __shared__ float s[32][33];
    int tx = threadIdx.x, ty = threadIdx.y;
    int ct = blockIdx.x, pt = blockIdx.y;
#pragma unroll
    for (int r2 = 0; r2 < 4; ++r2) {
        int ci = ty + r2 * 8;
        int c = ct * 32 + ci;
        int p = pt * 32 + tx;
        s[ci][tx] = (c < 232) ? src[(size_t)c * P_PTS + p] : 0.0f;
    }
    __syncthreads();
#pragma unroll
    for (int r2 = 0; r2 < 4; ++r2) {
        int pi = ty + r2 * 8;
        int p = pt * 32 + pi;
        int c = ct * 32 + tx;
        float v = s[tx][pi];
        __nv_bfloat16 h = __float2bfloat16(v);
        dx[(size_t)p * 512 + c]       = h;
        dx[(size_t)p * 512 + 256 + c] = __float2bfloat16(v - __bfloat162float(h));
        if (c < 230) {
            float vs = v * INV_SQRT2;
            __nv_bfloat16 hs = __float2bfloat16(vs);
            ds[(size_t)p * 512 + c + 26]       = hs;
            ds[(size_t)p * 512 + 256 + c + 26] = __float2bfloat16(vs - __bfloat162float(hs));
        }
    }
}

// ---------------- fused persistent MLP ----------------------------------------
#define R_LOW0 0
#define R_LOW1 65536
#define R_HIGH 131072
#define R_W    196608
#define SMEM_FUSED 229376

__global__ __launch_bounds__(256, 1)
void fused_mlp(const __nv_bfloat16* __restrict__ gx,
               const __nv_bfloat16* __restrict__ gs,
               const __nv_bfloat16* __restrict__ gw,
               BPtrs bp, float* __restrict__ out)
{
    extern __shared__ __align__(16) char smem[];
    const uint32_t s0 = smem_u32(smem);
    const int tid = threadIdx.x, warp = tid >> 5, lane = tid & 31;
    const int wm = warp & 3, wn = warp >> 2;
    const int m0 = blockIdx.x << 7;

    const int rbase = tid >> 2, cc = tid & 3;
    const uint32_t so0 = (uint32_t)(rbase * 64) +
                         (((uint32_t)cc ^ (((uint32_t)rbase >> 1) & 3)) << 4);

    const int lrow = lane & 15;
    const uint32_t lhi = (uint32_t)(lane >> 4);
    uint32_t rowA[2], rqA[2], rowB[4], rqB[4];
#pragma unroll
    for (int mi = 0; mi < 2; ++mi) {
        int R = wm * 32 + mi * 16 + lrow;
        rowA[mi] = (uint32_t)(R * 64); rqA[mi] = (uint32_t)((R >> 1) & 3);
    }
#pragma unroll
    for (int nb = 0; nb < 4; ++nb) {
        int R = wn * 64 + nb * 16 + lrow;
        rowB[nb] = (uint32_t)(R * 64); rqB[nb] = (uint32_t)((R >> 1) & 3);
    }

    auto load_full_act = [&](const __nv_bfloat16* src, uint32_t lowR) {
        const __nv_bfloat16* pS = src + (size_t)(m0 + rbase) * 512 + cc * 8;
#pragma unroll
        for (int kc = 0; kc < 8; ++kc) {
            uint32_t hiT = (kc < 4) ? (lowR + (uint32_t)kc * 8192)
                                    : (R_HIGH + (uint32_t)(kc - 4) * 8192);
            int k32 = kc << 5;
            cp16(s0 + hiT + so0,                pS + k32);
            cp16(s0 + hiT + so0 + 4096,         pS + 64 * 512 + k32);
            cp16(s0 + hiT + 32768 + so0,        pS + 256 + k32);
            cp16(s0 + hiT + 32768 + so0 + 4096, pS + 64 * 512 + 256 + k32);
        }
    };
    auto load_w = [&](const __nv_bfloat16* Wl, int n0w, int kc, int stg) {
        const __nv_bfloat16* pW = Wl + (size_t)(n0w + rbase) * 512 + cc * 8;
        uint32_t wb = s0 + R_W + (uint32_t)stg * 16384;
        int k32 = kc << 5;
        cp16(wb + so0,               pW + k32);
        cp16(wb + so0 + 4096,        pW + 64 * 512 + k32);
        cp16(wb + 8192 + so0,        pW + 256 + k32);
        cp16(wb + 8192 + so0 + 4096, pW + 64 * 512 + 256 + k32);
    };

    float c[2][8][4];
    uint32_t aF[3][8], bF[2][16];

    auto ldA = [&](int buf, uint32_t tile, int ks) {
        uint32_t ch = (uint32_t)(2 * ks) + lhi;
        ldsm4(&aF[buf][0], tile + rowA[0] + ((ch ^ rqA[0]) << 4));
        ldsm4(&aF[buf][4], tile + rowA[1] + ((ch ^ rqA[1]) << 4));
    };
    auto ldB = [&](int buf, uint32_t tile, int ks) {
        uint32_t ch = (uint32_t)(2 * ks) + lhi;
#pragma unroll
        for (int nb = 0; nb < 4; ++nb)
            ldsm4(&bF[buf][nb * 4], tile + rowB[nb] + ((ch ^ rqB[nb]) << 4));
    };
    auto mmaBlk = [&](int abuf, int bbuf) {
#pragma unroll
        for (int mi = 0; mi < 2; ++mi)
#pragma unroll
            for (int nb = 0; nb < 4; ++nb) {
                mma16816(c[mi][nb * 2],     &aF[abuf][mi * 4],
                         bF[bbuf][nb * 4 + 0], bF[bbuf][nb * 4 + 2]);
                mma16816(c[mi][nb * 2 + 1], &aF[abuf][mi * 4],
                         bF[bbuf][nb * 4 + 1], bF[bbuf][nb * 4 + 3]);
            }
    };

    // Steps: s0 AHI0*WHI0, s1 ALO0*WHI0, s2 AHI1*WHI1, s3 ALO1*WHI1,
    //        s4 AHI0*WLO0, s5 AHI1*WLO1.  AHI0/AHI1 cached for the whole chunk.
    auto run_half = [&](const __nv_bfloat16* Wl, int n0w, uint32_t lowR) {
#pragma unroll
        for (int mi = 0; mi < 2; ++mi)
#pragma unroll
            for (int nf = 0; nf < 8; ++nf)
#pragma unroll
                for (int r = 0; r < 4; ++r) c[mi][nf][r] = 0.0f;
        load_w(Wl, n0w, 0, 0); CP_COMMIT();
#pragma unroll 1
        for (int kc = 0; kc < 8; ++kc) {
            CP_WAIT0();
            __syncthreads();
            if (kc + 1 < 8) { load_w(Wl, n0w, kc + 1, (kc + 1) & 1); CP_COMMIT(); }
            uint32_t tHI = s0 + ((kc < 4) ? (lowR + (uint32_t)kc * 8192)
                                          : (R_HIGH + (uint32_t)(kc - 4) * 8192));
            uint32_t tLO = tHI + 32768;
            uint32_t wst = s0 + R_W + (uint32_t)(kc & 1) * 16384;
            uint32_t wlo = wst + 8192;
            ldB(0, wst, 0);          // WHI0
            ldA(0, tHI, 0);          // AHI0 (cached)
            ldA(2, tLO, 0);          // ALO0
            mmaBlk(0, 0);            // s0
            ldB(1, wst, 1);          // WHI1
            ldA(1, tHI, 1);          // AHI1 (cached)
            mmaBlk(2, 0);            // s1
            ldA(2, tLO, 1);          // ALO1
            mmaBlk(1, 1);            // s2
            ldB(0, wlo, 0);          // WLO0 (WHI0 dead after s1)
            mmaBlk(2, 1);            // s3
            ldB(1, wlo, 1);          // WLO1 (WHI1 dead after s3)
            mmaBlk(0, 0);            // s4
            mmaBlk(1, 1);            // s5
        }
    };

    auto epi_smem = [&](uint32_t destR, const float* bias, int nb0, float os, int validN) {
#pragma unroll
        for (int mi = 0; mi < 2; ++mi)
#pragma unroll
            for (int nf = 0; nf < 8; ++nf) {
                int ncol = wn * 64 + nf * 8 + ((lane & 3) << 1);
                if (ncol >= validN) continue;
                float b0 = __ldg(bias + nb0 + ncol);
                float b1 = __ldg(bias + nb0 + ncol + 1);
                uint32_t chunk = (uint32_t)ncol >> 5;
                uint32_t cpos  = (uint32_t)ncol & 31;
#pragma unroll
                for (int r2 = 0; r2 < 2; ++r2) {
                    int row = wm * 32 + mi * 16 + (lane >> 2) + r2 * 8;
                    float v0 = softplus100(c[mi][nf][r2 * 2 + 0] + b0) * os;
                    float v1 = softplus100(c[mi][nf][r2 * 2 + 1] + b1) * os;
                    __nv_bfloat16 h0 = __float2bfloat16(v0);
                    __nv_bfloat16 h1 = __float2bfloat16(v1);
                    __nv_bfloat16 l0 = __float2bfloat16(v0 - __bfloat162float(h0));
                    __nv_bfloat16 l1 = __float2bfloat16(v1 - __bfloat162float(h1));
                    uint32_t hw = (uint32_t)__bfloat16_as_ushort(h0) |
                                  ((uint32_t)__bfloat16_as_ushort(h1) << 16);
                    uint32_t lw = (uint32_t)__bfloat16_as_ushort(l0) |
                                  ((uint32_t)__bfloat16_as_ushort(l1) << 16);
                    uint32_t off = (uint32_t)(row * 64) +
                                   (((cpos >> 3) ^ (((uint32_t)row >> 1) & 3)) << 4) +
                                   ((cpos & 7) << 1);
                    *(uint32_t*)(smem + destR + chunk * 8192 + off)         = hw;
                    *(uint32_t*)(smem + destR + 32768 + chunk * 8192 + off) = lw;
                }
            }
    };

    auto epi_gmem = [&](int n0w, const float* bias) {
#pragma unroll
        for (int mi = 0; mi < 2; ++mi)
#pragma unroll
            for (int nf = 0; nf < 8; ++nf) {
                int ncol = wn * 64 + nf * 8 + ((lane & 3) << 1);
                int n = n0w + ncol;
                float b0 = __ldg(bias + n);
                float b1 = __ldg(bias + n + 1);
#pragma unroll
                for (int r2 = 0; r2 < 2; ++r2) {
                    int row = wm * 32 + mi * 16 + (lane >> 2) + r2 * 8;
                    size_t m = (size_t)(m0 + row);
                    out[m * 257 + n]     = c[mi][nf][r2 * 2 + 0] + b0;
                    out[m * 257 + n + 1] = c[mi][nf][r2 * 2 + 1] + b1;
                }
            }
    };

    // ---- initial activation load ----
    load_full_act(gx, R_LOW0); CP_COMMIT(); CP_WAIT0(); __syncthreads();
    uint32_t lowR = R_LOW0, altR = R_LOW1;
    const int wrow[9] = {0, 256, 512, 768, 896, 1152, 1408, 1664, 1920};

#pragma unroll 1
    for (int l = 0; l < 9; ++l) {
        const __nv_bfloat16* Wl = gw + (size_t)wrow[l] * 512;
        const float* bias = bp.b[l];
        if (l == 8) {
            run_half(Wl, 0, lowR);
            epi_gmem(0, bias);
            run_half(Wl, 128, lowR);
            epi_gmem(128, bias);
            // ---- column 256 via bf16x3 scalar dot from resident smem ----
            __syncthreads();
            // stage w row 2176 (hi 0..255, lo 256..511) into R_W (1 KB)
            ((uint32_t*)(smem + R_W))[tid] = ((const uint32_t*)(gw + (size_t)2176 * 512))[tid];
            __syncthreads();
            {
                int r = tid >> 1, kh = tid & 1;
                float acc = 0.0f;
                uint32_t rq = ((uint32_t)r >> 1) & 3;
#pragma unroll 1
                for (int c4 = 0; c4 < 4; ++c4) {
                    int kc = kh * 4 + c4;
                    uint32_t base = (kc < 4) ? (lowR + (uint32_t)kc * 8192)
                                             : (R_HIGH + (uint32_t)(kc - 4) * 8192);
#pragma unroll
                    for (int j = 0; j < 32; ++j) {
                        int col = kc * 32 + j;
                        uint32_t off = (uint32_t)(r * 64) +
                                       ((((uint32_t)j >> 3) ^ rq) << 4) + ((j & 7) << 1);
                        float ahi = __bfloat162float(*(__nv_bfloat16*)(smem + base + off));
                        float alo = __bfloat162float(*(__nv_bfloat16*)(smem + base + 32768 + off));
                        float whi = __bfloat162float(*(__nv_bfloat16*)(smem + R_W + col * 2));
                        float wlo = __bfloat162float(*(__nv_bfloat16*)(smem + R_W + 512 + col * 2));
                        acc = fmaf(ahi, whi, acc);
                        acc = fmaf(alo, whi, acc);
                        acc = fmaf(ahi, wlo, acc);
                    }
                }
                acc += __shfl_xor_sync(0xFFFFFFFFu, acc, 1);
                if (kh == 0)
                    out[(size_t)(m0 + r) * 257 + 256] = acc + __ldg(bias + 256);
            }
        } else if (l == 3) {
            run_half(Wl, 0, lowR);
            __syncthreads();
            load_full_act(gs, altR); CP_COMMIT(); CP_WAIT0(); __syncthreads();
            epi_smem(altR, bias, 0, INV_SQRT2, 26);
            __syncthreads();
            uint32_t t = lowR; lowR = altR; altR = t;
        } else {
            run_half(Wl, 0, lowR);
            epi_smem(altR, bias, 0, 1.0f, 128);
            run_half(Wl, 128, lowR);
            __syncthreads();
            epi_smem(R_HIGH, bias, 128, 1.0f, 128);
            __syncthreads();
            uint32_t t = lowR; lowR = altR; altR = t;
        }
    }
}

// ---------------- launch ------------------------------------------------------
extern "C" void kernel_launch(void* const* d_in, const int* in_sizes, int n_in,
                              void* d_out, int out_size)
{
    const float* inp   = (const float*)d_in[0];
    const float* parts = (const float*)d_in[1];
    const float* table = (const float*)d_in[2];
    WPtrs wp;
    BPtrs bp;
    for (int l = 0; l < 9; ++l) {
        wp.w[l] = (const float*)d_in[3 + 2 * l];
        bp.b[l] = (const float*)d_in[4 + 2 * l];
    }

    float *xin, *st;
    __nv_bfloat16 *xb, *sb, *wbase;
    cudaGetSymbolAddress((void**)&xin, g_xin);
    cudaGetSymbolAddress((void**)&st,  g_stats);
    cudaGetSymbolAddress((void**)&xb, g_x);
    cudaGetSymbolAddress((void**)&sb, g_s);
    cudaGetSymbolAddress((void**)&wbase, g_w);

    const int BQ_SMEM = (16384 + 2560) * 4;
    cudaFuncSetAttribute(fused_mlp, cudaFuncAttributeMaxDynamicSharedMemorySize, SMEM_FUSED);
    cudaFuncSetAttribute(ball_prep_kernel, cudaFuncAttributeMaxDynamicSharedMemorySize, BQ_SMEM);

    ball_prep_kernel<<<P_PTS / 64, 256, BQ_SMEM>>>(inp, parts, st, wp, wbase);  // idx 0
    encode_kernel<<<P_PTS / 32, 256>>>(inp, table, st, xin);                    // idx 1
    conv_tr2<<<dim3(8, P_PTS / 32), dim3(32, 8)>>>(xin, xb, sb);                // idx 2
    fused_mlp<<<P_PTS / 128, 256, SMEM_FUSED>>>(xb, sb, wbase, bp, (float*)d_out); // idx 3 (profiled)
}

// round 14
// speedup vs baseline: 1.8187x; 1.0046x over previous
#include <cuda_runtime.h>
#include <cuda_bf16.h>
#include <math.h>
#include <stdint.h>

#define P_PTS     16384
#define M_PART    4096
#define HASHMAP_SZ 524288u
#define NUM_LVL   16
#define INV_SQRT2 0.70710678118654752f

// ---------------- scratch (device globals; no allocation allowed) -------------
__device__ __align__(16) float g_xin[232 * P_PTS];
__device__ __align__(16) float g_stats[7 * P_PTS];
__device__ __align__(16) __nv_bfloat16 g_x[P_PTS * 512];
__device__ __align__(16) __nv_bfloat16 g_s[P_PTS * 512];   // skip input (cols 26..255)
__device__ __align__(16) __nv_bfloat16 g_w[2304 * 512];

// ---------------- PTX helpers -------------------------------------------------
static __device__ __forceinline__ uint32_t smem_u32(const void* p) {
    uint32_t a;
    asm("{ .reg .u64 t; cvta.to.shared.u64 t, %1; cvt.u32.u64 %0, t; }" : "=r"(a) : "l"(p));
    return a;
}
static __device__ __forceinline__ void cp16(uint32_t s, const void* g) {
    asm volatile("cp.async.ca.shared.global [%0], [%1], 16;" :: "r"(s), "l"(g));
}
#define CP_COMMIT()  asm volatile("cp.async.commit_group;" ::: "memory")
#define CP_WAIT0()   asm volatile("cp.async.wait_group 0;" ::: "memory")

static __device__ __forceinline__ void ldsm4(uint32_t* r, uint32_t a) {
    asm volatile("ldmatrix.sync.aligned.m8n8.x4.shared.b16 {%0,%1,%2,%3}, [%4];"
                 : "=r"(r[0]), "=r"(r[1]), "=r"(r[2]), "=r"(r[3]) : "r"(a));
}
static __device__ __forceinline__ void mma16816(float* c, const uint32_t* a,
                                                uint32_t b0, uint32_t b1) {
    asm volatile(
        "mma.sync.aligned.m16n8k16.row.col.f32.bf16.bf16.f32 "
        "{%0,%1,%2,%3}, {%4,%5,%6,%7}, {%8,%9}, {%0,%1,%2,%3};"
        : "+f"(c[0]), "+f"(c[1]), "+f"(c[2]), "+f"(c[3])
        : "r"(a[0]), "r"(a[1]), "r"(a[2]), "r"(a[3]), "r"(b0), "r"(b1));
}
static __device__ __forceinline__ float softplus100(float v) {
    float y = 100.0f * v;
    return (fmaxf(y, 0.0f) + __logf(1.0f + __expf(-fabsf(y)))) * 0.01f;
}

struct WPtrs { const float* w[9]; };
struct BPtrs { const float* b[9]; };

// ---------------- ball query + fused weight prep ------------------------------
__global__ __launch_bounds__(256)
void ball_prep_kernel(const float* __restrict__ inp,
                      const float* __restrict__ parts,
                      float* __restrict__ stats,
                      WPtrs wp, __nv_bfloat16* __restrict__ wout)
{
    {
        const int cum[10]  = {0, 256, 512, 768, 896, 1152, 1408, 1664, 1920, 2304};
        const int nout[9]  = {256, 256, 256, 26, 256, 256, 256, 256, 257};
        const int kact[9]  = {230, 256, 256, 256, 256, 256, 256, 256, 256};
        int gid = blockIdx.x * 256 + threadIdx.x;
#pragma unroll
        for (int t9 = 0; t9 < 9; ++t9) {
            int i = gid + t9 * 65536;
            int r = i >> 8, k = i & 255;
            int l = 0;
#pragma unroll
            for (int t = 1; t < 9; ++t) if (r >= cum[t]) l = t;
            int n = r - cum[l];
            float v = (n < nout[l] && k < kact[l]) ? wp.w[l][n * kact[l] + k] : 0.0f;
            __nv_bfloat16 h = __float2bfloat16(v);
            wout[(size_t)r * 512 + k]       = h;
            wout[(size_t)r * 512 + 256 + k] = __float2bfloat16(v - __bfloat162float(h));
        }
    }

    extern __shared__ float fsm[];
    float4* sp4 = (float4*)fsm;
    float*  ex  = fsm + 16384;
    int tid = threadIdx.x;
    for (int i = tid; i < M_PART; i += 256) {
        float px = parts[3 * i], py = parts[3 * i + 1], pz = parts[3 * i + 2];
        sp4[i] = make_float4(px, py, pz, (px * px + py * py) + pz * pz);
    }
    __syncthreads();

    const int c  = tid >> 6;
    const int pl = tid & 63;
    const int p  = blockIdx.x * 64 + pl;
    const float x = inp[3 * p], y = inp[3 * p + 1], z = inp[3 * p + 2];
    const float q1 = (x * x + y * y) + z * z;
    const float R2 = 0.01f;
    const int j0 = c << 10, j1 = j0 + 1024;

    int h = 0;
    float wsum = 0.f, swx = 0.f, swy = 0.f, swz = 0.f;
    float sdx = 0.f, sdy = 0.f, sdz = 0.f;
    float s2x = 0.f, s2y = 0.f, s2z = 0.f;
#pragma unroll 8
    for (int j = j0; j < j1; ++j) {
        float4 q = sp4[j];
        float dot = x * q.x + y * q.y + z * q.z;
        float d2e = (q1 + q.w) - 2.0f * dot;
        if (d2e < R2) {
            ++h;
            float dx = q.x - x, dy = q.y - y, dz = q.z - z;
            float d2 = dx * dx + dy * dy + dz * dz;
            float d  = sqrtf(fmaxf(d2, 1e-24f));
            float dr = d / 0.1f;
            float w  = fmaxf(1.0f - dr * dr * dr, 0.0f);
            wsum += w;
            swx = fmaf(w, q.x, swx); swy = fmaf(w, q.y, swy); swz = fmaf(w, q.z, swz);
            sdx += dx; sdy += dy; sdz += dz;
            s2x = fmaf(dx, dx, s2x); s2y = fmaf(dy, dy, s2y); s2z = fmaf(dz, dz, s2z);
        }
    }
    ex[c * 64 + pl] = (float)h;
    __syncthreads();
    int h0 = (int)ex[pl], h1 = (int)ex[64 + pl], h2 = (int)ex[128 + pl], h3 = (int)ex[192 + pl];
    int start = (c > 0 ? h0 : 0) + (c > 1 ? h1 : 0) + (c > 2 ? h2 : 0);
    int total = h0 + h1 + h2 + h3;
    int cnt   = min(32, total);
    int budget = max(0, min(32 - start, h));
    if (budget < h) {
        wsum = swx = swy = swz = 0.f;
        sdx = sdy = sdz = 0.f;
        s2x = s2y = s2z = 0.f;
        int taken = 0;
        for (int j = j0; j < j1 && taken < budget; ++j) {
            float4 q = sp4[j];
            float dot = x * q.x + y * q.y + z * q.z;
            float d2e = (q1 + q.w) - 2.0f * dot;
            if (d2e < R2) {
                ++taken;
                float dx = q.x - x, dy = q.y - y, dz = q.z - z;
                float d2 = dx * dx + dy * dy + dz * dz;
                float d  = sqrtf(fmaxf(d2, 1e-24f));
                float dr = d / 0.1f;
                float w  = fmaxf(1.0f - dr * dr * dr, 0.0f);
                wsum += w;
                swx = fmaf(w, q.x, swx); swy = fmaf(w, q.y, swy); swz = fmaf(w, q.z, swz);
                sdx += dx; sdy += dy; sdz += dz;
                s2x = fmaf(dx, dx, s2x); s2y = fmaf(dy, dy, s2y); s2z = fmaf(dz, dz, s2z);
            }
        }
    }
    __syncthreads();
    float part[10] = {wsum, swx, swy, swz, sdx, sdy, sdz, s2x, s2y, s2z};
#pragma unroll
    for (int f = 0; f < 10; ++f) ex[f * 256 + c * 64 + pl] = part[f];
    __syncthreads();

    if (c == 0) {
        float S[10];
#pragma unroll
        for (int f = 0; f < 10; ++f)
            S[f] = ((ex[f * 256 + pl] + ex[f * 256 + 64 + pl])
                  + ex[f * 256 + 128 + pl]) + ex[f * 256 + 192 + pl];
        int ninv = 32 - cnt;
        if (ninv > 0) {
            float d  = sqrtf(fmaxf(q1, 1e-24f));
            float dr = d / 0.1f;
            float w  = fmaxf(1.0f - dr * dr * dr, 0.0f);
            S[0] += (float)ninv * w;
        }
        float nf  = (float)cnt;
        float wdn = S[0] + 1e-12f;
        float den = nf + 1e-12f;
        float vmx = S[4] / den, vmy = S[5] / den, vmz = S[6] / den;
        stats[0 * P_PTS + p] = S[0];
        stats[1 * P_PTS + p] = S[1] / wdn;
        stats[2 * P_PTS + p] = S[2] / wdn;
        stats[3 * P_PTS + p] = S[3] / wdn;
        stats[4 * P_PTS + p] = (S[7] - 2.0f * vmx * S[4] + nf * vmx * vmx) / den;
        stats[5 * P_PTS + p] = (S[8] - 2.0f * vmy * S[5] + nf * vmy * vmy) / den;
        stats[6 * P_PTS + p] = (S[9] - 2.0f * vmz * S[6] + nf * vmz * vmz) / den;
    }
}

// ---------------- encode (unchanged, passing) ----------------------------------
__device__ __forceinline__ void penc3(float* __restrict__ xin, int p, int base,
                                      float a, float b, float c)
{
    xin[(base + 0) * P_PTS + p] = a;
    xin[(base + 1) * P_PTS + p] = b;
    xin[(base + 2) * P_PTS + p] = c;
    float v[3] = {a, b, c};
#pragma unroll
    for (int f = 0; f < 10; ++f) {
        float fr = (float)(1 << f);
#pragma unroll
        for (int ch = 0; ch < 3; ++ch) {
            float s, co;
            sincosf(v[ch] * fr, &s, &co);
            xin[(base + 3 + f * 6 + ch)     * P_PTS + p] = s;
            xin[(base + 3 + f * 6 + 3 + ch) * P_PTS + p] = co;
        }
    }
}

__global__ __launch_bounds__(256)
void encode_kernel(const float* __restrict__ inp,
                   const float* __restrict__ table,
                   const float* __restrict__ stats,
                   float* __restrict__ xin)
{
    int tid = threadIdx.x;
    int pl = tid & 31, s = tid >> 5;
    int p = blockIdx.x * 32 + pl;
    float x = inp[3 * p], y = inp[3 * p + 1], z = inp[3 * p + 2];

    if (s < 4) {
        float xn[3] = { (x / 1.5f + 1.0f) * 0.5f,
                        (y / 1.5f + 1.0f) * 0.5f,
                        (z / 1.5f + 1.0f) * 0.5f };
#pragma unroll 1
        for (int li = 0; li < 4; ++li) {
            int l = s * 4 + li;
            double scd   = exp2((7.0 * (double)l) / 15.0) * 16.0 - 1.0;
            float  scale = (float)scd;
            unsigned res = (unsigned)ceil(scd) + 1u;
            bool dense   = ((unsigned long long)res * res * res <= (unsigned long long)HASHMAP_SZ);
            unsigned pg[3]; float fr[3];
#pragma unroll
            for (int cc = 0; cc < 3; ++cc) {
                float pos = fmaf(xn[cc], scale, 0.5f);
                float pf  = floorf(pos);
                fr[cc] = pos - pf;
                pg[cc] = (unsigned)pf;
            }
            float wx[2] = {1.f - fr[0], fr[0]};
            float wy[2] = {1.f - fr[1], fr[1]};
            float wz[2] = {1.f - fr[2], fr[2]};
            const float2* tbl = (const float2*)table + (size_t)l * HASHMAP_SZ;
            float f0 = 0.f, f1 = 0.f;
#pragma unroll
            for (int cc = 0; cc < 8; ++cc) {
                unsigned gx = pg[0] + (unsigned)(cc & 1);
                unsigned gy = pg[1] + (unsigned)((cc >> 1) & 1);
                unsigned gz = pg[2] + (unsigned)((cc >> 2) & 1);
                unsigned idx;
                if (dense) idx = gx + gy * res + gz * res * res;
                else       idx = ((gx * 1u) ^ (gy * 2654435761u) ^ (gz * 805459861u)) & (HASHMAP_SZ - 1u);
                float w = (wx[cc & 1] * wy[(cc >> 1) & 1]) * wz[(cc >> 2) & 1];
                float2 t = tbl[idx];
                f0 = fmaf(w, t.x, f0);
                f1 = fmaf(w, t.y, f1);
            }
            xin[(198 + 2 * l) * P_PTS + p] = f0;
            xin[(199 + 2 * l) * P_PTS + p] = f1;
        }
    } else if (s == 4) {
        penc3(xin, p, 0, x, y, z);
    } else if (s == 5) {
        float wsum = stats[p];
        xin[63 * P_PTS + p] = wsum;
#pragma unroll
        for (int f = 0; f < 4; ++f) {
            float sn, co;
            sincosf(wsum * (float)(1 << f), &sn, &co);
            xin[(64 + 2 * f) * P_PTS + p] = sn;
            xin[(65 + 2 * f) * P_PTS + p] = co;
        }
        xin[230 * P_PTS + p] = 0.0f;
        xin[231 * P_PTS + p] = 0.0f;
    } else if (s == 6) {
        penc3(xin, p, 72, stats[1 * P_PTS + p], stats[2 * P_PTS + p], stats[3 * P_PTS + p]);
    } else {
        penc3(xin, p, 135, stats[4 * P_PTS + p], stats[5 * P_PTS + p], stats[6 * P_PTS + p]);
    }
}

// ---------------- fused transpose + bf16-split: xin -> g_x AND g_s ------------
__global__ void conv_tr2(const float* __restrict__ src,
                         __nv_bfloat16* __restrict__ dx,
                         __nv_bfloat16* __restrict__ ds)
{
    __shared__ float s[32][33];
    int tx = threadIdx.x, ty = threadIdx.y;
    int ct = blockIdx.x, pt = blockIdx.y;
#pragma unroll
    for (int r2 = 0; r2 < 4; ++r2) {
        int ci = ty + r2 * 8;
        int c = ct * 32 + ci;
        int p = pt * 32 + tx;
        s[ci][tx] = (c < 232) ? src[(size_t)c * P_PTS + p] : 0.0f;
    }
    __syncthreads();
#pragma unroll
    for (int r2 = 0; r2 < 4; ++r2) {
        int pi = ty + r2 * 8;
        int p = pt * 32 + pi;
        int c = ct * 32 + tx;
        float v = s[tx][pi];
        __nv_bfloat16 h = __float2bfloat16(v);
        dx[(size_t)p * 512 + c]       = h;
        dx[(size_t)p * 512 + 256 + c] = __float2bfloat16(v - __bfloat162float(h));
        if (c < 230) {
            float vs = v * INV_SQRT2;
            __nv_bfloat16 hs = __float2bfloat16(vs);
            ds[(size_t)p * 512 + c + 26]       = hs;
            ds[(size_t)p * 512 + 256 + c + 26] = __float2bfloat16(vs - __bfloat162float(hs));
        }
    }
}

// ---------------- fused persistent MLP: 512 threads, 32x32 warp tiles ---------
#define R_LOW0 0
#define R_LOW1 65536
#define R_HIGH 131072
#define R_W    196608
#define SMEM_FUSED 229376

__global__ __launch_bounds__(512, 1)
void fused_mlp(const __nv_bfloat16* __restrict__ gx,
               const __nv_bfloat16* __restrict__ gs,
               const __nv_bfloat16* __restrict__ gw,
               BPtrs bp, float* __restrict__ out)
{
    extern __shared__ __align__(16) char smem[];
    const uint32_t s0 = smem_u32(smem);
    const int tid = threadIdx.x, warp = tid >> 5, lane = tid & 31;
    const int wm = warp & 3, wn = warp >> 2;          // 4x4 warp grid
    const int m0 = blockIdx.x << 7;

    const int rbase = tid >> 2, cc = tid & 3;          // 512 thr = 128 rows x 4
    const uint32_t so0 = (uint32_t)(rbase * 64) +
                         (((uint32_t)cc ^ (((uint32_t)rbase >> 1) & 3)) << 4);

    const int lrow = lane & 15;
    const uint32_t lhi = (uint32_t)(lane >> 4);
    uint32_t rowA[2], rqA[2], rowB[2], rqB[2];
#pragma unroll
    for (int mi = 0; mi < 2; ++mi) {
        int R = wm * 32 + mi * 16 + lrow;
        rowA[mi] = (uint32_t)(R * 64); rqA[mi] = (uint32_t)((R >> 1) & 3);
    }
#pragma unroll
    for (int nb = 0; nb < 2; ++nb) {
        int R = wn * 32 + nb * 16 + lrow;
        rowB[nb] = (uint32_t)(R * 64); rqB[nb] = (uint32_t)((R >> 1) & 3);
    }

    auto load_full_act = [&](const __nv_bfloat16* src, uint32_t lowR) {
        const __nv_bfloat16* pS = src + (size_t)(m0 + rbase) * 512 + cc * 8;
#pragma unroll
        for (int kc = 0; kc < 8; ++kc) {
            uint32_t hiT = (kc < 4) ? (lowR + (uint32_t)kc * 8192)
                                    : (R_HIGH + (uint32_t)(kc - 4) * 8192);
            int k32 = kc << 5;
            cp16(s0 + hiT + so0,         pS + k32);
            cp16(s0 + hiT + 32768 + so0, pS + 256 + k32);
        }
    };
    auto load_w = [&](const __nv_bfloat16* Wl, int n0w, int kc, int stg) {
        const __nv_bfloat16* pW = Wl + (size_t)(n0w + rbase) * 512 + cc * 8;
        uint32_t wb = s0 + R_W + (uint32_t)stg * 16384;
        int k32 = kc << 5;
        cp16(wb + so0,        pW + k32);
        cp16(wb + 8192 + so0, pW + 256 + k32);
    };

    float c[2][4][4];
    uint32_t aF[3][8], bF[2][8];

    auto ldA = [&](int buf, uint32_t tile, int ks) {
        uint32_t ch = (uint32_t)(2 * ks) + lhi;
        ldsm4(&aF[buf][0], tile + rowA[0] + ((ch ^ rqA[0]) << 4));
        ldsm4(&aF[buf][4], tile + rowA[1] + ((ch ^ rqA[1]) << 4));
    };
    auto ldB = [&](int buf, uint32_t tile, int ks) {
        uint32_t ch = (uint32_t)(2 * ks) + lhi;
        ldsm4(&bF[buf][0], tile + rowB[0] + ((ch ^ rqB[0]) << 4));
        ldsm4(&bF[buf][4], tile + rowB[1] + ((ch ^ rqB[1]) << 4));
    };
    auto mmaBlk = [&](int abuf, int bbuf) {
#pragma unroll
        for (int mi = 0; mi < 2; ++mi)
#pragma unroll
            for (int nb = 0; nb < 2; ++nb) {
                mma16816(c[mi][nb * 2],     &aF[abuf][mi * 4],
                         bF[bbuf][nb * 4 + 0], bF[bbuf][nb * 4 + 2]);
                mma16816(c[mi][nb * 2 + 1], &aF[abuf][mi * 4],
                         bF[bbuf][nb * 4 + 1], bF[bbuf][nb * 4 + 3]);
            }
    };

    auto run_half = [&](const __nv_bfloat16* Wl, int n0w, uint32_t lowR) {
#pragma unroll
        for (int mi = 0; mi < 2; ++mi)
#pragma unroll
            for (int nf = 0; nf < 4; ++nf)
#pragma unroll
                for (int r = 0; r < 4; ++r) c[mi][nf][r] = 0.0f;
        load_w(Wl, n0w, 0, 0); CP_COMMIT();
#pragma unroll 1
        for (int kc = 0; kc < 8; ++kc) {
            CP_WAIT0();
            __syncthreads();
            if (kc + 1 < 8) { load_w(Wl, n0w, kc + 1, (kc + 1) & 1); CP_COMMIT(); }
            uint32_t tHI = s0 + ((kc < 4) ? (lowR + (uint32_t)kc * 8192)
                                          : (R_HIGH + (uint32_t)(kc - 4) * 8192));
            uint32_t tLO = tHI + 32768;
            uint32_t wst = s0 + R_W + (uint32_t)(kc & 1) * 16384;
            uint32_t wlo = wst + 8192;
            ldB(0, wst, 0);          // WHI0
            ldA(0, tHI, 0);          // AHI0 (cached)
            ldA(2, tLO, 0);          // ALO0
            mmaBlk(0, 0);            // s0
            ldB(1, wst, 1);          // WHI1
            ldA(1, tHI, 1);          // AHI1 (cached)
            mmaBlk(2, 0);            // s1
            ldA(2, tLO, 1);          // ALO1
            mmaBlk(1, 1);            // s2
            ldB(0, wlo, 0);          // WLO0
            mmaBlk(2, 1);            // s3
            ldB(1, wlo, 1);          // WLO1
            mmaBlk(0, 0);            // s4
            mmaBlk(1, 1);            // s5
        }
    };

    auto epi_smem = [&](uint32_t destR, const float* bias, int nb0, float os, int validN) {
#pragma unroll
        for (int mi = 0; mi < 2; ++mi)
#pragma unroll
            for (int nf = 0; nf < 4; ++nf) {
                int ncol = wn * 32 + nf * 8 + ((lane & 3) << 1);
                if (ncol >= validN) continue;
                float b0 = __ldg(bias + nb0 + ncol);
                float b1 = __ldg(bias + nb0 + ncol + 1);
                uint32_t chunk = (uint32_t)ncol >> 5;
                uint32_t cpos  = (uint32_t)ncol & 31;
#pragma unroll
                for (int r2 = 0; r2 < 2; ++r2) {
                    int row = wm * 32 + mi * 16 + (lane >> 2) + r2 * 8;
                    float v0 = softplus100(c[mi][nf][r2 * 2 + 0] + b0) * os;
                    float v1 = softplus100(c[mi][nf][r2 * 2 + 1] + b1) * os;
                    __nv_bfloat16 h0 = __float2bfloat16(v0);
                    __nv_bfloat16 h1 = __float2bfloat16(v1);
                    __nv_bfloat16 l0 = __float2bfloat16(v0 - __bfloat162float(h0));
                    __nv_bfloat16 l1 = __float2bfloat16(v1 - __bfloat162float(h1));
                    uint32_t hw = (uint32_t)__bfloat16_as_ushort(h0) |
                                  ((uint32_t)__bfloat16_as_ushort(h1) << 16);
                    uint32_t lw = (uint32_t)__bfloat16_as_ushort(l0) |
                                  ((uint32_t)__bfloat16_as_ushort(l1) << 16);
                    uint32_t off = (uint32_t)(row * 64) +
                                   (((cpos >> 3) ^ (((uint32_t)row >> 1) & 3)) << 4) +
                                   ((cpos & 7) << 1);
                    *(uint32_t*)(smem + destR + chunk * 8192 + off)         = hw;
                    *(uint32_t*)(smem + destR + 32768 + chunk * 8192 + off) = lw;
                }
            }
    };

    auto epi_gmem = [&](int n0w, const float* bias) {
#pragma unroll
        for (int mi = 0; mi < 2; ++mi)
#pragma unroll
            for (int nf = 0; nf < 4; ++nf) {
                int n = n0w + wn * 32 + nf * 8 + ((lane & 3) << 1);
                float b0 = __ldg(bias + n);
                float b1 = __ldg(bias + n + 1);
#pragma unroll
                for (int r2 = 0; r2 < 2; ++r2) {
                    int row = wm * 32 + mi * 16 + (lane >> 2) + r2 * 8;
                    size_t m = (size_t)(m0 + row);
                    out[m * 257 + n]     = c[mi][nf][r2 * 2 + 0] + b0;
                    out[m * 257 + n + 1] = c[mi][nf][r2 * 2 + 1] + b1;
                }
            }
    };

    // ---- initial activation load ----
    load_full_act(gx, R_LOW0); CP_COMMIT(); CP_WAIT0(); __syncthreads();
    uint32_t lowR = R_LOW0, altR = R_LOW1;
    const int wrow[9] = {0, 256, 512, 768, 896, 1152, 1408, 1664, 1920};

#pragma unroll 1
    for (int l = 0; l < 9; ++l) {
        const __nv_bfloat16* Wl = gw + (size_t)wrow[l] * 512;
        const float* bias = bp.b[l];
        if (l == 8) {
            run_half(Wl, 0, lowR);
            epi_gmem(0, bias);
            run_half(Wl, 128, lowR);
            epi_gmem(128, bias);
            // ---- column 256 via bf16x3 scalar dot from resident smem ----
            __syncthreads();
            if (tid < 256)
                ((uint32_t*)(smem + R_W))[tid] =
                    ((const uint32_t*)(gw + (size_t)2176 * 512))[tid];
            __syncthreads();
            {
                int r  = tid >> 2;           // 0..127
                int kq = tid & 3;            // 2 chunks each
                float acc = 0.0f;
                uint32_t rq = ((uint32_t)r >> 1) & 3;
#pragma unroll 1
                for (int c2 = 0; c2 < 2; ++c2) {
                    int kc = kq * 2 + c2;
                    uint32_t base = (kc < 4) ? (lowR + (uint32_t)kc * 8192)
                                             : (R_HIGH + (uint32_t)(kc - 4) * 8192);
#pragma unroll
                    for (int j = 0; j < 32; ++j) {
                        int col = kc * 32 + j;
                        uint32_t off = (uint32_t)(r * 64) +
                                       ((((uint32_t)j >> 3) ^ rq) << 4) + ((j & 7) << 1);
                        float ahi = __bfloat162float(*(__nv_bfloat16*)(smem + base + off));
                        float alo = __bfloat162float(*(__nv_bfloat16*)(smem + base + 32768 + off));
                        float whi = __bfloat162float(*(__nv_bfloat16*)(smem + R_W + col * 2));
                        float wlo = __bfloat162float(*(__nv_bfloat16*)(smem + R_W + 512 + col * 2));
                        acc = fmaf(ahi, whi, acc);
                        acc = fmaf(alo, whi, acc);
                        acc = fmaf(ahi, wlo, acc);
                    }
                }
                acc += __shfl_xor_sync(0xFFFFFFFFu, acc, 1);
                acc += __shfl_xor_sync(0xFFFFFFFFu, acc, 2);
                if (kq == 0)
                    out[(size_t)(m0 + r) * 257 + 256] = acc + __ldg(bias + 256);
            }
        } else if (l == 3) {
            run_half(Wl, 0, lowR);
            __syncthreads();
            load_full_act(gs, altR); CP_COMMIT(); CP_WAIT0(); __syncthreads();
            epi_smem(altR, bias, 0, INV_SQRT2, 26);
            __syncthreads();
            uint32_t t = lowR; lowR = altR; altR = t;
        } else {
            run_half(Wl, 0, lowR);
            epi_smem(altR, bias, 0, 1.0f, 128);
            run_half(Wl, 128, lowR);
            __syncthreads();
            epi_smem(R_HIGH, bias, 128, 1.0f, 128);
            __syncthreads();
            uint32_t t = lowR; lowR = altR; altR = t;
        }
    }
}

// ---------------- launch ------------------------------------------------------
extern "C" void kernel_launch(void* const* d_in, const int* in_sizes, int n_in,
                              void* d_out, int out_size)
{
    const float* inp   = (const float*)d_in[0];
    const float* parts = (const float*)d_in[1];
    const float* table = (const float*)d_in[2];
    WPtrs wp;
    BPtrs bp;
    for (int l = 0; l < 9; ++l) {
        wp.w[l] = (const float*)d_in[3 + 2 * l];
        bp.b[l] = (const float*)d_in[4 + 2 * l];
    }

    float *xin, *st;
    __nv_bfloat16 *xb, *sb, *wbase;
    cudaGetSymbolAddress((void**)&xin, g_xin);
    cudaGetSymbolAddress((void**)&st,  g_stats);
    cudaGetSymbolAddress((void**)&xb, g_x);
    cudaGetSymbolAddress((void**)&sb, g_s);
    cudaGetSymbolAddress((void**)&wbase, g_w);

    const int BQ_SMEM = (16384 + 2560) * 4;
    cudaFuncSetAttribute(fused_mlp, cudaFuncAttributeMaxDynamicSharedMemorySize, SMEM_FUSED);
    cudaFuncSetAttribute(ball_prep_kernel, cudaFuncAttributeMaxDynamicSharedMemorySize, BQ_SMEM);

    ball_prep_kernel<<<P_PTS / 64, 256, BQ_SMEM>>>(inp, parts, st, wp, wbase);  // idx 0
    encode_kernel<<<P_PTS / 32, 256>>>(inp, table, st, xin);                    // idx 1
    conv_tr2<<<dim3(8, P_PTS / 32), dim3(32, 8)>>>(xin, xb, sb);                // idx 2
    fused_mlp<<<P_PTS / 128, 512, SMEM_FUSED>>>(xb, sb, wbase, bp, (float*)d_out); // idx 3
}